// round 2
// baseline (speedup 1.0000x reference)
#include <cuda_runtime.h>
#include <cuda_bf16.h>
#include <math.h>

// Problem constants
#define Tc   128
#define Bc   1024
#define LAGc 6
#define Hc   256
#define H4c  1024
#define TBc  (Tc * Bc)      // 131072
#define BHc  (Bc * Hc)      // 262144

// ---------------------------------------------------------------------------
// Scratch (device globals; no runtime allocation allowed)
// ---------------------------------------------------------------------------
__device__ float g_buf0[TBc * Hc];          // 134 MB ping
__device__ float g_buf1[TBc * Hc];          // 134 MB pong
__device__ float g_G0[(size_t)TBc * H4c];   // 512 MB: precomputed u@Wih0^T + bias for all T
__device__ float g_hs[TBc * Hc];            // 134 MB: LSTM layer-1 outputs, all T
__device__ float g_h0[2 * BHc];             // double-buffered layer-0 hidden
__device__ float g_h1[2 * BHc];             // double-buffered layer-1 hidden
__device__ float g_c0[BHc];
__device__ float g_c1[BHc];

// ---------------------------------------------------------------------------
// Kernel 1: u = relu(x @ Wi1^T + bi1)   [TB,6] x [256,6]^T -> [TB,256]
// One block handles 16 rows; W+b staged in smem.
// ---------------------------------------------------------------------------
__global__ void __launch_bounds__(256) in_mlp1_k(
    const float* __restrict__ x, const float* __restrict__ W,
    const float* __restrict__ b, float* __restrict__ out)
{
    __shared__ float sW[Hc * LAGc];
    __shared__ float sb[Hc];
    __shared__ float sx[16 * LAGc];
    int tid = threadIdx.x;
    int m0  = blockIdx.x * 16;
    for (int i = tid; i < Hc * LAGc; i += 256) sW[i] = W[i];
    sb[tid] = b[tid];
    if (tid < 16 * LAGc) sx[tid] = x[m0 * LAGc + tid];
    __syncthreads();
    #pragma unroll
    for (int r = 0; r < 16; r++) {
        float acc = sb[tid];
        #pragma unroll
        for (int k = 0; k < LAGc; k++) acc += sx[r * LAGc + k] * sW[tid * LAGc + k];
        out[(m0 + r) * Hc + tid] = fmaxf(acc, 0.f);
    }
}

// ---------------------------------------------------------------------------
// Generic tiled fp32 GEMM: C = act( [pre_relu?]A @ W^T + b1 [+ b2] )
// A: [M,K] row-major, W: [N,K] row-major. BM=BN=64, BK=16, 256 thr, 4x4/thread.
// ---------------------------------------------------------------------------
template<bool RELU_OUT, bool PRE_RELU>
__global__ void __launch_bounds__(256) gemm_nt_k(
    const float* __restrict__ A, const float* __restrict__ W,
    const float* __restrict__ b1, const float* __restrict__ b2,
    float* __restrict__ C, int M, int N, int K)
{
    const int BM = 64, BN = 64, BK = 16;
    __shared__ float As[BK][BM];
    __shared__ float Ws[BK][BN];
    int tid = threadIdx.x;
    int tx = tid & 15;        // n sub-tile
    int ty = tid >> 4;        // m sub-tile
    int m0 = blockIdx.y * BM;
    int n0 = blockIdx.x * BN;

    int lr = tid >> 2;         // 0..63 row within tile
    int lk = (tid & 3) * 4;    // k offset 0/4/8/12
    const float* Ag = A + (size_t)(m0 + lr) * K + lk;
    const float* Wg = W + (size_t)(n0 + lr) * K + lk;

    float acc[4][4] = {};
    for (int k0 = 0; k0 < K; k0 += BK) {
        float4 av = *(const float4*)(Ag + k0);
        float4 wv = *(const float4*)(Wg + k0);
        if (PRE_RELU) {
            av.x = fmaxf(av.x, 0.f); av.y = fmaxf(av.y, 0.f);
            av.z = fmaxf(av.z, 0.f); av.w = fmaxf(av.w, 0.f);
        }
        As[lk + 0][lr] = av.x; As[lk + 1][lr] = av.y;
        As[lk + 2][lr] = av.z; As[lk + 3][lr] = av.w;
        Ws[lk + 0][lr] = wv.x; Ws[lk + 1][lr] = wv.y;
        Ws[lk + 2][lr] = wv.z; Ws[lk + 3][lr] = wv.w;
        __syncthreads();
        #pragma unroll
        for (int kk = 0; kk < BK; kk++) {
            float4 a = *(const float4*)&As[kk][ty * 4];
            float4 w = *(const float4*)&Ws[kk][tx * 4];
            acc[0][0] += a.x * w.x; acc[0][1] += a.x * w.y; acc[0][2] += a.x * w.z; acc[0][3] += a.x * w.w;
            acc[1][0] += a.y * w.x; acc[1][1] += a.y * w.y; acc[1][2] += a.y * w.z; acc[1][3] += a.y * w.w;
            acc[2][0] += a.z * w.x; acc[2][1] += a.z * w.y; acc[2][2] += a.z * w.z; acc[2][3] += a.z * w.w;
            acc[3][0] += a.w * w.x; acc[3][1] += a.w * w.y; acc[3][2] += a.w * w.z; acc[3][3] += a.w * w.w;
        }
        __syncthreads();
    }
    float bb[4];
    #pragma unroll
    for (int j = 0; j < 4; j++) {
        int n = n0 + tx * 4 + j;
        bb[j] = b1[n] + (b2 ? b2[n] : 0.f);
    }
    #pragma unroll
    for (int i = 0; i < 4; i++) {
        int m = m0 + ty * 4 + i;
        float4 v;
        v.x = acc[i][0] + bb[0]; v.y = acc[i][1] + bb[1];
        v.z = acc[i][2] + bb[2]; v.w = acc[i][3] + bb[3];
        if (RELU_OUT) {
            v.x = fmaxf(v.x, 0.f); v.y = fmaxf(v.y, 0.f);
            v.z = fmaxf(v.z, 0.f); v.w = fmaxf(v.w, 0.f);
        }
        *(float4*)(C + (size_t)m * N + n0 + tx * 4) = v;
    }
}

__device__ __forceinline__ float sigmoidf_(float v) { return 1.f / (1.f + expf(-v)); }

// ---------------------------------------------------------------------------
// Fused LSTM layer-0 step: gates = G0[t] + h0prev @ Whh0^T ; cell update.
// Block: 64 batch rows x 32 h-cols (x4 gates). Grid (8, 16). 256 threads.
// ---------------------------------------------------------------------------
__global__ void __launch_bounds__(256) lstm0_step_k(
    const float* __restrict__ h0prev, float* __restrict__ h0cur,
    float* __restrict__ c0, const float* __restrict__ Whh,
    const float* __restrict__ G0t)
{
    __shared__ float As[32][64];
    __shared__ float Ws[4][32][32];
    int tid = threadIdx.x;
    int tx = tid & 31;   // h-col
    int ty = tid >> 5;   // row group (0..7)
    int n0 = blockIdx.x * 32;
    int m0 = blockIdx.y * 64;
    float acc[8][4] = {};

    for (int k0 = 0; k0 < Hc; k0 += 32) {
        #pragma unroll
        for (int i = 0; i < 2; i++) {
            int idx = tid + i * 256;
            int row = idx >> 3; int kq = (idx & 7) * 4;
            float4 v = *(const float4*)(h0prev + (m0 + row) * Hc + k0 + kq);
            As[kq + 0][row] = v.x; As[kq + 1][row] = v.y;
            As[kq + 2][row] = v.z; As[kq + 3][row] = v.w;
        }
        {
            int j = tid >> 3; int kq = (tid & 7) * 4;
            #pragma unroll
            for (int g = 0; g < 4; g++) {
                float4 v = *(const float4*)(Whh + (g * Hc + n0 + j) * Hc + k0 + kq);
                Ws[g][kq + 0][j] = v.x; Ws[g][kq + 1][j] = v.y;
                Ws[g][kq + 2][j] = v.z; Ws[g][kq + 3][j] = v.w;
            }
        }
        __syncthreads();
        #pragma unroll 8
        for (int kk = 0; kk < 32; kk++) {
            float w0 = Ws[0][kk][tx], w1 = Ws[1][kk][tx];
            float w2 = Ws[2][kk][tx], w3 = Ws[3][kk][tx];
            #pragma unroll
            for (int r = 0; r < 8; r++) {
                float a = As[kk][ty * 8 + r];
                acc[r][0] += a * w0; acc[r][1] += a * w1;
                acc[r][2] += a * w2; acc[r][3] += a * w3;
            }
        }
        __syncthreads();
    }
    int n = n0 + tx;
    #pragma unroll
    for (int r = 0; r < 8; r++) {
        int m = m0 + ty * 8 + r;
        float gi = acc[r][0] + G0t[(size_t)m * H4c + n];
        float gf = acc[r][1] + G0t[(size_t)m * H4c + Hc + n];
        float gg = acc[r][2] + G0t[(size_t)m * H4c + 2 * Hc + n];
        float go = acc[r][3] + G0t[(size_t)m * H4c + 3 * Hc + n];
        float c  = c0[m * Hc + n];
        float c2 = sigmoidf_(gf) * c + sigmoidf_(gi) * tanhf(gg);
        c0[m * Hc + n] = c2;
        h0cur[m * Hc + n] = sigmoidf_(go) * tanhf(c2);
    }
}

// ---------------------------------------------------------------------------
// Fused LSTM layer-1 step: gates = h0cur@Wih1^T + h1prev@Whh1^T + bih1 + bhh1
// Same tiling; K loop runs over both sources. Writes h1cur, c1, and hs[t].
// ---------------------------------------------------------------------------
__global__ void __launch_bounds__(256) lstm1_step_k(
    const float* __restrict__ xin, const float* __restrict__ h1prev,
    float* __restrict__ h1cur, float* __restrict__ c1,
    const float* __restrict__ Wih, const float* __restrict__ Whh,
    const float* __restrict__ bih, const float* __restrict__ bhh,
    float* __restrict__ hst)
{
    __shared__ float As[32][64];
    __shared__ float Ws[4][32][32];
    int tid = threadIdx.x;
    int tx = tid & 31;
    int ty = tid >> 5;
    int n0 = blockIdx.x * 32;
    int m0 = blockIdx.y * 64;
    float acc[8][4] = {};

    for (int src = 0; src < 2; src++) {
        const float* Ap = (src == 0) ? xin : h1prev;
        const float* Wp = (src == 0) ? Wih : Whh;
        for (int k0 = 0; k0 < Hc; k0 += 32) {
            #pragma unroll
            for (int i = 0; i < 2; i++) {
                int idx = tid + i * 256;
                int row = idx >> 3; int kq = (idx & 7) * 4;
                float4 v = *(const float4*)(Ap + (m0 + row) * Hc + k0 + kq);
                As[kq + 0][row] = v.x; As[kq + 1][row] = v.y;
                As[kq + 2][row] = v.z; As[kq + 3][row] = v.w;
            }
            {
                int j = tid >> 3; int kq = (tid & 7) * 4;
                #pragma unroll
                for (int g = 0; g < 4; g++) {
                    float4 v = *(const float4*)(Wp + (g * Hc + n0 + j) * Hc + k0 + kq);
                    Ws[g][kq + 0][j] = v.x; Ws[g][kq + 1][j] = v.y;
                    Ws[g][kq + 2][j] = v.z; Ws[g][kq + 3][j] = v.w;
                }
            }
            __syncthreads();
            #pragma unroll 8
            for (int kk = 0; kk < 32; kk++) {
                float w0 = Ws[0][kk][tx], w1 = Ws[1][kk][tx];
                float w2 = Ws[2][kk][tx], w3 = Ws[3][kk][tx];
                #pragma unroll
                for (int r = 0; r < 8; r++) {
                    float a = As[kk][ty * 8 + r];
                    acc[r][0] += a * w0; acc[r][1] += a * w1;
                    acc[r][2] += a * w2; acc[r][3] += a * w3;
                }
            }
            __syncthreads();
        }
    }
    int n = n0 + tx;
    float bi = bih[0 * Hc + n] + bhh[0 * Hc + n];
    float bf = bih[1 * Hc + n] + bhh[1 * Hc + n];
    float bg = bih[2 * Hc + n] + bhh[2 * Hc + n];
    float bo = bih[3 * Hc + n] + bhh[3 * Hc + n];
    #pragma unroll
    for (int r = 0; r < 8; r++) {
        int m = m0 + ty * 8 + r;
        float c  = c1[m * Hc + n];
        float c2 = sigmoidf_(acc[r][1] + bf) * c
                 + sigmoidf_(acc[r][0] + bi) * tanhf(acc[r][2] + bg);
        c1[m * Hc + n] = c2;
        float h = sigmoidf_(acc[r][3] + bo) * tanhf(c2);
        h1cur[m * Hc + n] = h;
        hst[m * Hc + n]   = h;
    }
}

// ---------------------------------------------------------------------------
// Final layer: y = A @ Wo3^T + bo3  (N=6, K=256). One warp per row.
// ---------------------------------------------------------------------------
__global__ void __launch_bounds__(256) out_mlp3_k(
    const float* __restrict__ A, const float* __restrict__ W,
    const float* __restrict__ b, float* __restrict__ out)
{
    __shared__ float sW[LAGc * Hc];
    __shared__ float sb[LAGc];
    int tid = threadIdx.x;
    for (int i = tid; i < LAGc * Hc; i += 256) sW[i] = W[i];
    if (tid < LAGc) sb[tid] = b[tid];
    __syncthreads();
    int w = tid >> 5, lane = tid & 31;
    int m = blockIdx.x * 8 + w;
    float a[8];
    #pragma unroll
    for (int j = 0; j < 8; j++) a[j] = A[(size_t)m * Hc + lane + 32 * j];
    #pragma unroll
    for (int n = 0; n < LAGc; n++) {
        float s = 0.f;
        #pragma unroll
        for (int j = 0; j < 8; j++) s += a[j] * sW[n * Hc + lane + 32 * j];
        #pragma unroll
        for (int o = 16; o > 0; o >>= 1) s += __shfl_xor_sync(0xffffffff, s, o);
        if (lane == n) out[m * LAGc + n] = s + sb[n];
    }
}

// ---------------------------------------------------------------------------
extern "C" void kernel_launch(void* const* d_in, const int* in_sizes, int n_in,
                              void* d_out, int out_size)
{
    const float* x    = (const float*)d_in[0];
    const float* Wi1  = (const float*)d_in[1];
    const float* bi1  = (const float*)d_in[2];
    const float* Wi2  = (const float*)d_in[3];
    const float* bi2  = (const float*)d_in[4];
    const float* Wi3  = (const float*)d_in[5];
    const float* bi3  = (const float*)d_in[6];
    const float* Wih0 = (const float*)d_in[7];
    const float* Whh0 = (const float*)d_in[8];
    const float* bih0 = (const float*)d_in[9];
    const float* bhh0 = (const float*)d_in[10];
    const float* Wih1 = (const float*)d_in[11];
    const float* Whh1 = (const float*)d_in[12];
    const float* bih1 = (const float*)d_in[13];
    const float* bhh1 = (const float*)d_in[14];
    const float* Wo1  = (const float*)d_in[15];
    const float* bo1  = (const float*)d_in[16];
    const float* Wo2  = (const float*)d_in[17];
    const float* bo2  = (const float*)d_in[18];
    const float* Wo3  = (const float*)d_in[19];
    const float* bo3  = (const float*)d_in[20];
    float* out = (float*)d_out;

    float *buf0, *buf1, *G0, *hs, *h0, *h1, *c0, *c1;
    cudaGetSymbolAddress((void**)&buf0, g_buf0);
    cudaGetSymbolAddress((void**)&buf1, g_buf1);
    cudaGetSymbolAddress((void**)&G0,   g_G0);
    cudaGetSymbolAddress((void**)&hs,   g_hs);
    cudaGetSymbolAddress((void**)&h0,   g_h0);
    cudaGetSymbolAddress((void**)&h1,   g_h1);
    cudaGetSymbolAddress((void**)&c0,   g_c0);
    cudaGetSymbolAddress((void**)&c1,   g_c1);

    // Re-zero initial state on every replay (part of the captured graph).
    cudaMemsetAsync(h0, 0, BHc * sizeof(float));
    cudaMemsetAsync(h1, 0, BHc * sizeof(float));
    cudaMemsetAsync(c0, 0, BHc * sizeof(float));
    cudaMemsetAsync(c1, 0, BHc * sizeof(float));

    // Input MLP
    in_mlp1_k<<<TBc / 16, 256>>>(x, Wi1, bi1, buf0);
    dim3 g256(Hc / 64, TBc / 64);
    gemm_nt_k<true, false><<<g256, 256>>>(buf0, Wi2, bi2, nullptr, buf1, TBc, Hc, Hc);
    gemm_nt_k<true, false><<<g256, 256>>>(buf1, Wi3, bi3, nullptr, buf0, TBc, Hc, Hc);

    // Precompute layer-0 input projection for ALL timesteps in one big GEMM
    dim3 g1024(H4c / 64, TBc / 64);
    gemm_nt_k<false, false><<<g1024, 256>>>(buf0, Wih0, bih0, bhh0, G0, TBc, H4c, Hc);

    // Sequential recurrence: 2 fused kernels per timestep
    dim3 lgrid(Hc / 32, Bc / 64);
    for (int t = 0; t < Tc; t++) {
        const float* h0p = h0 + (t & 1) * BHc;
        float*       h0n = h0 + ((t + 1) & 1) * BHc;
        const float* h1p = h1 + (t & 1) * BHc;
        float*       h1n = h1 + ((t + 1) & 1) * BHc;
        lstm0_step_k<<<lgrid, 256>>>(h0p, h0n, c0, Whh0, G0 + (size_t)t * Bc * H4c);
        lstm1_step_k<<<lgrid, 256>>>(h0n, h1p, h1n, c1, Wih1, Whh1, bih1, bhh1,
                                     hs + (size_t)t * BHc);
    }

    // Output MLP (relu applied to hs on load of the first GEMM)
    gemm_nt_k<true, true ><<<g256, 256>>>(hs,   Wo1, bo1, nullptr, buf0, TBc, Hc, Hc);
    gemm_nt_k<true, false><<<g256, 256>>>(buf0, Wo2, bo2, nullptr, buf1, TBc, Hc, Hc);
    out_mlp3_k<<<TBc / 8, 256>>>(buf1, Wo3, bo3, out);
}

// round 3
// speedup vs baseline: 2.2281x; 2.2281x over previous
#include <cuda_runtime.h>
#include <cuda_bf16.h>
#include <math.h>

// Problem constants
#define Tc   128
#define Bc   1024
#define LAGc 6
#define Hc   256
#define H4c  1024
#define TBc  (Tc * Bc)      // 131072
#define BHc  (Bc * Hc)      // 262144

// ---------------------------------------------------------------------------
// Scratch (device globals; no runtime allocation allowed)
// ---------------------------------------------------------------------------
__device__ float g_buf0[TBc * Hc];
__device__ float g_buf1[TBc * Hc];
__device__ float g_G0[(size_t)TBc * H4c];   // u@Wih0^T + bih0 + bhh0 for all T
__device__ float g_hs[TBc * Hc];
__device__ float g_h0[2 * BHc];
__device__ float g_h1[2 * BHc];
__device__ float g_c0[BHc];
__device__ float g_c1[BHc];

// ---------------------------------------------------------------------------
// Helpers
// ---------------------------------------------------------------------------
__device__ __forceinline__ unsigned cvt_tf32(float x) {
    unsigned u; asm("cvt.rna.tf32.f32 %0, %1;" : "=r"(u) : "f"(x)); return u;
}
__device__ __forceinline__ void mma8(float* d, const unsigned* a, const unsigned* b) {
    asm volatile("mma.sync.aligned.m16n8k8.row.col.f32.tf32.tf32.f32 "
        "{%0,%1,%2,%3}, {%4,%5,%6,%7}, {%8,%9}, {%0,%1,%2,%3};"
        : "+f"(d[0]), "+f"(d[1]), "+f"(d[2]), "+f"(d[3])
        : "r"(a[0]), "r"(a[1]), "r"(a[2]), "r"(a[3]), "r"(b[0]), "r"(b[1]));
}
__device__ __forceinline__ float sigmoidf_(float v) { return 1.f / (1.f + expf(-v)); }

// ---------------------------------------------------------------------------
// Kernel 1: u = relu(x @ Wi1^T + bi1)   [TB,6] -> [TB,256]  (memory-bound)
// ---------------------------------------------------------------------------
__global__ void __launch_bounds__(256) in_mlp1_k(
    const float* __restrict__ x, const float* __restrict__ W,
    const float* __restrict__ b, float* __restrict__ out)
{
    __shared__ float sW[Hc * LAGc];
    __shared__ float sb[Hc];
    __shared__ float sx[16 * LAGc];
    int tid = threadIdx.x;
    int m0  = blockIdx.x * 16;
    for (int i = tid; i < Hc * LAGc; i += 256) sW[i] = W[i];
    sb[tid] = b[tid];
    if (tid < 16 * LAGc) sx[tid] = x[m0 * LAGc + tid];
    __syncthreads();
    #pragma unroll
    for (int r = 0; r < 16; r++) {
        float acc = sb[tid];
        #pragma unroll
        for (int k = 0; k < LAGc; k++) acc += sx[r * LAGc + k] * sW[tid * LAGc + k];
        out[(m0 + r) * Hc + tid] = fmaxf(acc, 0.f);
    }
}

// ---------------------------------------------------------------------------
// Generic tf32 tensor-core GEMM: C = act(A @ W^T + b1 [+ b2])
// Block tile 128x128, BK=16, 8 warps (2m x 4n), warp tile 64x32.
// A:[M,K] row-major fp32, W:[N,K] row-major fp32. K % 16 == 0, M%128==0, N%128==0.
// smem layout: [row][k] with stride 20 (conflict-free fragment loads).
// ---------------------------------------------------------------------------
template<bool RELU_OUT, bool PRE_RELU>
__global__ void __launch_bounds__(256) gemm_mma_k(
    const float* __restrict__ A, const float* __restrict__ W,
    const float* __restrict__ b1, const float* __restrict__ b2,
    float* __restrict__ C, int M, int N, int K)
{
    __shared__ unsigned As[128 * 20];
    __shared__ unsigned Bs[128 * 20];
    int tid = threadIdx.x, lane = tid & 31, wid = tid >> 5;
    int wm = wid & 1, wn = wid >> 1;
    int m0 = blockIdx.y * 128, n0 = blockIdx.x * 128;
    int r0 = tid >> 2;           // 0..63 (slot 0 row; slot 1 row = r0+64)
    int k4 = (tid & 3) * 4;

    const float* Ab = A + (size_t)m0 * K;
    const float* Wb = W + (size_t)n0 * K;

    float4 pa0 = *(const float4*)(Ab + (size_t)r0 * K + k4);
    float4 pa1 = *(const float4*)(Ab + (size_t)(r0 + 64) * K + k4);
    float4 pw0 = *(const float4*)(Wb + (size_t)r0 * K + k4);
    float4 pw1 = *(const float4*)(Wb + (size_t)(r0 + 64) * K + k4);

    float acc[4][4][4] = {};
    for (int k0 = 0; k0 < K; k0 += 16) {
        __syncthreads();
        float4 v;
        v = pa0;
        if (PRE_RELU) { v.x=fmaxf(v.x,0.f); v.y=fmaxf(v.y,0.f); v.z=fmaxf(v.z,0.f); v.w=fmaxf(v.w,0.f); }
        As[r0*20 + k4+0]=cvt_tf32(v.x); As[r0*20 + k4+1]=cvt_tf32(v.y);
        As[r0*20 + k4+2]=cvt_tf32(v.z); As[r0*20 + k4+3]=cvt_tf32(v.w);
        v = pa1;
        if (PRE_RELU) { v.x=fmaxf(v.x,0.f); v.y=fmaxf(v.y,0.f); v.z=fmaxf(v.z,0.f); v.w=fmaxf(v.w,0.f); }
        As[(r0+64)*20 + k4+0]=cvt_tf32(v.x); As[(r0+64)*20 + k4+1]=cvt_tf32(v.y);
        As[(r0+64)*20 + k4+2]=cvt_tf32(v.z); As[(r0+64)*20 + k4+3]=cvt_tf32(v.w);
        Bs[r0*20 + k4+0]=cvt_tf32(pw0.x); Bs[r0*20 + k4+1]=cvt_tf32(pw0.y);
        Bs[r0*20 + k4+2]=cvt_tf32(pw0.z); Bs[r0*20 + k4+3]=cvt_tf32(pw0.w);
        Bs[(r0+64)*20 + k4+0]=cvt_tf32(pw1.x); Bs[(r0+64)*20 + k4+1]=cvt_tf32(pw1.y);
        Bs[(r0+64)*20 + k4+2]=cvt_tf32(pw1.z); Bs[(r0+64)*20 + k4+3]=cvt_tf32(pw1.w);
        __syncthreads();

        if (k0 + 16 < K) {
            pa0 = *(const float4*)(Ab + (size_t)r0 * K + k0 + 16 + k4);
            pa1 = *(const float4*)(Ab + (size_t)(r0 + 64) * K + k0 + 16 + k4);
            pw0 = *(const float4*)(Wb + (size_t)r0 * K + k0 + 16 + k4);
            pw1 = *(const float4*)(Wb + (size_t)(r0 + 64) * K + k0 + 16 + k4);
        }

        int qr = lane >> 2, qk = lane & 3;
        #pragma unroll
        for (int ks = 0; ks < 16; ks += 8) {
            unsigned af[4][4], bf[4][2];
            #pragma unroll
            for (int mt = 0; mt < 4; mt++) {
                int rb = wm * 64 + mt * 16;
                af[mt][0] = As[(rb     + qr)*20 + ks     + qk];
                af[mt][1] = As[(rb + 8 + qr)*20 + ks     + qk];
                af[mt][2] = As[(rb     + qr)*20 + ks + 4 + qk];
                af[mt][3] = As[(rb + 8 + qr)*20 + ks + 4 + qk];
            }
            #pragma unroll
            for (int nt = 0; nt < 4; nt++) {
                int cb = wn * 32 + nt * 8;
                bf[nt][0] = Bs[(cb + qr)*20 + ks     + qk];
                bf[nt][1] = Bs[(cb + qr)*20 + ks + 4 + qk];
            }
            #pragma unroll
            for (int mt = 0; mt < 4; mt++)
                #pragma unroll
                for (int nt = 0; nt < 4; nt++)
                    mma8(acc[mt][nt], af[mt], bf[nt]);
        }
    }

    int qr = lane >> 2, qk = lane & 3;
    #pragma unroll
    for (int nt = 0; nt < 4; nt++) {
        int col = n0 + wn * 32 + nt * 8 + 2 * qk;
        float bb0 = b1[col]     + (b2 ? b2[col]     : 0.f);
        float bb1 = b1[col + 1] + (b2 ? b2[col + 1] : 0.f);
        #pragma unroll
        for (int mt = 0; mt < 4; mt++) {
            int row = m0 + wm * 64 + mt * 16 + qr;
            float2 v0, v1;
            v0.x = acc[mt][nt][0] + bb0; v0.y = acc[mt][nt][1] + bb1;
            v1.x = acc[mt][nt][2] + bb0; v1.y = acc[mt][nt][3] + bb1;
            if (RELU_OUT) {
                v0.x=fmaxf(v0.x,0.f); v0.y=fmaxf(v0.y,0.f);
                v1.x=fmaxf(v1.x,0.f); v1.y=fmaxf(v1.y,0.f);
            }
            *(float2*)(C + (size_t)row * N + col)       = v0;
            *(float2*)(C + (size_t)(row + 8) * N + col) = v1;
        }
    }
}

// ---------------------------------------------------------------------------
// Fused LSTM layer-0 step on tensor cores.
// Block: 64 batch rows x 32 hidden cols x 4 gates (=128 weight rows).
// 8 warps: warp_m = wid&1 (32 rows), gate = wid>>5... (wid>>1). Warp tile 32x32.
// Grid (8,16) = 128 blocks.
// ---------------------------------------------------------------------------
__global__ void __launch_bounds__(256) lstm0_mma_k(
    const float* __restrict__ h0prev, float* __restrict__ h0cur,
    float* __restrict__ c0g, const float* __restrict__ Whh,
    const float* __restrict__ G0t)
{
    __shared__ union {
        struct { unsigned As[64 * 20]; unsigned Bs[128 * 20]; } t;
        float sg[4][64][33];
    } u;
    int tid = threadIdx.x, lane = tid & 31, wid = tid >> 5;
    int wm = wid & 1, gate = wid >> 1;
    int n0 = blockIdx.x * 32, m0 = blockIdx.y * 64;
    int ar = tid >> 2, k4 = (tid & 3) * 4;
    int j0 = tid >> 2, j1 = j0 + 64;
    // weight global row offsets for Bs cols j0/j1
    size_t w0off = (size_t)((j0 >> 5) * Hc + n0 + (j0 & 31)) * Hc;
    size_t w1off = (size_t)((j1 >> 5) * Hc + n0 + (j1 & 31)) * Hc;

    float4 pa  = *(const float4*)(h0prev + (size_t)(m0 + ar) * Hc + k4);
    float4 pw0 = *(const float4*)(Whh + w0off + k4);
    float4 pw1 = *(const float4*)(Whh + w1off + k4);

    float acc[2][4][4] = {};
    for (int k0 = 0; k0 < Hc; k0 += 16) {
        __syncthreads();
        u.t.As[ar*20 + k4+0]=cvt_tf32(pa.x); u.t.As[ar*20 + k4+1]=cvt_tf32(pa.y);
        u.t.As[ar*20 + k4+2]=cvt_tf32(pa.z); u.t.As[ar*20 + k4+3]=cvt_tf32(pa.w);
        u.t.Bs[j0*20 + k4+0]=cvt_tf32(pw0.x); u.t.Bs[j0*20 + k4+1]=cvt_tf32(pw0.y);
        u.t.Bs[j0*20 + k4+2]=cvt_tf32(pw0.z); u.t.Bs[j0*20 + k4+3]=cvt_tf32(pw0.w);
        u.t.Bs[j1*20 + k4+0]=cvt_tf32(pw1.x); u.t.Bs[j1*20 + k4+1]=cvt_tf32(pw1.y);
        u.t.Bs[j1*20 + k4+2]=cvt_tf32(pw1.z); u.t.Bs[j1*20 + k4+3]=cvt_tf32(pw1.w);
        __syncthreads();

        if (k0 + 16 < Hc) {
            pa  = *(const float4*)(h0prev + (size_t)(m0 + ar) * Hc + k0 + 16 + k4);
            pw0 = *(const float4*)(Whh + w0off + k0 + 16 + k4);
            pw1 = *(const float4*)(Whh + w1off + k0 + 16 + k4);
        }

        int qr = lane >> 2, qk = lane & 3;
        #pragma unroll
        for (int ks = 0; ks < 16; ks += 8) {
            unsigned af[2][4], bf[4][2];
            #pragma unroll
            for (int mt = 0; mt < 2; mt++) {
                int rb = wm * 32 + mt * 16;
                af[mt][0] = u.t.As[(rb     + qr)*20 + ks     + qk];
                af[mt][1] = u.t.As[(rb + 8 + qr)*20 + ks     + qk];
                af[mt][2] = u.t.As[(rb     + qr)*20 + ks + 4 + qk];
                af[mt][3] = u.t.As[(rb + 8 + qr)*20 + ks + 4 + qk];
            }
            #pragma unroll
            for (int nt = 0; nt < 4; nt++) {
                int cb = gate * 32 + nt * 8;
                bf[nt][0] = u.t.Bs[(cb + qr)*20 + ks     + qk];
                bf[nt][1] = u.t.Bs[(cb + qr)*20 + ks + 4 + qk];
            }
            #pragma unroll
            for (int mt = 0; mt < 2; mt++)
                #pragma unroll
                for (int nt = 0; nt < 4; nt++)
                    mma8(acc[mt][nt], af[mt], bf[nt]);
        }
    }
    __syncthreads();  // As/Bs dead; reuse as sg
    {
        int qr = lane >> 2, qk = lane & 3;
        #pragma unroll
        for (int mt = 0; mt < 2; mt++)
            #pragma unroll
            for (int nt = 0; nt < 4; nt++) {
                int row = wm * 32 + mt * 16 + qr;
                int col = nt * 8 + 2 * qk;
                u.sg[gate][row    ][col]     = acc[mt][nt][0];
                u.sg[gate][row    ][col + 1] = acc[mt][nt][1];
                u.sg[gate][row + 8][col]     = acc[mt][nt][2];
                u.sg[gate][row + 8][col + 1] = acc[mt][nt][3];
            }
    }
    __syncthreads();
    #pragma unroll
    for (int i = 0; i < 8; i++) {
        int idx = tid + i * 256;
        int m = idx >> 5, h = idx & 31;
        size_t gb = (size_t)(m0 + m) * H4c + n0 + h;
        float gi = u.sg[0][m][h] + G0t[gb];
        float gf = u.sg[1][m][h] + G0t[gb + 256];
        float gg = u.sg[2][m][h] + G0t[gb + 512];
        float go = u.sg[3][m][h] + G0t[gb + 768];
        size_t ci = (size_t)(m0 + m) * Hc + n0 + h;
        float c  = c0g[ci];
        float c2 = sigmoidf_(gf) * c + sigmoidf_(gi) * tanhf(gg);
        c0g[ci] = c2;
        h0cur[ci] = sigmoidf_(go) * tanhf(c2);
    }
}

// ---------------------------------------------------------------------------
// Fused LSTM layer-1 step: gates = xin@Wih^T + h1prev@Whh^T + bih + bhh
// Same tiling as lstm0; K loop over both sources (2 x 256).
// ---------------------------------------------------------------------------
__global__ void __launch_bounds__(256) lstm1_mma_k(
    const float* __restrict__ xin, const float* __restrict__ h1prev,
    float* __restrict__ h1cur, float* __restrict__ c1g,
    const float* __restrict__ Wih, const float* __restrict__ Whh,
    const float* __restrict__ bih, const float* __restrict__ bhh,
    float* __restrict__ hst)
{
    __shared__ union {
        struct { unsigned As[64 * 20]; unsigned Bs[128 * 20]; } t;
        float sg[4][64][33];
    } u;
    int tid = threadIdx.x, lane = tid & 31, wid = tid >> 5;
    int wm = wid & 1, gate = wid >> 1;
    int n0 = blockIdx.x * 32, m0 = blockIdx.y * 64;
    int ar = tid >> 2, k4 = (tid & 3) * 4;
    int j0 = tid >> 2, j1 = j0 + 64;
    size_t w0off = (size_t)((j0 >> 5) * Hc + n0 + (j0 & 31)) * Hc;
    size_t w1off = (size_t)((j1 >> 5) * Hc + n0 + (j1 & 31)) * Hc;

    const float* Ap[2] = {xin, h1prev};
    const float* Wp[2] = {Wih, Whh};

    float4 pa  = *(const float4*)(Ap[0] + (size_t)(m0 + ar) * Hc + k4);
    float4 pw0 = *(const float4*)(Wp[0] + w0off + k4);
    float4 pw1 = *(const float4*)(Wp[0] + w1off + k4);

    float acc[2][4][4] = {};
    for (int kk = 0; kk < 32; kk++) {
        __syncthreads();
        u.t.As[ar*20 + k4+0]=cvt_tf32(pa.x); u.t.As[ar*20 + k4+1]=cvt_tf32(pa.y);
        u.t.As[ar*20 + k4+2]=cvt_tf32(pa.z); u.t.As[ar*20 + k4+3]=cvt_tf32(pa.w);
        u.t.Bs[j0*20 + k4+0]=cvt_tf32(pw0.x); u.t.Bs[j0*20 + k4+1]=cvt_tf32(pw0.y);
        u.t.Bs[j0*20 + k4+2]=cvt_tf32(pw0.z); u.t.Bs[j0*20 + k4+3]=cvt_tf32(pw0.w);
        u.t.Bs[j1*20 + k4+0]=cvt_tf32(pw1.x); u.t.Bs[j1*20 + k4+1]=cvt_tf32(pw1.y);
        u.t.Bs[j1*20 + k4+2]=cvt_tf32(pw1.z); u.t.Bs[j1*20 + k4+3]=cvt_tf32(pw1.w);
        __syncthreads();

        int nk = kk + 1;
        if (nk < 32) {
            int s = nk >> 4, k0 = (nk & 15) * 16;
            pa  = *(const float4*)(Ap[s] + (size_t)(m0 + ar) * Hc + k0 + k4);
            pw0 = *(const float4*)(Wp[s] + w0off + k0 + k4);
            pw1 = *(const float4*)(Wp[s] + w1off + k0 + k4);
        }

        int qr = lane >> 2, qk = lane & 3;
        #pragma unroll
        for (int ks = 0; ks < 16; ks += 8) {
            unsigned af[2][4], bf[4][2];
            #pragma unroll
            for (int mt = 0; mt < 2; mt++) {
                int rb = wm * 32 + mt * 16;
                af[mt][0] = u.t.As[(rb     + qr)*20 + ks     + qk];
                af[mt][1] = u.t.As[(rb + 8 + qr)*20 + ks     + qk];
                af[mt][2] = u.t.As[(rb     + qr)*20 + ks + 4 + qk];
                af[mt][3] = u.t.As[(rb + 8 + qr)*20 + ks + 4 + qk];
            }
            #pragma unroll
            for (int nt = 0; nt < 4; nt++) {
                int cb = gate * 32 + nt * 8;
                bf[nt][0] = u.t.Bs[(cb + qr)*20 + ks     + qk];
                bf[nt][1] = u.t.Bs[(cb + qr)*20 + ks + 4 + qk];
            }
            #pragma unroll
            for (int mt = 0; mt < 2; mt++)
                #pragma unroll
                for (int nt = 0; nt < 4; nt++)
                    mma8(acc[mt][nt], af[mt], bf[nt]);
        }
    }
    __syncthreads();
    {
        int qr = lane >> 2, qk = lane & 3;
        #pragma unroll
        for (int mt = 0; mt < 2; mt++)
            #pragma unroll
            for (int nt = 0; nt < 4; nt++) {
                int row = wm * 32 + mt * 16 + qr;
                int col = nt * 8 + 2 * qk;
                u.sg[gate][row    ][col]     = acc[mt][nt][0];
                u.sg[gate][row    ][col + 1] = acc[mt][nt][1];
                u.sg[gate][row + 8][col]     = acc[mt][nt][2];
                u.sg[gate][row + 8][col + 1] = acc[mt][nt][3];
            }
    }
    __syncthreads();
    #pragma unroll
    for (int i = 0; i < 8; i++) {
        int idx = tid + i * 256;
        int m = idx >> 5, h = idx & 31;
        int n = n0 + h;
        float bi = bih[n]           + bhh[n];
        float bf_ = bih[Hc + n]     + bhh[Hc + n];
        float bg = bih[2 * Hc + n]  + bhh[2 * Hc + n];
        float bo = bih[3 * Hc + n]  + bhh[3 * Hc + n];
        size_t ci = (size_t)(m0 + m) * Hc + n;
        float c  = c1g[ci];
        float c2 = sigmoidf_(u.sg[1][m][h] + bf_) * c
                 + sigmoidf_(u.sg[0][m][h] + bi) * tanhf(u.sg[2][m][h] + bg);
        c1g[ci] = c2;
        float hv = sigmoidf_(u.sg[3][m][h] + bo) * tanhf(c2);
        h1cur[ci] = hv;
        hst[ci]   = hv;
    }
}

// ---------------------------------------------------------------------------
// Final layer: y = A @ Wo3^T + bo3  (N=6, K=256). One warp per row.
// ---------------------------------------------------------------------------
__global__ void __launch_bounds__(256) out_mlp3_k(
    const float* __restrict__ A, const float* __restrict__ W,
    const float* __restrict__ b, float* __restrict__ out)
{
    __shared__ float sW[LAGc * Hc];
    __shared__ float sb[LAGc];
    int tid = threadIdx.x;
    for (int i = tid; i < LAGc * Hc; i += 256) sW[i] = W[i];
    if (tid < LAGc) sb[tid] = b[tid];
    __syncthreads();
    int w = tid >> 5, lane = tid & 31;
    int m = blockIdx.x * 8 + w;
    float a[8];
    #pragma unroll
    for (int j = 0; j < 8; j++) a[j] = A[(size_t)m * Hc + lane + 32 * j];
    #pragma unroll
    for (int n = 0; n < LAGc; n++) {
        float s = 0.f;
        #pragma unroll
        for (int j = 0; j < 8; j++) s += a[j] * sW[n * Hc + lane + 32 * j];
        #pragma unroll
        for (int o = 16; o > 0; o >>= 1) s += __shfl_xor_sync(0xffffffff, s, o);
        if (lane == n) out[m * LAGc + n] = s + sb[n];
    }
}

// ---------------------------------------------------------------------------
extern "C" void kernel_launch(void* const* d_in, const int* in_sizes, int n_in,
                              void* d_out, int out_size)
{
    const float* x    = (const float*)d_in[0];
    const float* Wi1  = (const float*)d_in[1];
    const float* bi1  = (const float*)d_in[2];
    const float* Wi2  = (const float*)d_in[3];
    const float* bi2  = (const float*)d_in[4];
    const float* Wi3  = (const float*)d_in[5];
    const float* bi3  = (const float*)d_in[6];
    const float* Wih0 = (const float*)d_in[7];
    const float* Whh0 = (const float*)d_in[8];
    const float* bih0 = (const float*)d_in[9];
    const float* bhh0 = (const float*)d_in[10];
    const float* Wih1 = (const float*)d_in[11];
    const float* Whh1 = (const float*)d_in[12];
    const float* bih1 = (const float*)d_in[13];
    const float* bhh1 = (const float*)d_in[14];
    const float* Wo1  = (const float*)d_in[15];
    const float* bo1  = (const float*)d_in[16];
    const float* Wo2  = (const float*)d_in[17];
    const float* bo2  = (const float*)d_in[18];
    const float* Wo3  = (const float*)d_in[19];
    const float* bo3  = (const float*)d_in[20];
    float* out = (float*)d_out;

    float *buf0, *buf1, *G0, *hs, *h0, *h1, *c0, *c1;
    cudaGetSymbolAddress((void**)&buf0, g_buf0);
    cudaGetSymbolAddress((void**)&buf1, g_buf1);
    cudaGetSymbolAddress((void**)&G0,   g_G0);
    cudaGetSymbolAddress((void**)&hs,   g_hs);
    cudaGetSymbolAddress((void**)&h0,   g_h0);
    cudaGetSymbolAddress((void**)&h1,   g_h1);
    cudaGetSymbolAddress((void**)&c0,   g_c0);
    cudaGetSymbolAddress((void**)&c1,   g_c1);

    cudaMemsetAsync(h0, 0, BHc * sizeof(float));
    cudaMemsetAsync(h1, 0, BHc * sizeof(float));
    cudaMemsetAsync(c0, 0, BHc * sizeof(float));
    cudaMemsetAsync(c1, 0, BHc * sizeof(float));

    // Input MLP
    in_mlp1_k<<<TBc / 16, 256>>>(x, Wi1, bi1, buf0);
    dim3 gH(Hc / 128, TBc / 128);      // (2, 1024)
    gemm_mma_k<true, false><<<gH, 256>>>(buf0, Wi2, bi2, nullptr, buf1, TBc, Hc, Hc);
    gemm_mma_k<true, false><<<gH, 256>>>(buf1, Wi3, bi3, nullptr, buf0, TBc, Hc, Hc);

    // Layer-0 input projection for ALL timesteps (includes both biases)
    dim3 gG(H4c / 128, TBc / 128);     // (8, 1024)
    gemm_mma_k<false, false><<<gG, 256>>>(buf0, Wih0, bih0, bhh0, G0, TBc, H4c, Hc);

    // Sequential recurrence on tensor cores
    dim3 lg(Hc / 32, Bc / 64);         // (8, 16) = 128 blocks
    for (int t = 0; t < Tc; t++) {
        const float* h0p = h0 + (t & 1) * BHc;
        float*       h0n = h0 + ((t + 1) & 1) * BHc;
        const float* h1p = h1 + (t & 1) * BHc;
        float*       h1n = h1 + ((t + 1) & 1) * BHc;
        lstm0_mma_k<<<lg, 256>>>(h0p, h0n, c0, Whh0, G0 + (size_t)t * Bc * H4c);
        lstm1_mma_k<<<lg, 256>>>(h0n, h1p, h1n, c1, Wih1, Whh1, bih1, bhh1,
                                 hs + (size_t)t * BHc);
    }

    // Output MLP
    gemm_mma_k<true, true ><<<gH, 256>>>(hs,   Wo1, bo1, nullptr, buf0, TBc, Hc, Hc);
    gemm_mma_k<true, false><<<gH, 256>>>(buf0, Wo2, bo2, nullptr, buf1, TBc, Hc, Hc);
    out_mlp3_k<<<TBc / 8, 256>>>(buf1, Wo3, bo3, out);
}

// round 4
// speedup vs baseline: 2.6126x; 1.1725x over previous
#include <cuda_runtime.h>
#include <cuda_bf16.h>
#include <math.h>

// Problem constants
#define Tc   128
#define Bc   1024
#define LAGc 6
#define Hc   256
#define H4c  1024
#define TBc  (Tc * Bc)      // 131072
#define BHc  (Bc * Hc)      // 262144

// Persistent recurrence kernel geometry
#define NGRP   8            // batch groups of 128 rows
#define NSUB   16           // blocks per group (16 h-cols each)
#define NBLK   (NGRP * NSUB)
#define W0STR  260          // smem row stride (words) for layer0 weights (K=256)
#define W1STR  516          // smem row stride (words) for layer1 weights (K=512)
#define SMEM_P ((64 * W0STR + 64 * W1STR) * 4)   // 198656 bytes

// ---------------------------------------------------------------------------
// Scratch (device globals; no runtime allocation allowed)
// ---------------------------------------------------------------------------
__device__ float g_buf0[TBc * Hc];
__device__ float g_buf1[TBc * Hc];
__device__ float g_G0[(size_t)TBc * H4c];   // u@Wih0^T + bih0 + bhh0 for all T
__device__ float g_hs[TBc * Hc];
__device__ float g_h0[2 * BHc];
__device__ float g_h1[2 * BHc];
__device__ unsigned g_bar[NGRP];

// ---------------------------------------------------------------------------
// Helpers
// ---------------------------------------------------------------------------
__device__ __forceinline__ unsigned cvt_tf32(float x) {
    unsigned u; asm("cvt.rna.tf32.f32 %0, %1;" : "=r"(u) : "f"(x)); return u;
}
__device__ __forceinline__ void mma8(float* d, const unsigned* a, const unsigned* b) {
    asm volatile("mma.sync.aligned.m16n8k8.row.col.f32.tf32.tf32.f32 "
        "{%0,%1,%2,%3}, {%4,%5,%6,%7}, {%8,%9}, {%0,%1,%2,%3};"
        : "+f"(d[0]), "+f"(d[1]), "+f"(d[2]), "+f"(d[3])
        : "r"(a[0]), "r"(a[1]), "r"(a[2]), "r"(a[3]), "r"(b[0]), "r"(b[1]));
}
__device__ __forceinline__ float sigmoidf_(float v) { return 1.f / (1.f + expf(-v)); }

// Group barrier: monotone counter, fence + atomic arrive, tid0 spins.
__device__ __forceinline__ void group_barrier(unsigned* ctr, unsigned target) {
    __syncthreads();
    if (threadIdx.x == 0) {
        __threadfence();
        atomicAdd(ctr, 1u);
        while (atomicAdd(ctr, 0u) < target) { }
        __threadfence();
    }
    __syncthreads();
}

// ---------------------------------------------------------------------------
// Kernel 1: u = relu(x @ Wi1^T + bi1)   [TB,6] -> [TB,256]
// ---------------------------------------------------------------------------
__global__ void __launch_bounds__(256) in_mlp1_k(
    const float* __restrict__ x, const float* __restrict__ W,
    const float* __restrict__ b, float* __restrict__ out)
{
    __shared__ float sW[Hc * LAGc];
    __shared__ float sb[Hc];
    __shared__ float sx[16 * LAGc];
    int tid = threadIdx.x;
    int m0  = blockIdx.x * 16;
    for (int i = tid; i < Hc * LAGc; i += 256) sW[i] = W[i];
    sb[tid] = b[tid];
    if (tid < 16 * LAGc) sx[tid] = x[m0 * LAGc + tid];
    __syncthreads();
    #pragma unroll
    for (int r = 0; r < 16; r++) {
        float acc = sb[tid];
        #pragma unroll
        for (int k = 0; k < LAGc; k++) acc += sx[r * LAGc + k] * sW[tid * LAGc + k];
        out[(m0 + r) * Hc + tid] = fmaxf(acc, 0.f);
    }
}

// ---------------------------------------------------------------------------
// Generic tf32 tensor-core GEMM (unchanged from round 3).
// ---------------------------------------------------------------------------
template<bool RELU_OUT, bool PRE_RELU>
__global__ void __launch_bounds__(256) gemm_mma_k(
    const float* __restrict__ A, const float* __restrict__ W,
    const float* __restrict__ b1, const float* __restrict__ b2,
    float* __restrict__ C, int M, int N, int K)
{
    __shared__ unsigned As[128 * 20];
    __shared__ unsigned Bs[128 * 20];
    int tid = threadIdx.x, lane = tid & 31, wid = tid >> 5;
    int wm = wid & 1, wn = wid >> 1;
    int m0 = blockIdx.y * 128, n0 = blockIdx.x * 128;
    int r0 = tid >> 2;
    int k4 = (tid & 3) * 4;

    const float* Ab = A + (size_t)m0 * K;
    const float* Wb = W + (size_t)n0 * K;

    float4 pa0 = *(const float4*)(Ab + (size_t)r0 * K + k4);
    float4 pa1 = *(const float4*)(Ab + (size_t)(r0 + 64) * K + k4);
    float4 pw0 = *(const float4*)(Wb + (size_t)r0 * K + k4);
    float4 pw1 = *(const float4*)(Wb + (size_t)(r0 + 64) * K + k4);

    float acc[4][4][4] = {};
    for (int k0 = 0; k0 < K; k0 += 16) {
        __syncthreads();
        float4 v;
        v = pa0;
        if (PRE_RELU) { v.x=fmaxf(v.x,0.f); v.y=fmaxf(v.y,0.f); v.z=fmaxf(v.z,0.f); v.w=fmaxf(v.w,0.f); }
        As[r0*20 + k4+0]=cvt_tf32(v.x); As[r0*20 + k4+1]=cvt_tf32(v.y);
        As[r0*20 + k4+2]=cvt_tf32(v.z); As[r0*20 + k4+3]=cvt_tf32(v.w);
        v = pa1;
        if (PRE_RELU) { v.x=fmaxf(v.x,0.f); v.y=fmaxf(v.y,0.f); v.z=fmaxf(v.z,0.f); v.w=fmaxf(v.w,0.f); }
        As[(r0+64)*20 + k4+0]=cvt_tf32(v.x); As[(r0+64)*20 + k4+1]=cvt_tf32(v.y);
        As[(r0+64)*20 + k4+2]=cvt_tf32(v.z); As[(r0+64)*20 + k4+3]=cvt_tf32(v.w);
        Bs[r0*20 + k4+0]=cvt_tf32(pw0.x); Bs[r0*20 + k4+1]=cvt_tf32(pw0.y);
        Bs[r0*20 + k4+2]=cvt_tf32(pw0.z); Bs[r0*20 + k4+3]=cvt_tf32(pw0.w);
        Bs[(r0+64)*20 + k4+0]=cvt_tf32(pw1.x); Bs[(r0+64)*20 + k4+1]=cvt_tf32(pw1.y);
        Bs[(r0+64)*20 + k4+2]=cvt_tf32(pw1.z); Bs[(r0+64)*20 + k4+3]=cvt_tf32(pw1.w);
        __syncthreads();

        if (k0 + 16 < K) {
            pa0 = *(const float4*)(Ab + (size_t)r0 * K + k0 + 16 + k4);
            pa1 = *(const float4*)(Ab + (size_t)(r0 + 64) * K + k0 + 16 + k4);
            pw0 = *(const float4*)(Wb + (size_t)r0 * K + k0 + 16 + k4);
            pw1 = *(const float4*)(Wb + (size_t)(r0 + 64) * K + k0 + 16 + k4);
        }

        int qr = lane >> 2, qk = lane & 3;
        #pragma unroll
        for (int ks = 0; ks < 16; ks += 8) {
            unsigned af[4][4], bf[4][2];
            #pragma unroll
            for (int mt = 0; mt < 4; mt++) {
                int rb = wm * 64 + mt * 16;
                af[mt][0] = As[(rb     + qr)*20 + ks     + qk];
                af[mt][1] = As[(rb + 8 + qr)*20 + ks     + qk];
                af[mt][2] = As[(rb     + qr)*20 + ks + 4 + qk];
                af[mt][3] = As[(rb + 8 + qr)*20 + ks + 4 + qk];
            }
            #pragma unroll
            for (int nt = 0; nt < 4; nt++) {
                int cb = wn * 32 + nt * 8;
                bf[nt][0] = Bs[(cb + qr)*20 + ks     + qk];
                bf[nt][1] = Bs[(cb + qr)*20 + ks + 4 + qk];
            }
            #pragma unroll
            for (int mt = 0; mt < 4; mt++)
                #pragma unroll
                for (int nt = 0; nt < 4; nt++)
                    mma8(acc[mt][nt], af[mt], bf[nt]);
        }
    }

    int qr = lane >> 2, qk = lane & 3;
    #pragma unroll
    for (int nt = 0; nt < 4; nt++) {
        int col = n0 + wn * 32 + nt * 8 + 2 * qk;
        float bb0 = b1[col]     + (b2 ? b2[col]     : 0.f);
        float bb1 = b1[col + 1] + (b2 ? b2[col + 1] : 0.f);
        #pragma unroll
        for (int mt = 0; mt < 4; mt++) {
            int row = m0 + wm * 64 + mt * 16 + qr;
            float2 v0, v1;
            v0.x = acc[mt][nt][0] + bb0; v0.y = acc[mt][nt][1] + bb1;
            v1.x = acc[mt][nt][2] + bb0; v1.y = acc[mt][nt][3] + bb1;
            if (RELU_OUT) {
                v0.x=fmaxf(v0.x,0.f); v0.y=fmaxf(v0.y,0.f);
                v1.x=fmaxf(v1.x,0.f); v1.y=fmaxf(v1.y,0.f);
            }
            *(float2*)(C + (size_t)row * N + col)       = v0;
            *(float2*)(C + (size_t)(row + 8) * N + col) = v1;
        }
    }
}

// ---------------------------------------------------------------------------
// Fragment K-loop for the persistent LSTM kernel.
// A rows come straight from global (L2); B (weights, tf32) from smem.
// acc[nf][4], nf = gate*2 + half, covering N=64 gate cols (16 h x 4 gates).
// ---------------------------------------------------------------------------
__device__ __forceinline__ void frag_kloop(
    const float* __restrict__ Ar0, const float* __restrict__ Ar1,
    const unsigned* __restrict__ Wsm, int wstr, int kbase,
    int qr, int qk, float acc[8][4])
{
    #pragma unroll 4
    for (int ks = 0; ks < 32; ks++) {
        int k0 = ks * 8;
        unsigned a[4];
        a[0] = cvt_tf32(Ar0[k0 + qk]);
        a[1] = cvt_tf32(Ar1[k0 + qk]);
        a[2] = cvt_tf32(Ar0[k0 + 4 + qk]);
        a[3] = cvt_tf32(Ar1[k0 + 4 + qk]);
        #pragma unroll
        for (int nf = 0; nf < 8; nf++) {
            const unsigned* wp = Wsm + (nf * 8 + qr) * wstr + kbase + k0;
            unsigned b[2] = { wp[qk], wp[4 + qk] };
            mma8(acc[nf], a, b);
        }
    }
}

// ---------------------------------------------------------------------------
// Persistent recurrence kernel: all 128 timesteps, both LSTM layers.
// Grid = 128 blocks (8 groups x 16 subs), 256 threads (8 warps x M16).
// Weights live in smem for the whole kernel; c-state lives in registers.
// ---------------------------------------------------------------------------
__global__ void __launch_bounds__(256) lstm_persistent_k(
    const float* __restrict__ Whh0, const float* __restrict__ Wih1,
    const float* __restrict__ Whh1, const float* __restrict__ bih1,
    const float* __restrict__ bhh1, const float* __restrict__ G0,
    float* __restrict__ h0buf, float* __restrict__ h1buf,
    float* __restrict__ hs)
{
    extern __shared__ unsigned smem[];
    unsigned* W0 = smem;                  // [64][W0STR]
    unsigned* W1 = smem + 64 * W0STR;     // [64][W1STR]

    int tid = threadIdx.x, lane = tid & 31, wid = tid >> 5;
    int qr = lane >> 2, qk = lane & 3;
    int grp = blockIdx.x >> 4, sub = blockIdx.x & 15;
    int m0  = grp * 128;                  // batch rows
    int hc0 = sub * 16;                   // h-cols

    // ---- stage weights to smem as tf32 ----
    for (int i = tid; i < 64 * 64; i += 256) {           // layer0: 64n x 256k
        int n = i >> 6, kq = (i & 63) * 4;
        int gr = (n >> 4) * Hc + hc0 + (n & 15);
        float4 v = *(const float4*)(Whh0 + (size_t)gr * Hc + kq);
        unsigned* dst = W0 + n * W0STR + kq;
        dst[0]=cvt_tf32(v.x); dst[1]=cvt_tf32(v.y); dst[2]=cvt_tf32(v.z); dst[3]=cvt_tf32(v.w);
    }
    for (int i = tid; i < 64 * 128; i += 256) {          // layer1: 64n x 512k
        int n = i >> 7, kq = (i & 127) * 4;
        int gr = (n >> 4) * Hc + hc0 + (n & 15);
        const float* src = (kq < 256) ? (Wih1 + (size_t)gr * Hc + kq)
                                      : (Whh1 + (size_t)gr * Hc + (kq - 256));
        float4 v = *(const float4*)src;
        unsigned* dst = W1 + n * W1STR + kq;
        dst[0]=cvt_tf32(v.x); dst[1]=cvt_tf32(v.y); dst[2]=cvt_tf32(v.z); dst[3]=cvt_tf32(v.w);
    }
    __syncthreads();

    // ---- per-lane persistent state ----
    int wrow = wid * 16 + qr;             // local row (and wrow+8)
    float c0v[2][4] = {};                 // [r][h*2+p]
    float c1v[2][4] = {};
    float b1v[8][2];                      // [nf=g*2+h][p]
    #pragma unroll
    for (int g = 0; g < 4; g++)
        #pragma unroll
        for (int h = 0; h < 2; h++)
            #pragma unroll
            for (int p = 0; p < 2; p++) {
                int n = g * Hc + hc0 + h * 8 + 2 * qk + p;
                b1v[g * 2 + h][p] = bih1[n] + bhh1[n];
            }

    unsigned* ctr = &g_bar[grp];
    unsigned target = 0;

    for (int t = 0; t < Tc; t++) {
        const float* h0prev = h0buf + (t & 1) * BHc;
        float*       h0cur  = h0buf + ((t + 1) & 1) * BHc;
        const float* h1prev = h1buf + (t & 1) * BHc;
        float*       h1cur  = h1buf + ((t + 1) & 1) * BHc;

        // ================= layer 0 =================
        float acc[8][4] = {};
        {
            const float* Ar0 = h0prev + (size_t)(m0 + wrow) * Hc;
            frag_kloop(Ar0, Ar0 + 8 * Hc, W0, W0STR, 0, qr, qk, acc);
        }
        {
            const float* g0r0 = G0 + ((size_t)t * Bc + m0 + wrow) * H4c + hc0;
            #pragma unroll
            for (int r = 0; r < 2; r++) {
                const float* g0r = g0r0 + r * 8 * H4c;
                float* hw = h0cur + (size_t)(m0 + wrow + r * 8) * Hc + hc0;
                #pragma unroll
                for (int h = 0; h < 2; h++) {
                    int hcl = h * 8 + 2 * qk;
                    float2 gI = *(const float2*)(g0r + hcl);
                    float2 gF = *(const float2*)(g0r + 256 + hcl);
                    float2 gG = *(const float2*)(g0r + 512 + hcl);
                    float2 gO = *(const float2*)(g0r + 768 + hcl);
                    float hv[2];
                    #pragma unroll
                    for (int p = 0; p < 2; p++) {
                        float gi = acc[0 + h][r * 2 + p] + (p ? gI.y : gI.x);
                        float gf = acc[2 + h][r * 2 + p] + (p ? gF.y : gF.x);
                        float gg = acc[4 + h][r * 2 + p] + (p ? gG.y : gG.x);
                        float go = acc[6 + h][r * 2 + p] + (p ? gO.y : gO.x);
                        float c  = c0v[r][h * 2 + p];
                        float c2 = sigmoidf_(gf) * c + sigmoidf_(gi) * tanhf(gg);
                        c0v[r][h * 2 + p] = c2;
                        hv[p] = sigmoidf_(go) * tanhf(c2);
                    }
                    *(float2*)(hw + hcl) = make_float2(hv[0], hv[1]);
                }
            }
        }
        target += NSUB;
        group_barrier(ctr, target);

        // ================= layer 1 =================
        #pragma unroll
        for (int nf = 0; nf < 8; nf++)
            #pragma unroll
            for (int j = 0; j < 4; j++) acc[nf][j] = 0.f;
        {
            const float* Ar0 = h0cur + (size_t)(m0 + wrow) * Hc;
            frag_kloop(Ar0, Ar0 + 8 * Hc, W1, W1STR, 0, qr, qk, acc);
            const float* Br0 = h1prev + (size_t)(m0 + wrow) * Hc;
            frag_kloop(Br0, Br0 + 8 * Hc, W1, W1STR, 256, qr, qk, acc);
        }
        {
            #pragma unroll
            for (int r = 0; r < 2; r++) {
                float* hw = h1cur + (size_t)(m0 + wrow + r * 8) * Hc + hc0;
                float* ho = hs + (size_t)t * BHc + (size_t)(m0 + wrow + r * 8) * Hc + hc0;
                #pragma unroll
                for (int h = 0; h < 2; h++) {
                    int hcl = h * 8 + 2 * qk;
                    float hv[2];
                    #pragma unroll
                    for (int p = 0; p < 2; p++) {
                        float gi = acc[0 + h][r * 2 + p] + b1v[0 + h][p];
                        float gf = acc[2 + h][r * 2 + p] + b1v[2 + h][p];
                        float gg = acc[4 + h][r * 2 + p] + b1v[4 + h][p];
                        float go = acc[6 + h][r * 2 + p] + b1v[6 + h][p];
                        float c  = c1v[r][h * 2 + p];
                        float c2 = sigmoidf_(gf) * c + sigmoidf_(gi) * tanhf(gg);
                        c1v[r][h * 2 + p] = c2;
                        hv[p] = sigmoidf_(go) * tanhf(c2);
                    }
                    float2 v2 = make_float2(hv[0], hv[1]);
                    *(float2*)(hw + hcl) = v2;
                    *(float2*)(ho + hcl) = v2;
                }
            }
        }
        target += NSUB;
        group_barrier(ctr, target);
    }
}

// ---------------------------------------------------------------------------
// Final layer: y = A @ Wo3^T + bo3  (N=6, K=256). One warp per row.
// ---------------------------------------------------------------------------
__global__ void __launch_bounds__(256) out_mlp3_k(
    const float* __restrict__ A, const float* __restrict__ W,
    const float* __restrict__ b, float* __restrict__ out)
{
    __shared__ float sW[LAGc * Hc];
    __shared__ float sb[LAGc];
    int tid = threadIdx.x;
    for (int i = tid; i < LAGc * Hc; i += 256) sW[i] = W[i];
    if (tid < LAGc) sb[tid] = b[tid];
    __syncthreads();
    int w = tid >> 5, lane = tid & 31;
    int m = blockIdx.x * 8 + w;
    float a[8];
    #pragma unroll
    for (int j = 0; j < 8; j++) a[j] = A[(size_t)m * Hc + lane + 32 * j];
    #pragma unroll
    for (int n = 0; n < LAGc; n++) {
        float s = 0.f;
        #pragma unroll
        for (int j = 0; j < 8; j++) s += a[j] * sW[n * Hc + lane + 32 * j];
        #pragma unroll
        for (int o = 16; o > 0; o >>= 1) s += __shfl_xor_sync(0xffffffff, s, o);
        if (lane == n) out[m * LAGc + n] = s + sb[n];
    }
}

// ---------------------------------------------------------------------------
extern "C" void kernel_launch(void* const* d_in, const int* in_sizes, int n_in,
                              void* d_out, int out_size)
{
    const float* x    = (const float*)d_in[0];
    const float* Wi1  = (const float*)d_in[1];
    const float* bi1  = (const float*)d_in[2];
    const float* Wi2  = (const float*)d_in[3];
    const float* bi2  = (const float*)d_in[4];
    const float* Wi3  = (const float*)d_in[5];
    const float* bi3  = (const float*)d_in[6];
    const float* Wih0 = (const float*)d_in[7];
    const float* Whh0 = (const float*)d_in[8];
    const float* bih0 = (const float*)d_in[9];
    const float* bhh0 = (const float*)d_in[10];
    const float* Wih1 = (const float*)d_in[11];
    const float* Whh1 = (const float*)d_in[12];
    const float* bih1 = (const float*)d_in[13];
    const float* bhh1 = (const float*)d_in[14];
    const float* Wo1  = (const float*)d_in[15];
    const float* bo1  = (const float*)d_in[16];
    const float* Wo2  = (const float*)d_in[17];
    const float* bo2  = (const float*)d_in[18];
    const float* Wo3  = (const float*)d_in[19];
    const float* bo3  = (const float*)d_in[20];
    float* out = (float*)d_out;

    float *buf0, *buf1, *G0, *hs, *h0, *h1;
    unsigned* bar;
    cudaGetSymbolAddress((void**)&buf0, g_buf0);
    cudaGetSymbolAddress((void**)&buf1, g_buf1);
    cudaGetSymbolAddress((void**)&G0,   g_G0);
    cudaGetSymbolAddress((void**)&hs,   g_hs);
    cudaGetSymbolAddress((void**)&h0,   g_h0);
    cudaGetSymbolAddress((void**)&h1,   g_h1);
    cudaGetSymbolAddress((void**)&bar,  g_bar);

    cudaFuncSetAttribute(lstm_persistent_k,
                         cudaFuncAttributeMaxDynamicSharedMemorySize, SMEM_P);

    cudaMemsetAsync(h0, 0, 2 * BHc * sizeof(float));
    cudaMemsetAsync(h1, 0, 2 * BHc * sizeof(float));
    cudaMemsetAsync(bar, 0, NGRP * sizeof(unsigned));

    // Input MLP
    in_mlp1_k<<<TBc / 16, 256>>>(x, Wi1, bi1, buf0);
    dim3 gH(Hc / 128, TBc / 128);
    gemm_mma_k<true, false><<<gH, 256>>>(buf0, Wi2, bi2, nullptr, buf1, TBc, Hc, Hc);
    gemm_mma_k<true, false><<<gH, 256>>>(buf1, Wi3, bi3, nullptr, buf0, TBc, Hc, Hc);

    // Layer-0 input projection for ALL timesteps (includes both biases)
    dim3 gG(H4c / 128, TBc / 128);
    gemm_mma_k<false, false><<<gG, 256>>>(buf0, Wih0, bih0, bhh0, G0, TBc, H4c, Hc);

    // Entire recurrence in one persistent launch
    lstm_persistent_k<<<NBLK, 256, SMEM_P>>>(Whh0, Wih1, Whh1, bih1, bhh1,
                                             G0, h0, h1, hs);

    // Output MLP
    gemm_mma_k<true, true ><<<gH, 256>>>(hs,   Wo1, bo1, nullptr, buf0, TBc, Hc, Hc);
    gemm_mma_k<true, false><<<gH, 256>>>(buf0, Wo2, bo2, nullptr, buf1, TBc, Hc, Hc);
    out_mlp3_k<<<TBc / 8, 256>>>(buf1, Wo3, bo3, out);
}

// round 5
// speedup vs baseline: 2.9322x; 1.1223x over previous
#include <cuda_runtime.h>
#include <cuda_bf16.h>
#include <math.h>

// Problem constants
#define Tc   128
#define Bc   1024
#define LAGc 6
#define Hc   256
#define H4c  1024
#define TBc  (Tc * Bc)      // 131072
#define BHc  (Bc * Hc)      // 262144

// Persistent recurrence kernel geometry
#define NGRP   8            // batch groups of 128 rows
#define NSUB   16           // blocks per group (16 h-cols each)
#define NBLK   (NGRP * NSUB)
#define W0STR  260          // smem row stride (words) layer0 weights (K=256)
#define W1STR  516          // smem row stride (words) layer1 weights (K=512)
#define ASTR   20           // smem row stride (words) A staging (K-chunk 16)
#define ABUFW  (128 * ASTR) // words per A buffer (2560)
#define SMEM_P ((64 * W0STR + 64 * W1STR + 3 * ABUFW) * 4)   // 229376 bytes

// ---------------------------------------------------------------------------
// Scratch (device globals; no runtime allocation allowed)
// ---------------------------------------------------------------------------
__device__ float g_buf0[TBc * Hc];
__device__ float g_buf1[TBc * Hc];
__device__ float g_G0[(size_t)TBc * H4c];   // u@Wih0^T + bih0 + bhh0 for all T
__device__ float g_hs[TBc * Hc];
__device__ float g_h0[2 * BHc];
__device__ float g_h1[2 * BHc];
__device__ unsigned g_bar[NGRP];

// ---------------------------------------------------------------------------
// Helpers
// ---------------------------------------------------------------------------
__device__ __forceinline__ unsigned cvt_tf32(float x) {
    unsigned u; asm("cvt.rna.tf32.f32 %0, %1;" : "=r"(u) : "f"(x)); return u;
}
__device__ __forceinline__ void mma8(float* d, const unsigned* a, const unsigned* b) {
    asm volatile("mma.sync.aligned.m16n8k8.row.col.f32.tf32.tf32.f32 "
        "{%0,%1,%2,%3}, {%4,%5,%6,%7}, {%8,%9}, {%0,%1,%2,%3};"
        : "+f"(d[0]), "+f"(d[1]), "+f"(d[2]), "+f"(d[3])
        : "r"(a[0]), "r"(a[1]), "r"(a[2]), "r"(a[3]), "r"(b[0]), "r"(b[1]));
}
__device__ __forceinline__ float sigmoidf_(float v) { return 1.f / (1.f + expf(-v)); }

__device__ __forceinline__ void cp_async16(void* dst, const void* src) {
    unsigned d = (unsigned)__cvta_generic_to_shared(dst);
    asm volatile("cp.async.ca.shared.global [%0], [%1], 16;\n" :: "r"(d), "l"(src));
}
__device__ __forceinline__ void cp_commit() {
    asm volatile("cp.async.commit_group;\n");
}
template<int N> __device__ __forceinline__ void cp_wait() {
    asm volatile("cp.async.wait_group %0;\n" :: "n"(N));
}

// Group barrier: monotone counter; fence + atomic arrive; tid0 polls via L2 read.
__device__ __forceinline__ void group_barrier(unsigned* ctr, unsigned target) {
    __syncthreads();
    if (threadIdx.x == 0) {
        __threadfence();
        atomicAdd(ctr, 1u);
        volatile unsigned* p = (volatile unsigned*)ctr;
        while (*p < target) { }
        __threadfence();
    }
    __syncthreads();
}

// ---------------------------------------------------------------------------
// Kernel 1: u = relu(x @ Wi1^T + bi1)   [TB,6] -> [TB,256]
// ---------------------------------------------------------------------------
__global__ void __launch_bounds__(256) in_mlp1_k(
    const float* __restrict__ x, const float* __restrict__ W,
    const float* __restrict__ b, float* __restrict__ out)
{
    __shared__ float sW[Hc * LAGc];
    __shared__ float sb[Hc];
    __shared__ float sx[16 * LAGc];
    int tid = threadIdx.x;
    int m0  = blockIdx.x * 16;
    for (int i = tid; i < Hc * LAGc; i += 256) sW[i] = W[i];
    sb[tid] = b[tid];
    if (tid < 16 * LAGc) sx[tid] = x[m0 * LAGc + tid];
    __syncthreads();
    #pragma unroll
    for (int r = 0; r < 16; r++) {
        float acc = sb[tid];
        #pragma unroll
        for (int k = 0; k < LAGc; k++) acc += sx[r * LAGc + k] * sW[tid * LAGc + k];
        out[(m0 + r) * Hc + tid] = fmaxf(acc, 0.f);
    }
}

// ---------------------------------------------------------------------------
// Generic tf32 tensor-core GEMM (unchanged).
// ---------------------------------------------------------------------------
template<bool RELU_OUT, bool PRE_RELU>
__global__ void __launch_bounds__(256) gemm_mma_k(
    const float* __restrict__ A, const float* __restrict__ W,
    const float* __restrict__ b1, const float* __restrict__ b2,
    float* __restrict__ C, int M, int N, int K)
{
    __shared__ unsigned As[128 * 20];
    __shared__ unsigned Bs[128 * 20];
    int tid = threadIdx.x, lane = tid & 31, wid = tid >> 5;
    int wm = wid & 1, wn = wid >> 1;
    int m0 = blockIdx.y * 128, n0 = blockIdx.x * 128;
    int r0 = tid >> 2;
    int k4 = (tid & 3) * 4;

    const float* Ab = A + (size_t)m0 * K;
    const float* Wb = W + (size_t)n0 * K;

    float4 pa0 = *(const float4*)(Ab + (size_t)r0 * K + k4);
    float4 pa1 = *(const float4*)(Ab + (size_t)(r0 + 64) * K + k4);
    float4 pw0 = *(const float4*)(Wb + (size_t)r0 * K + k4);
    float4 pw1 = *(const float4*)(Wb + (size_t)(r0 + 64) * K + k4);

    float acc[4][4][4] = {};
    for (int k0 = 0; k0 < K; k0 += 16) {
        __syncthreads();
        float4 v;
        v = pa0;
        if (PRE_RELU) { v.x=fmaxf(v.x,0.f); v.y=fmaxf(v.y,0.f); v.z=fmaxf(v.z,0.f); v.w=fmaxf(v.w,0.f); }
        As[r0*20 + k4+0]=cvt_tf32(v.x); As[r0*20 + k4+1]=cvt_tf32(v.y);
        As[r0*20 + k4+2]=cvt_tf32(v.z); As[r0*20 + k4+3]=cvt_tf32(v.w);
        v = pa1;
        if (PRE_RELU) { v.x=fmaxf(v.x,0.f); v.y=fmaxf(v.y,0.f); v.z=fmaxf(v.z,0.f); v.w=fmaxf(v.w,0.f); }
        As[(r0+64)*20 + k4+0]=cvt_tf32(v.x); As[(r0+64)*20 + k4+1]=cvt_tf32(v.y);
        As[(r0+64)*20 + k4+2]=cvt_tf32(v.z); As[(r0+64)*20 + k4+3]=cvt_tf32(v.w);
        Bs[r0*20 + k4+0]=cvt_tf32(pw0.x); Bs[r0*20 + k4+1]=cvt_tf32(pw0.y);
        Bs[r0*20 + k4+2]=cvt_tf32(pw0.z); Bs[r0*20 + k4+3]=cvt_tf32(pw0.w);
        Bs[(r0+64)*20 + k4+0]=cvt_tf32(pw1.x); Bs[(r0+64)*20 + k4+1]=cvt_tf32(pw1.y);
        Bs[(r0+64)*20 + k4+2]=cvt_tf32(pw1.z); Bs[(r0+64)*20 + k4+3]=cvt_tf32(pw1.w);
        __syncthreads();

        if (k0 + 16 < K) {
            pa0 = *(const float4*)(Ab + (size_t)r0 * K + k0 + 16 + k4);
            pa1 = *(const float4*)(Ab + (size_t)(r0 + 64) * K + k0 + 16 + k4);
            pw0 = *(const float4*)(Wb + (size_t)r0 * K + k0 + 16 + k4);
            pw1 = *(const float4*)(Wb + (size_t)(r0 + 64) * K + k0 + 16 + k4);
        }

        int qr = lane >> 2, qk = lane & 3;
        #pragma unroll
        for (int ks = 0; ks < 16; ks += 8) {
            unsigned af[4][4], bf[4][2];
            #pragma unroll
            for (int mt = 0; mt < 4; mt++) {
                int rb = wm * 64 + mt * 16;
                af[mt][0] = As[(rb     + qr)*20 + ks     + qk];
                af[mt][1] = As[(rb + 8 + qr)*20 + ks     + qk];
                af[mt][2] = As[(rb     + qr)*20 + ks + 4 + qk];
                af[mt][3] = As[(rb + 8 + qr)*20 + ks + 4 + qk];
            }
            #pragma unroll
            for (int nt = 0; nt < 4; nt++) {
                int cb = wn * 32 + nt * 8;
                bf[nt][0] = Bs[(cb + qr)*20 + ks     + qk];
                bf[nt][1] = Bs[(cb + qr)*20 + ks + 4 + qk];
            }
            #pragma unroll
            for (int mt = 0; mt < 4; mt++)
                #pragma unroll
                for (int nt = 0; nt < 4; nt++)
                    mma8(acc[mt][nt], af[mt], bf[nt]);
        }
    }

    int qr = lane >> 2, qk = lane & 3;
    #pragma unroll
    for (int nt = 0; nt < 4; nt++) {
        int col = n0 + wn * 32 + nt * 8 + 2 * qk;
        float bb0 = b1[col]     + (b2 ? b2[col]     : 0.f);
        float bb1 = b1[col + 1] + (b2 ? b2[col + 1] : 0.f);
        #pragma unroll
        for (int mt = 0; mt < 4; mt++) {
            int row = m0 + wm * 64 + mt * 16 + qr;
            float2 v0, v1;
            v0.x = acc[mt][nt][0] + bb0; v0.y = acc[mt][nt][1] + bb1;
            v1.x = acc[mt][nt][2] + bb0; v1.y = acc[mt][nt][3] + bb1;
            if (RELU_OUT) {
                v0.x=fmaxf(v0.x,0.f); v0.y=fmaxf(v0.y,0.f);
                v1.x=fmaxf(v1.x,0.f); v1.y=fmaxf(v1.y,0.f);
            }
            *(float2*)(C + (size_t)row * N + col)       = v0;
            *(float2*)(C + (size_t)(row + 8) * N + col) = v1;
        }
    }
}

// ---------------------------------------------------------------------------
// Persistent LSTM: chunk staging + mma helpers
// ---------------------------------------------------------------------------
// Stage one 128x16 fp32 A chunk into smem buffer via cp.async (2x16B per thread).
__device__ __forceinline__ void stage_chunk(float* Abuf, const float* src_base, int tid) {
    #pragma unroll
    for (int i = 0; i < 2; i++) {
        int s = tid + i * 256;
        int row = s >> 2, kq = (s & 3) * 4;
        cp_async16(Abuf + row * ASTR + kq, src_base + (size_t)row * Hc + kq);
    }
    cp_commit();
}

// MMA over one staged chunk (2 k-steps of 8). A fp32 in smem (cvt at read).
__device__ __forceinline__ void mma_chunk(
    const float* Ab, const unsigned* Wsm, int wstr, int kbase,
    int wid, int qr, int qk, float acc[8][4])
{
    #pragma unroll
    for (int ks = 0; ks < 2; ks++) {
        int k0 = ks * 8;
        const float* ar = Ab + (wid * 16 + qr) * ASTR + k0;
        unsigned a[4];
        a[0] = cvt_tf32(ar[qk]);
        a[1] = cvt_tf32(ar[8 * ASTR + qk]);
        a[2] = cvt_tf32(ar[4 + qk]);
        a[3] = cvt_tf32(ar[8 * ASTR + 4 + qk]);
        #pragma unroll
        for (int nf = 0; nf < 8; nf++) {
            const unsigned* wp = Wsm + (nf * 8 + qr) * wstr + kbase + k0;
            unsigned b[2] = { wp[qk], wp[4 + qk] };
            mma8(acc[nf], a, b);
        }
    }
}

// ---------------------------------------------------------------------------
// Persistent recurrence kernel: all 128 timesteps, both LSTM layers.
// Grid = 128 blocks (8 groups x 16 subs), 256 threads (8 warps x M16).
// Weights resident in smem; c-state in registers; A staged via cp.async.
// ---------------------------------------------------------------------------
__global__ void __launch_bounds__(256, 1) lstm_persistent_k(
    const float* __restrict__ Whh0, const float* __restrict__ Wih1,
    const float* __restrict__ Whh1, const float* __restrict__ bih1,
    const float* __restrict__ bhh1, const float* __restrict__ G0,
    float* __restrict__ h0buf, float* __restrict__ h1buf,
    float* __restrict__ hs)
{
    extern __shared__ unsigned smem[];
    unsigned* W0 = smem;                       // [64][W0STR]
    unsigned* W1 = smem + 64 * W0STR;          // [64][W1STR]
    float* Abuf  = (float*)(smem + 64 * W0STR + 64 * W1STR);  // 3 x [128][ASTR]

    int tid = threadIdx.x, lane = tid & 31, wid = tid >> 5;
    int qr = lane >> 2, qk = lane & 3;
    int grp = blockIdx.x >> 4, sub = blockIdx.x & 15;
    int m0  = grp * 128;                  // batch rows
    int hc0 = sub * 16;                   // h-cols

    // ---- stage weights to smem as tf32 (once) ----
    for (int i = tid; i < 64 * 64; i += 256) {           // layer0: 64n x 256k
        int n = i >> 6, kq = (i & 63) * 4;
        int gr = (n >> 4) * Hc + hc0 + (n & 15);
        float4 v = *(const float4*)(Whh0 + (size_t)gr * Hc + kq);
        unsigned* dst = W0 + n * W0STR + kq;
        dst[0]=cvt_tf32(v.x); dst[1]=cvt_tf32(v.y); dst[2]=cvt_tf32(v.z); dst[3]=cvt_tf32(v.w);
    }
    for (int i = tid; i < 64 * 128; i += 256) {          // layer1: 64n x 512k
        int n = i >> 7, kq = (i & 127) * 4;
        int gr = (n >> 4) * Hc + hc0 + (n & 15);
        const float* src = (kq < 256) ? (Wih1 + (size_t)gr * Hc + kq)
                                      : (Whh1 + (size_t)gr * Hc + (kq - 256));
        float4 v = *(const float4*)src;
        unsigned* dst = W1 + n * W1STR + kq;
        dst[0]=cvt_tf32(v.x); dst[1]=cvt_tf32(v.y); dst[2]=cvt_tf32(v.z); dst[3]=cvt_tf32(v.w);
    }
    __syncthreads();

    // ---- per-lane persistent state ----
    int wrow = wid * 16 + qr;             // local row (pair at wrow+8)
    float c0v[2][4] = {};                 // [r][h*2+p]
    float c1v[2][4] = {};
    float b1v[8][2];                      // [nf=g*2+h][p]
    #pragma unroll
    for (int g = 0; g < 4; g++)
        #pragma unroll
        for (int h = 0; h < 2; h++)
            #pragma unroll
            for (int p = 0; p < 2; p++) {
                int n = g * Hc + hc0 + h * 8 + 2 * qk + p;
                b1v[g * 2 + h][p] = bih1[n] + bhh1[n];
            }

    unsigned* ctr = &g_bar[grp];
    unsigned target = 0;

    for (int t = 0; t < Tc; t++) {
        const float* h0prev = h0buf + (t & 1) * BHc;
        float*       h0cur  = h0buf + ((t + 1) & 1) * BHc;
        const float* h1prev = h1buf + (t & 1) * BHc;
        float*       h1cur  = h1buf + ((t + 1) & 1) * BHc;

        // ================= layer 0 (K=256, 16 chunks) =================
        // Prefetch G0 gate slabs into registers (DRAM latency hidden by mma loop)
        float2 gI[2][2], gF[2][2], gG[2][2], gO[2][2];
        {
            const float* g0r0 = G0 + ((size_t)t * Bc + m0 + wrow) * H4c + hc0;
            #pragma unroll
            for (int r = 0; r < 2; r++) {
                const float* g0r = g0r0 + (size_t)r * 8 * H4c;
                #pragma unroll
                for (int h = 0; h < 2; h++) {
                    int hcl = h * 8 + 2 * qk;
                    gI[r][h] = *(const float2*)(g0r + hcl);
                    gF[r][h] = *(const float2*)(g0r + 256 + hcl);
                    gG[r][h] = *(const float2*)(g0r + 512 + hcl);
                    gO[r][h] = *(const float2*)(g0r + 768 + hcl);
                }
            }
        }

        float acc[8][4] = {};
        {
            const float* A0 = h0prev + (size_t)m0 * Hc;
            stage_chunk(Abuf + 0 * ABUFW, A0 + 0 * 16, tid);
            stage_chunk(Abuf + 1 * ABUFW, A0 + 1 * 16, tid);
            #pragma unroll 4
            for (int c = 0; c < 16; c++) {
                if (c == 15) cp_wait<0>(); else cp_wait<1>();
                __syncthreads();
                if (c + 2 < 16)
                    stage_chunk(Abuf + ((c + 2) % 3) * ABUFW, A0 + (c + 2) * 16, tid);
                mma_chunk(Abuf + (c % 3) * ABUFW, W0, W0STR, c * 16, wid, qr, qk, acc);
            }
        }
        // epilogue: cell update, write h0cur
        #pragma unroll
        for (int r = 0; r < 2; r++) {
            float* hw = h0cur + (size_t)(m0 + wrow + r * 8) * Hc + hc0;
            #pragma unroll
            for (int h = 0; h < 2; h++) {
                int hcl = h * 8 + 2 * qk;
                float hv[2];
                #pragma unroll
                for (int p = 0; p < 2; p++) {
                    float gi = acc[0 + h][r * 2 + p] + (p ? gI[r][h].y : gI[r][h].x);
                    float gf = acc[2 + h][r * 2 + p] + (p ? gF[r][h].y : gF[r][h].x);
                    float gg = acc[4 + h][r * 2 + p] + (p ? gG[r][h].y : gG[r][h].x);
                    float go = acc[6 + h][r * 2 + p] + (p ? gO[r][h].y : gO[r][h].x);
                    float c  = c0v[r][h * 2 + p];
                    float c2 = sigmoidf_(gf) * c + sigmoidf_(gi) * tanhf(gg);
                    c0v[r][h * 2 + p] = c2;
                    hv[p] = sigmoidf_(go) * tanhf(c2);
                }
                *(float2*)(hw + hcl) = make_float2(hv[0], hv[1]);
            }
        }

        // single barrier per step (orders h0cur for layer1, and previous
        // step's h1cur for the next layer1 — see ordering analysis)
        target += NSUB;
        group_barrier(ctr, target);

        // ================= layer 1 (K=512, 32 chunks) =================
        #pragma unroll
        for (int nf = 0; nf < 8; nf++)
            #pragma unroll
            for (int j = 0; j < 4; j++) acc[nf][j] = 0.f;
        {
            const float* A0 = h0cur + (size_t)m0 * Hc;
            const float* A1 = h1prev + (size_t)m0 * Hc;
            stage_chunk(Abuf + 0 * ABUFW, A0 + 0 * 16, tid);
            stage_chunk(Abuf + 1 * ABUFW, A0 + 1 * 16, tid);
            #pragma unroll 4
            for (int c = 0; c < 32; c++) {
                if (c == 31) cp_wait<0>(); else cp_wait<1>();
                __syncthreads();
                if (c + 2 < 32) {
                    int cn = c + 2;
                    const float* src = (cn < 16) ? (A0 + cn * 16) : (A1 + (cn - 16) * 16);
                    stage_chunk(Abuf + (cn % 3) * ABUFW, src, tid);
                }
                mma_chunk(Abuf + (c % 3) * ABUFW, W1, W1STR, c * 16, wid, qr, qk, acc);
            }
        }
        // epilogue: cell update, write h1cur and hs
        #pragma unroll
        for (int r = 0; r < 2; r++) {
            float* hw = h1cur + (size_t)(m0 + wrow + r * 8) * Hc + hc0;
            float* ho = hs + (size_t)t * BHc + (size_t)(m0 + wrow + r * 8) * Hc + hc0;
            #pragma unroll
            for (int h = 0; h < 2; h++) {
                int hcl = h * 8 + 2 * qk;
                float hv[2];
                #pragma unroll
                for (int p = 0; p < 2; p++) {
                    float gi = acc[0 + h][r * 2 + p] + b1v[0 + h][p];
                    float gf = acc[2 + h][r * 2 + p] + b1v[2 + h][p];
                    float gg = acc[4 + h][r * 2 + p] + b1v[4 + h][p];
                    float go = acc[6 + h][r * 2 + p] + b1v[6 + h][p];
                    float c  = c1v[r][h * 2 + p];
                    float c2 = sigmoidf_(gf) * c + sigmoidf_(gi) * tanhf(gg);
                    c1v[r][h * 2 + p] = c2;
                    hv[p] = sigmoidf_(go) * tanhf(c2);
                }
                float2 v2 = make_float2(hv[0], hv[1]);
                *(float2*)(hw + hcl) = v2;
                *(float2*)(ho + hcl) = v2;
            }
        }
        // no second barrier: next step's post-layer0 barrier provides ordering
    }
}

// ---------------------------------------------------------------------------
// Final layer: y = A @ Wo3^T + bo3  (N=6, K=256). One warp per row.
// ---------------------------------------------------------------------------
__global__ void __launch_bounds__(256) out_mlp3_k(
    const float* __restrict__ A, const float* __restrict__ W,
    const float* __restrict__ b, float* __restrict__ out)
{
    __shared__ float sW[LAGc * Hc];
    __shared__ float sb[LAGc];
    int tid = threadIdx.x;
    for (int i = tid; i < LAGc * Hc; i += 256) sW[i] = W[i];
    if (tid < LAGc) sb[tid] = b[tid];
    __syncthreads();
    int w = tid >> 5, lane = tid & 31;
    int m = blockIdx.x * 8 + w;
    float a[8];
    #pragma unroll
    for (int j = 0; j < 8; j++) a[j] = A[(size_t)m * Hc + lane + 32 * j];
    #pragma unroll
    for (int n = 0; n < LAGc; n++) {
        float s = 0.f;
        #pragma unroll
        for (int j = 0; j < 8; j++) s += a[j] * sW[n * Hc + lane + 32 * j];
        #pragma unroll
        for (int o = 16; o > 0; o >>= 1) s += __shfl_xor_sync(0xffffffff, s, o);
        if (lane == n) out[m * LAGc + n] = s + sb[n];
    }
}

// ---------------------------------------------------------------------------
extern "C" void kernel_launch(void* const* d_in, const int* in_sizes, int n_in,
                              void* d_out, int out_size)
{
    const float* x    = (const float*)d_in[0];
    const float* Wi1  = (const float*)d_in[1];
    const float* bi1  = (const float*)d_in[2];
    const float* Wi2  = (const float*)d_in[3];
    const float* bi2  = (const float*)d_in[4];
    const float* Wi3  = (const float*)d_in[5];
    const float* bi3  = (const float*)d_in[6];
    const float* Wih0 = (const float*)d_in[7];
    const float* Whh0 = (const float*)d_in[8];
    const float* bih0 = (const float*)d_in[9];
    const float* bhh0 = (const float*)d_in[10];
    const float* Wih1 = (const float*)d_in[11];
    const float* Whh1 = (const float*)d_in[12];
    const float* bih1 = (const float*)d_in[13];
    const float* bhh1 = (const float*)d_in[14];
    const float* Wo1  = (const float*)d_in[15];
    const float* bo1  = (const float*)d_in[16];
    const float* Wo2  = (const float*)d_in[17];
    const float* bo2  = (const float*)d_in[18];
    const float* Wo3  = (const float*)d_in[19];
    const float* bo3  = (const float*)d_in[20];
    float* out = (float*)d_out;

    float *buf0, *buf1, *G0, *hs, *h0, *h1;
    unsigned* bar;
    cudaGetSymbolAddress((void**)&buf0, g_buf0);
    cudaGetSymbolAddress((void**)&buf1, g_buf1);
    cudaGetSymbolAddress((void**)&G0,   g_G0);
    cudaGetSymbolAddress((void**)&hs,   g_hs);
    cudaGetSymbolAddress((void**)&h0,   g_h0);
    cudaGetSymbolAddress((void**)&h1,   g_h1);
    cudaGetSymbolAddress((void**)&bar,  g_bar);

    cudaFuncSetAttribute(lstm_persistent_k,
                         cudaFuncAttributeMaxDynamicSharedMemorySize, SMEM_P);

    cudaMemsetAsync(h0, 0, 2 * BHc * sizeof(float));
    cudaMemsetAsync(h1, 0, 2 * BHc * sizeof(float));
    cudaMemsetAsync(bar, 0, NGRP * sizeof(unsigned));

    // Input MLP
    in_mlp1_k<<<TBc / 16, 256>>>(x, Wi1, bi1, buf0);
    dim3 gH(Hc / 128, TBc / 128);
    gemm_mma_k<true, false><<<gH, 256>>>(buf0, Wi2, bi2, nullptr, buf1, TBc, Hc, Hc);
    gemm_mma_k<true, false><<<gH, 256>>>(buf1, Wi3, bi3, nullptr, buf0, TBc, Hc, Hc);

    // Layer-0 input projection for ALL timesteps (includes both biases)
    dim3 gG(H4c / 128, TBc / 128);
    gemm_mma_k<false, false><<<gG, 256>>>(buf0, Wih0, bih0, bhh0, G0, TBc, H4c, Hc);

    // Entire recurrence in one persistent launch
    lstm_persistent_k<<<NBLK, 256, SMEM_P>>>(Whh0, Wih1, Whh1, bih1, bhh1,
                                             G0, h0, h1, hs);

    // Output MLP
    gemm_mma_k<true, true ><<<gH, 256>>>(hs,   Wo1, bo1, nullptr, buf0, TBc, Hc, Hc);
    gemm_mma_k<true, false><<<gH, 256>>>(buf0, Wo2, bo2, nullptr, buf1, TBc, Hc, Hc);
    out_mlp3_k<<<TBc / 8, 256>>>(buf1, Wo3, bo3, out);
}

// round 6
// speedup vs baseline: 3.1198x; 1.0640x over previous
#include <cuda_runtime.h>
#include <cuda_bf16.h>
#include <math.h>

// Problem constants
#define Tc   128
#define Bc   1024
#define LAGc 6
#define Hc   256
#define H4c  1024
#define TBc  (Tc * Bc)      // 131072
#define BHc  (Bc * Hc)      // 262144

// Persistent recurrence kernel geometry
#define NGRP   8            // batch groups of 128 rows
#define NSUB   16           // blocks per group (16 h-cols each)
#define NBLK   (NGRP * NSUB)
#define W0STR  260          // smem row stride (words) layer0 weights (K=256)
#define W1STR  516          // smem row stride (words) layer1 weights (K=512)
#define ASTR   20           // smem row stride (words) A staging (K-chunk 16)
#define ABUFW  (128 * ASTR) // words per A buffer (2560)
#define SMEM_P ((64 * W0STR + 64 * W1STR + 3 * ABUFW) * 4)   // 229376 bytes

// ---------------------------------------------------------------------------
// Scratch (device globals; no runtime allocation allowed)
// ---------------------------------------------------------------------------
__device__ float g_buf0[TBc * Hc];
__device__ float g_buf1[TBc * Hc];
__device__ float g_G0[(size_t)TBc * H4c];   // u@Wih0^T + bih0 + bhh0 for all T
__device__ float g_hs[TBc * Hc];            // doubles as h1 state (h1cur = hs[t])
__device__ float g_h0[2 * BHc];             // layer-0 hidden ping-pong
__device__ float g_zb[BHc];                 // zero h1prev for t=0
__device__ unsigned g_bar[NGRP];

// ---------------------------------------------------------------------------
// Helpers
// ---------------------------------------------------------------------------
__device__ __forceinline__ unsigned cvt_tf32(float x) {
    unsigned u; asm("cvt.rna.tf32.f32 %0, %1;" : "=r"(u) : "f"(x)); return u;
}
__device__ __forceinline__ void mma8(float* d, const unsigned* a, const unsigned* b) {
    asm volatile("mma.sync.aligned.m16n8k8.row.col.f32.tf32.tf32.f32 "
        "{%0,%1,%2,%3}, {%4,%5,%6,%7}, {%8,%9}, {%0,%1,%2,%3};"
        : "+f"(d[0]), "+f"(d[1]), "+f"(d[2]), "+f"(d[3])
        : "r"(a[0]), "r"(a[1]), "r"(a[2]), "r"(a[3]), "r"(b[0]), "r"(b[1]));
}
__device__ __forceinline__ float sigmoidf_(float v) { return 1.f / (1.f + expf(-v)); }

__device__ __forceinline__ void cp_async16(void* dst, const void* src) {
    unsigned d = (unsigned)__cvta_generic_to_shared(dst);
    asm volatile("cp.async.ca.shared.global [%0], [%1], 16;\n" :: "r"(d), "l"(src));
}
__device__ __forceinline__ void cp_commit() {
    asm volatile("cp.async.commit_group;\n");
}
template<int N> __device__ __forceinline__ void cp_wait() {
    asm volatile("cp.async.wait_group %0;\n" :: "n"(N));
}

// ldmatrix x4 (b16 view; 8 rows x 16B per matrix)
__device__ __forceinline__ void ldsm4f(unsigned* r, const float* p) {
    unsigned a = (unsigned)__cvta_generic_to_shared(p);
    asm volatile("ldmatrix.sync.aligned.m8n8.x4.shared.b16 {%0,%1,%2,%3}, [%4];"
        : "=r"(r[0]), "=r"(r[1]), "=r"(r[2]), "=r"(r[3]) : "r"(a));
}
__device__ __forceinline__ void ldsm4u(unsigned* r, const unsigned* p) {
    unsigned a = (unsigned)__cvta_generic_to_shared(p);
    asm volatile("ldmatrix.sync.aligned.m8n8.x4.shared.b16 {%0,%1,%2,%3}, [%4];"
        : "=r"(r[0]), "=r"(r[1]), "=r"(r[2]), "=r"(r[3]) : "r"(a));
}

// Decoupled group barrier: release-arrive / acquire-wait on an L2 counter.
__device__ __forceinline__ void bar_arrive(unsigned* ctr) {
    __syncthreads();                       // all block writes done
    if (threadIdx.x == 0)
        asm volatile("red.release.gpu.global.add.u32 [%0], 1;" :: "l"(ctr) : "memory");
}
__device__ __forceinline__ void bar_wait(unsigned* ctr, unsigned target) {
    if (threadIdx.x == 0) {
        unsigned v;
        do {
            asm volatile("ld.acquire.gpu.global.u32 %0, [%1];" : "=r"(v) : "l"(ctr) : "memory");
        } while (v < target);
    }
    __syncthreads();
}

// ---------------------------------------------------------------------------
// Kernel 1: u = relu(x @ Wi1^T + bi1)   [TB,6] -> [TB,256]
// ---------------------------------------------------------------------------
__global__ void __launch_bounds__(256) in_mlp1_k(
    const float* __restrict__ x, const float* __restrict__ W,
    const float* __restrict__ b, float* __restrict__ out)
{
    __shared__ float sW[Hc * LAGc];
    __shared__ float sb[Hc];
    __shared__ float sx[16 * LAGc];
    int tid = threadIdx.x;
    int m0  = blockIdx.x * 16;
    for (int i = tid; i < Hc * LAGc; i += 256) sW[i] = W[i];
    sb[tid] = b[tid];
    if (tid < 16 * LAGc) sx[tid] = x[m0 * LAGc + tid];
    __syncthreads();
    #pragma unroll
    for (int r = 0; r < 16; r++) {
        float acc = sb[tid];
        #pragma unroll
        for (int k = 0; k < LAGc; k++) acc += sx[r * LAGc + k] * sW[tid * LAGc + k];
        out[(m0 + r) * Hc + tid] = fmaxf(acc, 0.f);
    }
}

// ---------------------------------------------------------------------------
// Generic tf32 tensor-core GEMM (unchanged).
// ---------------------------------------------------------------------------
template<bool RELU_OUT, bool PRE_RELU>
__global__ void __launch_bounds__(256) gemm_mma_k(
    const float* __restrict__ A, const float* __restrict__ W,
    const float* __restrict__ b1, const float* __restrict__ b2,
    float* __restrict__ C, int M, int N, int K)
{
    __shared__ unsigned As[128 * 20];
    __shared__ unsigned Bs[128 * 20];
    int tid = threadIdx.x, lane = tid & 31, wid = tid >> 5;
    int wm = wid & 1, wn = wid >> 1;
    int m0 = blockIdx.y * 128, n0 = blockIdx.x * 128;
    int r0 = tid >> 2;
    int k4 = (tid & 3) * 4;

    const float* Ab = A + (size_t)m0 * K;
    const float* Wb = W + (size_t)n0 * K;

    float4 pa0 = *(const float4*)(Ab + (size_t)r0 * K + k4);
    float4 pa1 = *(const float4*)(Ab + (size_t)(r0 + 64) * K + k4);
    float4 pw0 = *(const float4*)(Wb + (size_t)r0 * K + k4);
    float4 pw1 = *(const float4*)(Wb + (size_t)(r0 + 64) * K + k4);

    float acc[4][4][4] = {};
    for (int k0 = 0; k0 < K; k0 += 16) {
        __syncthreads();
        float4 v;
        v = pa0;
        if (PRE_RELU) { v.x=fmaxf(v.x,0.f); v.y=fmaxf(v.y,0.f); v.z=fmaxf(v.z,0.f); v.w=fmaxf(v.w,0.f); }
        As[r0*20 + k4+0]=cvt_tf32(v.x); As[r0*20 + k4+1]=cvt_tf32(v.y);
        As[r0*20 + k4+2]=cvt_tf32(v.z); As[r0*20 + k4+3]=cvt_tf32(v.w);
        v = pa1;
        if (PRE_RELU) { v.x=fmaxf(v.x,0.f); v.y=fmaxf(v.y,0.f); v.z=fmaxf(v.z,0.f); v.w=fmaxf(v.w,0.f); }
        As[(r0+64)*20 + k4+0]=cvt_tf32(v.x); As[(r0+64)*20 + k4+1]=cvt_tf32(v.y);
        As[(r0+64)*20 + k4+2]=cvt_tf32(v.z); As[(r0+64)*20 + k4+3]=cvt_tf32(v.w);
        Bs[r0*20 + k4+0]=cvt_tf32(pw0.x); Bs[r0*20 + k4+1]=cvt_tf32(pw0.y);
        Bs[r0*20 + k4+2]=cvt_tf32(pw0.z); Bs[r0*20 + k4+3]=cvt_tf32(pw0.w);
        Bs[(r0+64)*20 + k4+0]=cvt_tf32(pw1.x); Bs[(r0+64)*20 + k4+1]=cvt_tf32(pw1.y);
        Bs[(r0+64)*20 + k4+2]=cvt_tf32(pw1.z); Bs[(r0+64)*20 + k4+3]=cvt_tf32(pw1.w);
        __syncthreads();

        if (k0 + 16 < K) {
            pa0 = *(const float4*)(Ab + (size_t)r0 * K + k0 + 16 + k4);
            pa1 = *(const float4*)(Ab + (size_t)(r0 + 64) * K + k0 + 16 + k4);
            pw0 = *(const float4*)(Wb + (size_t)r0 * K + k0 + 16 + k4);
            pw1 = *(const float4*)(Wb + (size_t)(r0 + 64) * K + k0 + 16 + k4);
        }

        int qr = lane >> 2, qk = lane & 3;
        #pragma unroll
        for (int ks = 0; ks < 16; ks += 8) {
            unsigned af[4][4], bf[4][2];
            #pragma unroll
            for (int mt = 0; mt < 4; mt++) {
                int rb = wm * 64 + mt * 16;
                af[mt][0] = As[(rb     + qr)*20 + ks     + qk];
                af[mt][1] = As[(rb + 8 + qr)*20 + ks     + qk];
                af[mt][2] = As[(rb     + qr)*20 + ks + 4 + qk];
                af[mt][3] = As[(rb + 8 + qr)*20 + ks + 4 + qk];
            }
            #pragma unroll
            for (int nt = 0; nt < 4; nt++) {
                int cb = wn * 32 + nt * 8;
                bf[nt][0] = Bs[(cb + qr)*20 + ks     + qk];
                bf[nt][1] = Bs[(cb + qr)*20 + ks + 4 + qk];
            }
            #pragma unroll
            for (int mt = 0; mt < 4; mt++)
                #pragma unroll
                for (int nt = 0; nt < 4; nt++)
                    mma8(acc[mt][nt], af[mt], bf[nt]);
        }
    }

    int qr = lane >> 2, qk = lane & 3;
    #pragma unroll
    for (int nt = 0; nt < 4; nt++) {
        int col = n0 + wn * 32 + nt * 8 + 2 * qk;
        float bb0 = b1[col]     + (b2 ? b2[col]     : 0.f);
        float bb1 = b1[col + 1] + (b2 ? b2[col + 1] : 0.f);
        #pragma unroll
        for (int mt = 0; mt < 4; mt++) {
            int row = m0 + wm * 64 + mt * 16 + qr;
            float2 v0, v1;
            v0.x = acc[mt][nt][0] + bb0; v0.y = acc[mt][nt][1] + bb1;
            v1.x = acc[mt][nt][2] + bb0; v1.y = acc[mt][nt][3] + bb1;
            if (RELU_OUT) {
                v0.x=fmaxf(v0.x,0.f); v0.y=fmaxf(v0.y,0.f);
                v1.x=fmaxf(v1.x,0.f); v1.y=fmaxf(v1.y,0.f);
            }
            *(float2*)(C + (size_t)row * N + col)       = v0;
            *(float2*)(C + (size_t)(row + 8) * N + col) = v1;
        }
    }
}

// ---------------------------------------------------------------------------
// Persistent LSTM helpers
// ---------------------------------------------------------------------------
// Stage one 128x16 fp32 A chunk into smem via cp.async (2x16B per thread).
__device__ __forceinline__ void stage_chunk(float* Abuf, const float* src_base, int tid) {
    #pragma unroll
    for (int i = 0; i < 2; i++) {
        int s = tid + i * 256;
        int row = s >> 2, kq = (s & 3) * 4;
        cp_async16(Abuf + row * ASTR + kq, src_base + (size_t)row * Hc + kq);
    }
    cp_commit();
}

// MMA over one staged chunk using ldmatrix fragment loads.
// aoff/woff are precomputed per-lane word offsets.
__device__ __forceinline__ void mma_chunk(
    const float* Ab, int aoff, const unsigned* Wsm, int wstr, int woff, int kbase,
    float acc[8][4])
{
    #pragma unroll
    for (int ks = 0; ks < 2; ks++) {
        int k0 = ks * 8;
        unsigned a[4];
        ldsm4f(a, Ab + aoff + k0);
        #pragma unroll
        for (int i = 0; i < 4; i++) a[i] = cvt_tf32(__uint_as_float(a[i]));
        #pragma unroll
        for (int p = 0; p < 4; p++) {
            unsigned b[4];
            ldsm4u(b, Wsm + (size_t)(p * 16) * wstr + woff + kbase + k0);
            mma8(acc[2 * p],     a, b);
            mma8(acc[2 * p + 1], a, b + 2);
        }
    }
}

// ---------------------------------------------------------------------------
// Persistent recurrence kernel: all 128 timesteps, both LSTM layers.
// Grid = 128 blocks (8 groups x 16 subs), 256 threads (8 warps x M16).
// Weights resident in smem (tf32); c-state in registers; A staged via cp.async;
// decoupled arrive/wait barrier hidden behind the h1prev half of layer-1.
// ---------------------------------------------------------------------------
__global__ void __launch_bounds__(256, 1) lstm_persistent_k(
    const float* __restrict__ Whh0, const float* __restrict__ Wih1,
    const float* __restrict__ Whh1, const float* __restrict__ bih1,
    const float* __restrict__ bhh1, const float* __restrict__ G0,
    float* __restrict__ h0buf, const float* __restrict__ zbuf,
    float* __restrict__ hs)
{
    extern __shared__ unsigned smem[];
    unsigned* W0 = smem;                       // [64][W0STR]
    unsigned* W1 = smem + 64 * W0STR;          // [64][W1STR]
    float* Abuf  = (float*)(smem + 64 * W0STR + 64 * W1STR);  // 3 x [128][ASTR]

    int tid = threadIdx.x, lane = tid & 31, wid = tid >> 5;
    int qr = lane >> 2, qk = lane & 3;
    int grp = blockIdx.x >> 4, sub = blockIdx.x & 15;
    int m0  = grp * 128;                  // batch rows
    int hc0 = sub * 16;                   // h-cols

    // ---- stage weights to smem as tf32 (once) ----
    for (int i = tid; i < 64 * 64; i += 256) {           // layer0: 64n x 256k
        int n = i >> 6, kq = (i & 63) * 4;
        int gr = (n >> 4) * Hc + hc0 + (n & 15);
        float4 v = *(const float4*)(Whh0 + (size_t)gr * Hc + kq);
        unsigned* dst = W0 + n * W0STR + kq;
        dst[0]=cvt_tf32(v.x); dst[1]=cvt_tf32(v.y); dst[2]=cvt_tf32(v.z); dst[3]=cvt_tf32(v.w);
    }
    for (int i = tid; i < 64 * 128; i += 256) {          // layer1: 64n x 512k
        int n = i >> 7, kq = (i & 127) * 4;
        int gr = (n >> 4) * Hc + hc0 + (n & 15);
        const float* src = (kq < 256) ? (Wih1 + (size_t)gr * Hc + kq)
                                      : (Whh1 + (size_t)gr * Hc + (kq - 256));
        float4 v = *(const float4*)src;
        unsigned* dst = W1 + n * W1STR + kq;
        dst[0]=cvt_tf32(v.x); dst[1]=cvt_tf32(v.y); dst[2]=cvt_tf32(v.z); dst[3]=cvt_tf32(v.w);
    }
    __syncthreads();

    // ---- per-lane fragment address offsets (words) ----
    int l8 = lane & 7, lsel = (lane >> 3) & 1, lhalf = lane >> 4;
    int aoff  = (wid * 16 + l8 + lsel * 8) * ASTR + lhalf * 4;     // A ldsm
    int woff0 = (lhalf * 8 + l8) * W0STR + lsel * 4;               // W ldsm
    int woff1 = (lhalf * 8 + l8) * W1STR + lsel * 4;

    // ---- per-lane persistent state ----
    int wrow = wid * 16 + qr;             // local row (pair at wrow+8)
    float c0v[2][4] = {};                 // [r][h*2+p]
    float c1v[2][4] = {};
    float b1v[8][2];                      // [nf=g*2+h][p]
    #pragma unroll
    for (int g = 0; g < 4; g++)
        #pragma unroll
        for (int h = 0; h < 2; h++)
            #pragma unroll
            for (int p = 0; p < 2; p++) {
                int n = g * Hc + hc0 + h * 8 + 2 * qk + p;
                b1v[g * 2 + h][p] = bih1[n] + bhh1[n];
            }

    unsigned* ctr = &g_bar[grp];

    for (int t = 0; t < Tc; t++) {
        const float* h0prev = h0buf + (t & 1) * BHc;
        float*       h0cur  = h0buf + ((t + 1) & 1) * BHc;
        const float* h1prev = (t == 0) ? zbuf : (hs + (size_t)(t - 1) * BHc);
        float*       h1cur  = hs + (size_t)t * BHc;
        unsigned tB = (unsigned)(2 * t) * NSUB;        // L1(t-1) writes visible
        unsigned tA = (unsigned)(2 * t + 1) * NSUB;    // L0(t) writes visible

        // ================= layer 0 (K=256, 16 chunks) =================
        // Prefetch G0 gate slabs (DRAM latency hidden by the mma loop)
        float2 gI[2][2], gF[2][2], gG[2][2], gO[2][2];
        {
            const float* g0r0 = G0 + ((size_t)t * Bc + m0 + wrow) * H4c + hc0;
            #pragma unroll
            for (int r = 0; r < 2; r++) {
                const float* g0r = g0r0 + (size_t)r * 8 * H4c;
                #pragma unroll
                for (int h = 0; h < 2; h++) {
                    int hcl = h * 8 + 2 * qk;
                    gI[r][h] = *(const float2*)(g0r + hcl);
                    gF[r][h] = *(const float2*)(g0r + 256 + hcl);
                    gG[r][h] = *(const float2*)(g0r + 512 + hcl);
                    gO[r][h] = *(const float2*)(g0r + 768 + hcl);
                }
            }
        }

        float acc[8][4] = {};
        {
            const float* A0p = h0prev + (size_t)m0 * Hc;
            stage_chunk(Abuf + 0 * ABUFW, A0p + 0 * 16, tid);
            stage_chunk(Abuf + 1 * ABUFW, A0p + 1 * 16, tid);
            #pragma unroll 4
            for (int c = 0; c < 16; c++) {
                if (c == 15) cp_wait<0>(); else cp_wait<1>();
                __syncthreads();
                if (c + 2 < 16)
                    stage_chunk(Abuf + ((c + 2) % 3) * ABUFW, A0p + (c + 2) * 16, tid);
                mma_chunk(Abuf + (c % 3) * ABUFW, aoff, W0, W0STR, woff0, c * 16, acc);
            }
        }
        // epilogue: cell update, write h0cur
        #pragma unroll
        for (int r = 0; r < 2; r++) {
            float* hw = h0cur + (size_t)(m0 + wrow + r * 8) * Hc + hc0;
            #pragma unroll
            for (int h = 0; h < 2; h++) {
                int hcl = h * 8 + 2 * qk;
                float hv[2];
                #pragma unroll
                for (int p = 0; p < 2; p++) {
                    float gi = acc[0 + h][r * 2 + p] + (p ? gI[r][h].y : gI[r][h].x);
                    float gf = acc[2 + h][r * 2 + p] + (p ? gF[r][h].y : gF[r][h].x);
                    float gg = acc[4 + h][r * 2 + p] + (p ? gG[r][h].y : gG[r][h].x);
                    float go = acc[6 + h][r * 2 + p] + (p ? gO[r][h].y : gO[r][h].x);
                    float c  = c0v[r][h * 2 + p];
                    float c2 = sigmoidf_(gf) * c + sigmoidf_(gi) * tanhf(gg);
                    c0v[r][h * 2 + p] = c2;
                    hv[p] = sigmoidf_(go) * tanhf(c2);
                }
                *(float2*)(hw + hcl) = make_float2(hv[0], hv[1]);
            }
        }
        bar_arrive(ctr);                 // phase 2t+1 (includes __syncthreads)

        // ================= layer 1 (K=512, 32 chunks) =================
        // h1prev half first (ordered by phase 2t); wait for h0cur at c==14,
        // hidden behind 14 chunks of mma while other blocks finish layer 0.
        #pragma unroll
        for (int nf = 0; nf < 8; nf++)
            #pragma unroll
            for (int j = 0; j < 4; j++) acc[nf][j] = 0.f;

        bar_wait(ctr, tB);               // normally already satisfied
        {
            const float* A1 = h1prev + (size_t)m0 * Hc;
            const float* A0 = h0cur + (size_t)m0 * Hc;
            stage_chunk(Abuf + 0 * ABUFW, A1 + 0 * 16, tid);
            stage_chunk(Abuf + 1 * ABUFW, A1 + 1 * 16, tid);
            #pragma unroll 4
            for (int c = 0; c < 32; c++) {
                if (c == 31) cp_wait<0>(); else cp_wait<1>();
                __syncthreads();
                if (c == 14) bar_wait(ctr, tA);     // before staging h0cur
                if (c + 2 < 32) {
                    int cn = c + 2;
                    const float* src = (cn < 16) ? (A1 + cn * 16) : (A0 + (cn - 16) * 16);
                    stage_chunk(Abuf + (cn % 3) * ABUFW, src, tid);
                }
                int kb = (c < 16) ? (256 + c * 16) : ((c - 16) * 16);
                mma_chunk(Abuf + (c % 3) * ABUFW, aoff, W1, W1STR, woff1, kb, acc);
            }
        }
        // epilogue: cell update, write h1cur (== hs[t])
        #pragma unroll
        for (int r = 0; r < 2; r++) {
            float* hw = h1cur + (size_t)(m0 + wrow + r * 8) * Hc + hc0;
            #pragma unroll
            for (int h = 0; h < 2; h++) {
                int hcl = h * 8 + 2 * qk;
                float hv[2];
                #pragma unroll
                for (int p = 0; p < 2; p++) {
                    float gi = acc[0 + h][r * 2 + p] + b1v[0 + h][p];
                    float gf = acc[2 + h][r * 2 + p] + b1v[2 + h][p];
                    float gg = acc[4 + h][r * 2 + p] + b1v[4 + h][p];
                    float go = acc[6 + h][r * 2 + p] + b1v[6 + h][p];
                    float c  = c1v[r][h * 2 + p];
                    float c2 = sigmoidf_(gf) * c + sigmoidf_(gi) * tanhf(gg);
                    c1v[r][h * 2 + p] = c2;
                    hv[p] = sigmoidf_(go) * tanhf(c2);
                }
                *(float2*)(hw + hcl) = make_float2(hv[0], hv[1]);
            }
        }
        bar_arrive(ctr);                 // phase 2t+2
    }
}

// ---------------------------------------------------------------------------
// Final layer: y = A @ Wo3^T + bo3  (N=6, K=256). One warp per row.
// ---------------------------------------------------------------------------
__global__ void __launch_bounds__(256) out_mlp3_k(
    const float* __restrict__ A, const float* __restrict__ W,
    const float* __restrict__ b, float* __restrict__ out)
{
    __shared__ float sW[LAGc * Hc];
    __shared__ float sb[LAGc];
    int tid = threadIdx.x;
    for (int i = tid; i < LAGc * Hc; i += 256) sW[i] = W[i];
    if (tid < LAGc) sb[tid] = b[tid];
    __syncthreads();
    int w = tid >> 5, lane = tid & 31;
    int m = blockIdx.x * 8 + w;
    float a[8];
    #pragma unroll
    for (int j = 0; j < 8; j++) a[j] = A[(size_t)m * Hc + lane + 32 * j];
    #pragma unroll
    for (int n = 0; n < LAGc; n++) {
        float s = 0.f;
        #pragma unroll
        for (int j = 0; j < 8; j++) s += a[j] * sW[n * Hc + lane + 32 * j];
        #pragma unroll
        for (int o = 16; o > 0; o >>= 1) s += __shfl_xor_sync(0xffffffff, s, o);
        if (lane == n) out[m * LAGc + n] = s + sb[n];
    }
}

// ---------------------------------------------------------------------------
extern "C" void kernel_launch(void* const* d_in, const int* in_sizes, int n_in,
                              void* d_out, int out_size)
{
    const float* x    = (const float*)d_in[0];
    const float* Wi1  = (const float*)d_in[1];
    const float* bi1  = (const float*)d_in[2];
    const float* Wi2  = (const float*)d_in[3];
    const float* bi2  = (const float*)d_in[4];
    const float* Wi3  = (const float*)d_in[5];
    const float* bi3  = (const float*)d_in[6];
    const float* Wih0 = (const float*)d_in[7];
    const float* Whh0 = (const float*)d_in[8];
    const float* bih0 = (const float*)d_in[9];
    const float* bhh0 = (const float*)d_in[10];
    const float* Wih1 = (const float*)d_in[11];
    const float* Whh1 = (const float*)d_in[12];
    const float* bih1 = (const float*)d_in[13];
    const float* bhh1 = (const float*)d_in[14];
    const float* Wo1  = (const float*)d_in[15];
    const float* bo1  = (const float*)d_in[16];
    const float* Wo2  = (const float*)d_in[17];
    const float* bo2  = (const float*)d_in[18];
    const float* Wo3  = (const float*)d_in[19];
    const float* bo3  = (const float*)d_in[20];
    float* out = (float*)d_out;

    float *buf0, *buf1, *G0, *hs, *h0, *zb;
    unsigned* bar;
    cudaGetSymbolAddress((void**)&buf0, g_buf0);
    cudaGetSymbolAddress((void**)&buf1, g_buf1);
    cudaGetSymbolAddress((void**)&G0,   g_G0);
    cudaGetSymbolAddress((void**)&hs,   g_hs);
    cudaGetSymbolAddress((void**)&h0,   g_h0);
    cudaGetSymbolAddress((void**)&zb,   g_zb);
    cudaGetSymbolAddress((void**)&bar,  g_bar);

    cudaFuncSetAttribute(lstm_persistent_k,
                         cudaFuncAttributeMaxDynamicSharedMemorySize, SMEM_P);

    cudaMemsetAsync(h0, 0, 2 * BHc * sizeof(float));
    cudaMemsetAsync(zb, 0, BHc * sizeof(float));
    cudaMemsetAsync(bar, 0, NGRP * sizeof(unsigned));

    // Input MLP
    in_mlp1_k<<<TBc / 16, 256>>>(x, Wi1, bi1, buf0);
    dim3 gH(Hc / 128, TBc / 128);
    gemm_mma_k<true, false><<<gH, 256>>>(buf0, Wi2, bi2, nullptr, buf1, TBc, Hc, Hc);
    gemm_mma_k<true, false><<<gH, 256>>>(buf1, Wi3, bi3, nullptr, buf0, TBc, Hc, Hc);

    // Layer-0 input projection for ALL timesteps (includes both biases)
    dim3 gG(H4c / 128, TBc / 128);
    gemm_mma_k<false, false><<<gG, 256>>>(buf0, Wih0, bih0, bhh0, G0, TBc, H4c, Hc);

    // Entire recurrence in one persistent launch
    lstm_persistent_k<<<NBLK, 256, SMEM_P>>>(Whh0, Wih1, Whh1, bih1, bhh1,
                                             G0, h0, zb, hs);

    // Output MLP
    gemm_mma_k<true, true ><<<gH, 256>>>(hs,   Wo1, bo1, nullptr, buf0, TBc, Hc, Hc);
    gemm_mma_k<true, false><<<gH, 256>>>(buf0, Wo2, bo2, nullptr, buf1, TBc, Hc, Hc);
    out_mlp3_k<<<TBc / 8, 256>>>(buf1, Wo3, bo3, out);
}

// round 7
// speedup vs baseline: 3.4651x; 1.1107x over previous
#include <cuda_runtime.h>
#include <cuda_bf16.h>
#include <math.h>

// Problem constants
#define Tc   128
#define Bc   1024
#define LAGc 6
#define Hc   256
#define H4c  1024
#define TBc  (Tc * Bc)      // 131072
#define BHc  (Bc * Hc)      // 262144

// Persistent recurrence kernel geometry
#define NGRP   8            // batch groups of 128 rows
#define NSUB   16           // blocks per group (16 h-cols each)
#define NBLK   (NGRP * NSUB)
#define W0STR  260          // smem row stride (words) layer0 weights (K=256)
#define W1STR  516          // smem row stride (words) layer1 weights (K=512)
#define ASTR   20           // smem row stride (words) A staging (K-chunk 16)
#define ABUFW  (128 * ASTR) // words per A buffer (2560)
#define SMEM_P ((64 * W0STR + 64 * W1STR + 3 * ABUFW) * 4)   // 229376 bytes

// ---------------------------------------------------------------------------
// Scratch (device globals; no runtime allocation allowed)
// ---------------------------------------------------------------------------
__device__ float g_buf0[TBc * Hc];
__device__ float g_buf1[TBc * Hc];
__device__ float g_G0[(size_t)TBc * H4c];   // u@Wih0^T + bih0 + bhh0 for all T
__device__ float g_hs[TBc * Hc];            // doubles as h1 state (h1cur = hs[t])
__device__ float g_h0[2 * BHc];             // layer-0 hidden ping-pong
__device__ float g_zb[BHc];                 // zero h1prev for t=0
__device__ unsigned g_bar[NGRP];

// ---------------------------------------------------------------------------
// Helpers
// ---------------------------------------------------------------------------
__device__ __forceinline__ unsigned cvt_tf32(float x) {
    unsigned u; asm("cvt.rna.tf32.f32 %0, %1;" : "=r"(u) : "f"(x)); return u;
}
__device__ __forceinline__ void mma8(float* d, const unsigned* a, const unsigned* b) {
    asm volatile("mma.sync.aligned.m16n8k8.row.col.f32.tf32.tf32.f32 "
        "{%0,%1,%2,%3}, {%4,%5,%6,%7}, {%8,%9}, {%0,%1,%2,%3};"
        : "+f"(d[0]), "+f"(d[1]), "+f"(d[2]), "+f"(d[3])
        : "r"(a[0]), "r"(a[1]), "r"(a[2]), "r"(a[3]), "r"(b[0]), "r"(b[1]));
}
__device__ __forceinline__ float sigmoidf_(float v) { return 1.f / (1.f + expf(-v)); }

__device__ __forceinline__ void cp_async16(void* dst, const void* src) {
    unsigned d = (unsigned)__cvta_generic_to_shared(dst);
    asm volatile("cp.async.ca.shared.global [%0], [%1], 16;\n" :: "r"(d), "l"(src));
}
__device__ __forceinline__ void cp_commit() {
    asm volatile("cp.async.commit_group;\n");
}
template<int N> __device__ __forceinline__ void cp_wait() {
    asm volatile("cp.async.wait_group %0;\n" :: "n"(N));
}

// ldmatrix x4 (b16 view; 8 rows x 16B per matrix)
__device__ __forceinline__ void ldsm4f(unsigned* r, const float* p) {
    unsigned a = (unsigned)__cvta_generic_to_shared(p);
    asm volatile("ldmatrix.sync.aligned.m8n8.x4.shared.b16 {%0,%1,%2,%3}, [%4];"
        : "=r"(r[0]), "=r"(r[1]), "=r"(r[2]), "=r"(r[3]) : "r"(a));
}
__device__ __forceinline__ void ldsm4u(unsigned* r, const unsigned* p) {
    unsigned a = (unsigned)__cvta_generic_to_shared(p);
    asm volatile("ldmatrix.sync.aligned.m8n8.x4.shared.b16 {%0,%1,%2,%3}, [%4];"
        : "=r"(r[0]), "=r"(r[1]), "=r"(r[2]), "=r"(r[3]) : "r"(a));
}

// Decoupled group barrier: release-arrive / acquire-wait on an L2 counter.
__device__ __forceinline__ void bar_arrive(unsigned* ctr) {
    __syncthreads();                       // all block writes done
    if (threadIdx.x == 0)
        asm volatile("red.release.gpu.global.add.u32 [%0], 1;" :: "l"(ctr) : "memory");
}
__device__ __forceinline__ void bar_wait(unsigned* ctr, unsigned target) {
    if (threadIdx.x == 0) {
        unsigned v;
        do {
            asm volatile("ld.acquire.gpu.global.u32 %0, [%1];" : "=r"(v) : "l"(ctr) : "memory");
        } while (v < target);
    }
    __syncthreads();
}

// ---------------------------------------------------------------------------
// Kernel 1: u = relu(x @ Wi1^T + bi1)   [TB,6] -> [TB,256]
// ---------------------------------------------------------------------------
__global__ void __launch_bounds__(256) in_mlp1_k(
    const float* __restrict__ x, const float* __restrict__ W,
    const float* __restrict__ b, float* __restrict__ out)
{
    __shared__ float sW[Hc * LAGc];
    __shared__ float sb[Hc];
    __shared__ float sx[16 * LAGc];
    int tid = threadIdx.x;
    int m0  = blockIdx.x * 16;
    for (int i = tid; i < Hc * LAGc; i += 256) sW[i] = W[i];
    sb[tid] = b[tid];
    if (tid < 16 * LAGc) sx[tid] = x[m0 * LAGc + tid];
    __syncthreads();
    #pragma unroll
    for (int r = 0; r < 16; r++) {
        float acc = sb[tid];
        #pragma unroll
        for (int k = 0; k < LAGc; k++) acc += sx[r * LAGc + k] * sW[tid * LAGc + k];
        out[(m0 + r) * Hc + tid] = fmaxf(acc, 0.f);
    }
}

// ---------------------------------------------------------------------------
// Generic tf32 tensor-core GEMM (unchanged).
// ---------------------------------------------------------------------------
template<bool RELU_OUT, bool PRE_RELU>
__global__ void __launch_bounds__(256) gemm_mma_k(
    const float* __restrict__ A, const float* __restrict__ W,
    const float* __restrict__ b1, const float* __restrict__ b2,
    float* __restrict__ C, int M, int N, int K)
{
    __shared__ unsigned As[128 * 20];
    __shared__ unsigned Bs[128 * 20];
    int tid = threadIdx.x, lane = tid & 31, wid = tid >> 5;
    int wm = wid & 1, wn = wid >> 1;
    int m0 = blockIdx.y * 128, n0 = blockIdx.x * 128;
    int r0 = tid >> 2;
    int k4 = (tid & 3) * 4;

    const float* Ab = A + (size_t)m0 * K;
    const float* Wb = W + (size_t)n0 * K;

    float4 pa0 = *(const float4*)(Ab + (size_t)r0 * K + k4);
    float4 pa1 = *(const float4*)(Ab + (size_t)(r0 + 64) * K + k4);
    float4 pw0 = *(const float4*)(Wb + (size_t)r0 * K + k4);
    float4 pw1 = *(const float4*)(Wb + (size_t)(r0 + 64) * K + k4);

    float acc[4][4][4] = {};
    for (int k0 = 0; k0 < K; k0 += 16) {
        __syncthreads();
        float4 v;
        v = pa0;
        if (PRE_RELU) { v.x=fmaxf(v.x,0.f); v.y=fmaxf(v.y,0.f); v.z=fmaxf(v.z,0.f); v.w=fmaxf(v.w,0.f); }
        As[r0*20 + k4+0]=cvt_tf32(v.x); As[r0*20 + k4+1]=cvt_tf32(v.y);
        As[r0*20 + k4+2]=cvt_tf32(v.z); As[r0*20 + k4+3]=cvt_tf32(v.w);
        v = pa1;
        if (PRE_RELU) { v.x=fmaxf(v.x,0.f); v.y=fmaxf(v.y,0.f); v.z=fmaxf(v.z,0.f); v.w=fmaxf(v.w,0.f); }
        As[(r0+64)*20 + k4+0]=cvt_tf32(v.x); As[(r0+64)*20 + k4+1]=cvt_tf32(v.y);
        As[(r0+64)*20 + k4+2]=cvt_tf32(v.z); As[(r0+64)*20 + k4+3]=cvt_tf32(v.w);
        Bs[r0*20 + k4+0]=cvt_tf32(pw0.x); Bs[r0*20 + k4+1]=cvt_tf32(pw0.y);
        Bs[r0*20 + k4+2]=cvt_tf32(pw0.z); Bs[r0*20 + k4+3]=cvt_tf32(pw0.w);
        Bs[(r0+64)*20 + k4+0]=cvt_tf32(pw1.x); Bs[(r0+64)*20 + k4+1]=cvt_tf32(pw1.y);
        Bs[(r0+64)*20 + k4+2]=cvt_tf32(pw1.z); Bs[(r0+64)*20 + k4+3]=cvt_tf32(pw1.w);
        __syncthreads();

        if (k0 + 16 < K) {
            pa0 = *(const float4*)(Ab + (size_t)r0 * K + k0 + 16 + k4);
            pa1 = *(const float4*)(Ab + (size_t)(r0 + 64) * K + k0 + 16 + k4);
            pw0 = *(const float4*)(Wb + (size_t)r0 * K + k0 + 16 + k4);
            pw1 = *(const float4*)(Wb + (size_t)(r0 + 64) * K + k0 + 16 + k4);
        }

        int qr = lane >> 2, qk = lane & 3;
        #pragma unroll
        for (int ks = 0; ks < 16; ks += 8) {
            unsigned af[4][4], bf[4][2];
            #pragma unroll
            for (int mt = 0; mt < 4; mt++) {
                int rb = wm * 64 + mt * 16;
                af[mt][0] = As[(rb     + qr)*20 + ks     + qk];
                af[mt][1] = As[(rb + 8 + qr)*20 + ks     + qk];
                af[mt][2] = As[(rb     + qr)*20 + ks + 4 + qk];
                af[mt][3] = As[(rb + 8 + qr)*20 + ks + 4 + qk];
            }
            #pragma unroll
            for (int nt = 0; nt < 4; nt++) {
                int cb = wn * 32 + nt * 8;
                bf[nt][0] = Bs[(cb + qr)*20 + ks     + qk];
                bf[nt][1] = Bs[(cb + qr)*20 + ks + 4 + qk];
            }
            #pragma unroll
            for (int mt = 0; mt < 4; mt++)
                #pragma unroll
                for (int nt = 0; nt < 4; nt++)
                    mma8(acc[mt][nt], af[mt], bf[nt]);
        }
    }

    int qr = lane >> 2, qk = lane & 3;
    #pragma unroll
    for (int nt = 0; nt < 4; nt++) {
        int col = n0 + wn * 32 + nt * 8 + 2 * qk;
        float bb0 = b1[col]     + (b2 ? b2[col]     : 0.f);
        float bb1 = b1[col + 1] + (b2 ? b2[col + 1] : 0.f);
        #pragma unroll
        for (int mt = 0; mt < 4; mt++) {
            int row = m0 + wm * 64 + mt * 16 + qr;
            float2 v0, v1;
            v0.x = acc[mt][nt][0] + bb0; v0.y = acc[mt][nt][1] + bb1;
            v1.x = acc[mt][nt][2] + bb0; v1.y = acc[mt][nt][3] + bb1;
            if (RELU_OUT) {
                v0.x=fmaxf(v0.x,0.f); v0.y=fmaxf(v0.y,0.f);
                v1.x=fmaxf(v1.x,0.f); v1.y=fmaxf(v1.y,0.f);
            }
            *(float2*)(C + (size_t)row * N + col)       = v0;
            *(float2*)(C + (size_t)(row + 8) * N + col) = v1;
        }
    }
}

// ---------------------------------------------------------------------------
// Persistent LSTM helpers — warp-decoupled staging.
// Each warp stages ONLY its own 16 A-rows of each chunk (1KB) and syncs only
// on its own cp.async groups: no block-wide sync in the K loops.
// ---------------------------------------------------------------------------
__device__ __forceinline__ void stage_warp(float* Abuf, const float* src_base,
                                           int wid, int lane) {
    #pragma unroll
    for (int i = 0; i < 2; i++) {
        int s = lane + i * 32;
        int row = wid * 16 + (s >> 2), kq = (s & 3) * 4;
        cp_async16(Abuf + row * ASTR + kq, src_base + (size_t)row * Hc + kq);
    }
    cp_commit();
}

// MMA over one staged chunk using ldmatrix fragment loads.
__device__ __forceinline__ void mma_chunk(
    const float* Ab, int aoff, const unsigned* Wsm, int wstr, int woff, int kbase,
    float acc[8][4])
{
    #pragma unroll
    for (int ks = 0; ks < 2; ks++) {
        int k0 = ks * 8;
        unsigned a[4];
        ldsm4f(a, Ab + aoff + k0);
        #pragma unroll
        for (int i = 0; i < 4; i++) a[i] = cvt_tf32(__uint_as_float(a[i]));
        #pragma unroll
        for (int p = 0; p < 4; p++) {
            unsigned b[4];
            ldsm4u(b, Wsm + (size_t)(p * 16) * wstr + woff + kbase + k0);
            mma8(acc[2 * p],     a, b);
            mma8(acc[2 * p + 1], a, b + 2);
        }
    }
}

// ---------------------------------------------------------------------------
// Persistent recurrence kernel: all 128 timesteps, both LSTM layers.
// Grid = 128 blocks (8 groups x 16 subs), 256 threads (8 warps x M16).
// Weights resident in smem (tf32); c-state in registers; per-warp cp.async
// staging with zero block-wide syncs inside the K loops.
// ---------------------------------------------------------------------------
__global__ void __launch_bounds__(256, 1) lstm_persistent_k(
    const float* __restrict__ Whh0, const float* __restrict__ Wih1,
    const float* __restrict__ Whh1, const float* __restrict__ bih1,
    const float* __restrict__ bhh1, const float* __restrict__ G0,
    float* __restrict__ h0buf, const float* __restrict__ zbuf,
    float* __restrict__ hs)
{
    extern __shared__ unsigned smem[];
    unsigned* W0 = smem;                       // [64][W0STR]
    unsigned* W1 = smem + 64 * W0STR;          // [64][W1STR]
    float* Abuf  = (float*)(smem + 64 * W0STR + 64 * W1STR);  // 3 x [128][ASTR]

    int tid = threadIdx.x, lane = tid & 31, wid = tid >> 5;
    int qr = lane >> 2, qk = lane & 3;
    int grp = blockIdx.x >> 4, sub = blockIdx.x & 15;
    int m0  = grp * 128;                  // batch rows
    int hc0 = sub * 16;                   // h-cols

    // ---- stage weights to smem as tf32 (once) ----
    for (int i = tid; i < 64 * 64; i += 256) {           // layer0: 64n x 256k
        int n = i >> 6, kq = (i & 63) * 4;
        int gr = (n >> 4) * Hc + hc0 + (n & 15);
        float4 v = *(const float4*)(Whh0 + (size_t)gr * Hc + kq);
        unsigned* dst = W0 + n * W0STR + kq;
        dst[0]=cvt_tf32(v.x); dst[1]=cvt_tf32(v.y); dst[2]=cvt_tf32(v.z); dst[3]=cvt_tf32(v.w);
    }
    for (int i = tid; i < 64 * 128; i += 256) {          // layer1: 64n x 512k
        int n = i >> 7, kq = (i & 127) * 4;
        int gr = (n >> 4) * Hc + hc0 + (n & 15);
        const float* src = (kq < 256) ? (Wih1 + (size_t)gr * Hc + kq)
                                      : (Whh1 + (size_t)gr * Hc + (kq - 256));
        float4 v = *(const float4*)src;
        unsigned* dst = W1 + n * W1STR + kq;
        dst[0]=cvt_tf32(v.x); dst[1]=cvt_tf32(v.y); dst[2]=cvt_tf32(v.z); dst[3]=cvt_tf32(v.w);
    }
    __syncthreads();

    // ---- per-lane fragment address offsets (words) ----
    int l8 = lane & 7, lsel = (lane >> 3) & 1, lhalf = lane >> 4;
    int aoff  = (wid * 16 + l8 + lsel * 8) * ASTR + lhalf * 4;     // A ldsm
    int woff0 = (lhalf * 8 + l8) * W0STR + lsel * 4;               // W ldsm
    int woff1 = (lhalf * 8 + l8) * W1STR + lsel * 4;

    // ---- per-lane persistent state ----
    int wrow = wid * 16 + qr;             // local row (pair at wrow+8)
    float c0v[2][4] = {};                 // [r][h*2+p]
    float c1v[2][4] = {};
    float b1v[8][2];                      // [nf=g*2+h][p]
    #pragma unroll
    for (int g = 0; g < 4; g++)
        #pragma unroll
        for (int h = 0; h < 2; h++)
            #pragma unroll
            for (int p = 0; p < 2; p++) {
                int n = g * Hc + hc0 + h * 8 + 2 * qk + p;
                b1v[g * 2 + h][p] = bih1[n] + bhh1[n];
            }

    unsigned* ctr = &g_bar[grp];

    for (int t = 0; t < Tc; t++) {
        const float* h0prev = h0buf + (t & 1) * BHc;
        float*       h0cur  = h0buf + ((t + 1) & 1) * BHc;
        const float* h1prev = (t == 0) ? zbuf : (hs + (size_t)(t - 1) * BHc);
        float*       h1cur  = hs + (size_t)t * BHc;
        unsigned tB = (unsigned)(2 * t) * NSUB;        // L1(t-1) writes visible
        unsigned tA = (unsigned)(2 * t + 1) * NSUB;    // L0(t) writes visible

        // ================= layer 0 (K=256, 16 chunks) =================
        // Prefetch G0 gate slabs (DRAM latency hidden by the mma loop)
        float2 gI[2][2], gF[2][2], gG[2][2], gO[2][2];
        {
            const float* g0r0 = G0 + ((size_t)t * Bc + m0 + wrow) * H4c + hc0;
            #pragma unroll
            for (int r = 0; r < 2; r++) {
                const float* g0r = g0r0 + (size_t)r * 8 * H4c;
                #pragma unroll
                for (int h = 0; h < 2; h++) {
                    int hcl = h * 8 + 2 * qk;
                    gI[r][h] = *(const float2*)(g0r + hcl);
                    gF[r][h] = *(const float2*)(g0r + 256 + hcl);
                    gG[r][h] = *(const float2*)(g0r + 512 + hcl);
                    gO[r][h] = *(const float2*)(g0r + 768 + hcl);
                }
            }
        }

        float acc[8][4] = {};
        {
            const float* A0p = h0prev + (size_t)m0 * Hc;
            stage_warp(Abuf + 0 * ABUFW, A0p + 0 * 16, wid, lane);
            stage_warp(Abuf + 1 * ABUFW, A0p + 1 * 16, wid, lane);
            #pragma unroll 4
            for (int c = 0; c < 16; c++) {
                if (c == 15) cp_wait<0>(); else cp_wait<1>();
                __syncwarp();
                if (c + 2 < 16)
                    stage_warp(Abuf + ((c + 2) % 3) * ABUFW, A0p + (c + 2) * 16, wid, lane);
                mma_chunk(Abuf + (c % 3) * ABUFW, aoff, W0, W0STR, woff0, c * 16, acc);
            }
        }
        // epilogue: cell update, write h0cur
        #pragma unroll
        for (int r = 0; r < 2; r++) {
            float* hw = h0cur + (size_t)(m0 + wrow + r * 8) * Hc + hc0;
            #pragma unroll
            for (int h = 0; h < 2; h++) {
                int hcl = h * 8 + 2 * qk;
                float hv[2];
                #pragma unroll
                for (int p = 0; p < 2; p++) {
                    float gi = acc[0 + h][r * 2 + p] + (p ? gI[r][h].y : gI[r][h].x);
                    float gf = acc[2 + h][r * 2 + p] + (p ? gF[r][h].y : gF[r][h].x);
                    float gg = acc[4 + h][r * 2 + p] + (p ? gG[r][h].y : gG[r][h].x);
                    float go = acc[6 + h][r * 2 + p] + (p ? gO[r][h].y : gO[r][h].x);
                    float c  = c0v[r][h * 2 + p];
                    float c2 = sigmoidf_(gf) * c + sigmoidf_(gi) * tanhf(gg);
                    c0v[r][h * 2 + p] = c2;
                    hv[p] = sigmoidf_(go) * tanhf(c2);
                }
                *(float2*)(hw + hcl) = make_float2(hv[0], hv[1]);
            }
        }
        bar_arrive(ctr);                 // phase 2t+1 (syncthreads inside)

        // ================= layer 1 (K=512, 32 chunks) =================
        // h1prev half first (ordered by phase 2t); wait for h0cur at c==14,
        // hidden behind 14 chunks of mma while other blocks finish layer 0.
        #pragma unroll
        for (int nf = 0; nf < 8; nf++)
            #pragma unroll
            for (int j = 0; j < 4; j++) acc[nf][j] = 0.f;

        bar_wait(ctr, tB);               // normally already satisfied
        {
            const float* A1 = h1prev + (size_t)m0 * Hc;
            const float* A0 = h0cur + (size_t)m0 * Hc;
            stage_warp(Abuf + 0 * ABUFW, A1 + 0 * 16, wid, lane);
            stage_warp(Abuf + 1 * ABUFW, A1 + 1 * 16, wid, lane);
            #pragma unroll 4
            for (int c = 0; c < 32; c++) {
                if (c == 31) cp_wait<0>(); else cp_wait<1>();
                __syncwarp();
                if (c == 14) bar_wait(ctr, tA);     // before staging h0cur
                if (c + 2 < 32) {
                    int cn = c + 2;
                    const float* src = (cn < 16) ? (A1 + cn * 16) : (A0 + (cn - 16) * 16);
                    stage_warp(Abuf + (cn % 3) * ABUFW, src, wid, lane);
                }
                int kb = (c < 16) ? (256 + c * 16) : ((c - 16) * 16);
                mma_chunk(Abuf + (c % 3) * ABUFW, aoff, W1, W1STR, woff1, kb, acc);
            }
        }
        // epilogue: cell update, write h1cur (== hs[t])
        #pragma unroll
        for (int r = 0; r < 2; r++) {
            float* hw = h1cur + (size_t)(m0 + wrow + r * 8) * Hc + hc0;
            #pragma unroll
            for (int h = 0; h < 2; h++) {
                int hcl = h * 8 + 2 * qk;
                float hv[2];
                #pragma unroll
                for (int p = 0; p < 2; p++) {
                    float gi = acc[0 + h][r * 2 + p] + b1v[0 + h][p];
                    float gf = acc[2 + h][r * 2 + p] + b1v[2 + h][p];
                    float gg = acc[4 + h][r * 2 + p] + b1v[4 + h][p];
                    float go = acc[6 + h][r * 2 + p] + b1v[6 + h][p];
                    float c  = c1v[r][h * 2 + p];
                    float c2 = sigmoidf_(gf) * c + sigmoidf_(gi) * tanhf(gg);
                    c1v[r][h * 2 + p] = c2;
                    hv[p] = sigmoidf_(go) * tanhf(c2);
                }
                *(float2*)(hw + hcl) = make_float2(hv[0], hv[1]);
            }
        }
        bar_arrive(ctr);                 // phase 2t+2
    }
}

// ---------------------------------------------------------------------------
// Final layer: y = A @ Wo3^T + bo3  (N=6, K=256). One warp per row.
// ---------------------------------------------------------------------------
__global__ void __launch_bounds__(256) out_mlp3_k(
    const float* __restrict__ A, const float* __restrict__ W,
    const float* __restrict__ b, float* __restrict__ out)
{
    __shared__ float sW[LAGc * Hc];
    __shared__ float sb[LAGc];
    int tid = threadIdx.x;
    for (int i = tid; i < LAGc * Hc; i += 256) sW[i] = W[i];
    if (tid < LAGc) sb[tid] = b[tid];
    __syncthreads();
    int w = tid >> 5, lane = tid & 31;
    int m = blockIdx.x * 8 + w;
    float a[8];
    #pragma unroll
    for (int j = 0; j < 8; j++) a[j] = A[(size_t)m * Hc + lane + 32 * j];
    #pragma unroll
    for (int n = 0; n < LAGc; n++) {
        float s = 0.f;
        #pragma unroll
        for (int j = 0; j < 8; j++) s += a[j] * sW[n * Hc + lane + 32 * j];
        #pragma unroll
        for (int o = 16; o > 0; o >>= 1) s += __shfl_xor_sync(0xffffffff, s, o);
        if (lane == n) out[m * LAGc + n] = s + sb[n];
    }
}

// ---------------------------------------------------------------------------
extern "C" void kernel_launch(void* const* d_in, const int* in_sizes, int n_in,
                              void* d_out, int out_size)
{
    const float* x    = (const float*)d_in[0];
    const float* Wi1  = (const float*)d_in[1];
    const float* bi1  = (const float*)d_in[2];
    const float* Wi2  = (const float*)d_in[3];
    const float* bi2  = (const float*)d_in[4];
    const float* Wi3  = (const float*)d_in[5];
    const float* bi3  = (const float*)d_in[6];
    const float* Wih0 = (const float*)d_in[7];
    const float* Whh0 = (const float*)d_in[8];
    const float* bih0 = (const float*)d_in[9];
    const float* bhh0 = (const float*)d_in[10];
    const float* Wih1 = (const float*)d_in[11];
    const float* Whh1 = (const float*)d_in[12];
    const float* bih1 = (const float*)d_in[13];
    const float* bhh1 = (const float*)d_in[14];
    const float* Wo1  = (const float*)d_in[15];
    const float* bo1  = (const float*)d_in[16];
    const float* Wo2  = (const float*)d_in[17];
    const float* bo2  = (const float*)d_in[18];
    const float* Wo3  = (const float*)d_in[19];
    const float* bo3  = (const float*)d_in[20];
    float* out = (float*)d_out;

    float *buf0, *buf1, *G0, *hs, *h0, *zb;
    unsigned* bar;
    cudaGetSymbolAddress((void**)&buf0, g_buf0);
    cudaGetSymbolAddress((void**)&buf1, g_buf1);
    cudaGetSymbolAddress((void**)&G0,   g_G0);
    cudaGetSymbolAddress((void**)&hs,   g_hs);
    cudaGetSymbolAddress((void**)&h0,   g_h0);
    cudaGetSymbolAddress((void**)&zb,   g_zb);
    cudaGetSymbolAddress((void**)&bar,  g_bar);

    cudaFuncSetAttribute(lstm_persistent_k,
                         cudaFuncAttributeMaxDynamicSharedMemorySize, SMEM_P);

    cudaMemsetAsync(h0, 0, 2 * BHc * sizeof(float));
    cudaMemsetAsync(zb, 0, BHc * sizeof(float));
    cudaMemsetAsync(bar, 0, NGRP * sizeof(unsigned));

    // Input MLP
    in_mlp1_k<<<TBc / 16, 256>>>(x, Wi1, bi1, buf0);
    dim3 gH(Hc / 128, TBc / 128);
    gemm_mma_k<true, false><<<gH, 256>>>(buf0, Wi2, bi2, nullptr, buf1, TBc, Hc, Hc);
    gemm_mma_k<true, false><<<gH, 256>>>(buf1, Wi3, bi3, nullptr, buf0, TBc, Hc, Hc);

    // Layer-0 input projection for ALL timesteps (includes both biases)
    dim3 gG(H4c / 128, TBc / 128);
    gemm_mma_k<false, false><<<gG, 256>>>(buf0, Wih0, bih0, bhh0, G0, TBc, H4c, Hc);

    // Entire recurrence in one persistent launch
    lstm_persistent_k<<<NBLK, 256, SMEM_P>>>(Whh0, Wih1, Whh1, bih1, bhh1,
                                             G0, h0, zb, hs);

    // Output MLP
    gemm_mma_k<true, true ><<<gH, 256>>>(hs,   Wo1, bo1, nullptr, buf0, TBc, Hc, Hc);
    gemm_mma_k<true, false><<<gH, 256>>>(buf0, Wo2, bo2, nullptr, buf1, TBc, Hc, Hc);
    out_mlp3_k<<<TBc / 8, 256>>>(buf1, Wo3, bo3, out);
}

// round 9
// speedup vs baseline: 3.5737x; 1.0314x over previous
#include <cuda_runtime.h>
#include <cuda_bf16.h>
#include <math.h>

// Problem constants
#define Tc   128
#define Bc   1024
#define LAGc 6
#define Hc   256
#define H4c  1024
#define TBc  (Tc * Bc)      // 131072
#define BHc  (Bc * Hc)      // 262144

// Persistent recurrence kernel geometry
#define NGRP   8
#define NSUB   16
#define NBLK   (NGRP * NSUB)
#define W0STR  260
#define W1STR  516
#define ASTR   20
#define ABUFW  (128 * ASTR)
#define SMEM_P ((64 * W0STR + 64 * W1STR + 3 * ABUFW) * 4)   // 229376 bytes

// GEMM pipeline geometry: 3 stages x (A 128x16 + B 128x16), stride 20 words
#define GSTG   5120                       // words per stage (A 2560 + B 2560)
#define SMEM_G (3 * GSTG * 4)             // 61440 bytes

// ---------------------------------------------------------------------------
__device__ float g_buf0[TBc * Hc];
__device__ float g_buf1[TBc * Hc];
__device__ float g_G0[(size_t)TBc * H4c];
__device__ float g_hs[TBc * Hc];            // h1 state (h1cur = hs[t])
__device__ float g_h0[2 * BHc];
__device__ float g_zb[BHc];
__device__ unsigned g_bar[NGRP];

// ---------------------------------------------------------------------------
__device__ __forceinline__ unsigned cvt_tf32(float x) {
    unsigned u; asm("cvt.rna.tf32.f32 %0, %1;" : "=r"(u) : "f"(x)); return u;
}
__device__ __forceinline__ void mma8(float* d, const unsigned* a, const unsigned* b) {
    asm volatile("mma.sync.aligned.m16n8k8.row.col.f32.tf32.tf32.f32 "
        "{%0,%1,%2,%3}, {%4,%5,%6,%7}, {%8,%9}, {%0,%1,%2,%3};"
        : "+f"(d[0]), "+f"(d[1]), "+f"(d[2]), "+f"(d[3])
        : "r"(a[0]), "r"(a[1]), "r"(a[2]), "r"(a[3]), "r"(b[0]), "r"(b[1]));
}
__device__ __forceinline__ float sigmoidf_(float v) { return 1.f / (1.f + expf(-v)); }

__device__ __forceinline__ void cp_async16(void* dst, const void* src) {
    unsigned d = (unsigned)__cvta_generic_to_shared(dst);
    asm volatile("cp.async.ca.shared.global [%0], [%1], 16;\n" :: "r"(d), "l"(src));
}
__device__ __forceinline__ void cp_commit() {
    asm volatile("cp.async.commit_group;\n");
}
template<int N> __device__ __forceinline__ void cp_wait() {
    asm volatile("cp.async.wait_group %0;\n" :: "n"(N));
}

__device__ __forceinline__ void ldsm4f(unsigned* r, const float* p) {
    unsigned a = (unsigned)__cvta_generic_to_shared(p);
    asm volatile("ldmatrix.sync.aligned.m8n8.x4.shared.b16 {%0,%1,%2,%3}, [%4];"
        : "=r"(r[0]), "=r"(r[1]), "=r"(r[2]), "=r"(r[3]) : "r"(a));
}
__device__ __forceinline__ void ldsm4u(unsigned* r, const unsigned* p) {
    unsigned a = (unsigned)__cvta_generic_to_shared(p);
    asm volatile("ldmatrix.sync.aligned.m8n8.x4.shared.b16 {%0,%1,%2,%3}, [%4];"
        : "=r"(r[0]), "=r"(r[1]), "=r"(r[2]), "=r"(r[3]) : "r"(a));
}

// Decoupled group barrier: release-arrive / acquire-wait on an L2 counter.
__device__ __forceinline__ void bar_arrive(unsigned* ctr) {
    __syncthreads();
    if (threadIdx.x == 0)
        asm volatile("red.release.gpu.global.add.u32 [%0], 1;" :: "l"(ctr) : "memory");
}
__device__ __forceinline__ void bar_wait(unsigned* ctr, unsigned target) {
    if (threadIdx.x == 0) {
        unsigned v;
        do {
            asm volatile("ld.acquire.gpu.global.u32 %0, [%1];" : "=r"(v) : "l"(ctr) : "memory");
        } while (v < target);
    }
    __syncthreads();
}

// ---------------------------------------------------------------------------
// Kernel 1: u = relu(x @ Wi1^T + bi1)   [TB,6] -> [TB,256]
// ---------------------------------------------------------------------------
__global__ void __launch_bounds__(256) in_mlp1_k(
    const float* __restrict__ x, const float* __restrict__ W,
    const float* __restrict__ b, float* __restrict__ out)
{
    __shared__ float sW[Hc * LAGc];
    __shared__ float sb[Hc];
    __shared__ float sx[16 * LAGc];
    int tid = threadIdx.x;
    int m0  = blockIdx.x * 16;
    for (int i = tid; i < Hc * LAGc; i += 256) sW[i] = W[i];
    sb[tid] = b[tid];
    if (tid < 16 * LAGc) sx[tid] = x[m0 * LAGc + tid];
    __syncthreads();
    #pragma unroll
    for (int r = 0; r < 16; r++) {
        float acc = sb[tid];
        #pragma unroll
        for (int k = 0; k < LAGc; k++) acc += sx[r * LAGc + k] * sW[tid * LAGc + k];
        out[(m0 + r) * Hc + tid] = fmaxf(acc, 0.f);
    }
}

// ---------------------------------------------------------------------------
// tf32 GEMM, cp.async 3-stage pipeline + ldmatrix fragments.
// C = act(A @ W^T + b1 [+ b2]); block tile 128x128, BK=16, 8 warps (2m x 4n).
// Dynamic smem: 3 x (A[128][20] + B[128][20]) = 61440 B -> 2 CTAs/SM.
// TAIL FIX (round 9): last iteration must wait_group 0, not 1.
// ---------------------------------------------------------------------------
template<bool RELU_OUT, bool PRE_RELU>
__global__ void __launch_bounds__(256, 2) gemm_mma_k(
    const float* __restrict__ A, const float* __restrict__ W,
    const float* __restrict__ b1, const float* __restrict__ b2,
    float* __restrict__ C, int M, int N, int K)
{
    extern __shared__ unsigned gsm[];
    int tid = threadIdx.x, lane = tid & 31, wid = tid >> 5;
    int wm = wid & 1, wn = wid >> 1;
    int m0 = blockIdx.y * 128, n0 = blockIdx.x * 128;
    int qr = lane >> 2, qk = lane & 3;
    int l8 = lane & 7, lsel = (lane >> 3) & 1, lhalf = lane >> 4;

    const float* Ab = A + (size_t)m0 * K;
    const float* Wb = W + (size_t)n0 * K;

    // staging indices: 2 threads per row, 8 floats each
    int srow = tid >> 1, sko = (tid & 1) * 8;

    // fragment word offsets within a stage
    int aoff[4], boff[2];
    #pragma unroll
    for (int mt = 0; mt < 4; mt++)
        aoff[mt] = (wm * 64 + mt * 16 + l8 + lsel * 8) * 20 + lhalf * 4;
    #pragma unroll
    for (int q = 0; q < 2; q++)
        boff[q] = 2560 + (wn * 32 + q * 16 + lhalf * 8 + l8) * 20 + lsel * 4;

    int nk = K / 16;
    auto stage = [&](int kt) {
        unsigned* S = gsm + (kt % 3) * GSTG;
        const float* as = Ab + (size_t)srow * K + kt * 16 + sko;
        float* da = (float*)S + srow * 20 + sko;
        cp_async16(da, as); cp_async16(da + 4, as + 4);
        const float* bs = Wb + (size_t)srow * K + kt * 16 + sko;
        float* db = (float*)(S + 2560) + srow * 20 + sko;
        cp_async16(db, bs); cp_async16(db + 4, bs + 4);
        cp_commit();
    };

    stage(0);
    if (nk > 1) stage(1);

    float acc[4][4][4] = {};
    for (int kt = 0; kt < nk; kt++) {
        if (kt == nk - 1) cp_wait<0>(); else cp_wait<1>();   // TAIL FIX
        __syncthreads();
        if (kt + 2 < nk) stage(kt + 2);
        unsigned* S = gsm + (kt % 3) * GSTG;
        const float* SA = (const float*)S;
        #pragma unroll
        for (int ks = 0; ks < 16; ks += 8) {
            unsigned ua[4][4], ub[2][4];
            #pragma unroll
            for (int mt = 0; mt < 4; mt++) {
                ldsm4f(ua[mt], SA + aoff[mt] + ks);
                #pragma unroll
                for (int i = 0; i < 4; i++) {
                    float v = __uint_as_float(ua[mt][i]);
                    if (PRE_RELU) v = fmaxf(v, 0.f);
                    ua[mt][i] = cvt_tf32(v);
                }
            }
            #pragma unroll
            for (int q = 0; q < 2; q++) {
                ldsm4u(ub[q], S + boff[q] + ks);
                #pragma unroll
                for (int i = 0; i < 4; i++)
                    ub[q][i] = cvt_tf32(__uint_as_float(ub[q][i]));
            }
            #pragma unroll
            for (int mt = 0; mt < 4; mt++)
                #pragma unroll
                for (int q = 0; q < 2; q++) {
                    mma8(acc[mt][2 * q],     ua[mt], ub[q]);
                    mma8(acc[mt][2 * q + 1], ua[mt], ub[q] + 2);
                }
        }
        __syncthreads();
    }

    #pragma unroll
    for (int nt = 0; nt < 4; nt++) {
        int col = n0 + wn * 32 + nt * 8 + 2 * qk;
        float bb0 = b1[col]     + (b2 ? b2[col]     : 0.f);
        float bb1 = b1[col + 1] + (b2 ? b2[col + 1] : 0.f);
        #pragma unroll
        for (int mt = 0; mt < 4; mt++) {
            int row = m0 + wm * 64 + mt * 16 + qr;
            float2 v0, v1;
            v0.x = acc[mt][nt][0] + bb0; v0.y = acc[mt][nt][1] + bb1;
            v1.x = acc[mt][nt][2] + bb0; v1.y = acc[mt][nt][3] + bb1;
            if (RELU_OUT) {
                v0.x=fmaxf(v0.x,0.f); v0.y=fmaxf(v0.y,0.f);
                v1.x=fmaxf(v1.x,0.f); v1.y=fmaxf(v1.y,0.f);
            }
            *(float2*)(C + (size_t)row * N + col)       = v0;
            *(float2*)(C + (size_t)(row + 8) * N + col) = v1;
        }
    }
}

// ---------------------------------------------------------------------------
// Persistent LSTM helpers — warp-decoupled staging.
// ---------------------------------------------------------------------------
__device__ __forceinline__ void stage_warp(float* Abuf, const float* src_base,
                                           int wid, int lane) {
    #pragma unroll
    for (int i = 0; i < 2; i++) {
        int s = lane + i * 32;
        int row = wid * 16 + (s >> 2), kq = (s & 3) * 4;
        cp_async16(Abuf + row * ASTR + kq, src_base + (size_t)row * Hc + kq);
    }
    cp_commit();
}

__device__ __forceinline__ void mma_chunk(
    const float* Ab, int aoff, const unsigned* Wsm, int wstr, int woff, int kbase,
    float acc[8][4])
{
    #pragma unroll
    for (int ks = 0; ks < 2; ks++) {
        int k0 = ks * 8;
        unsigned a[4];
        ldsm4f(a, Ab + aoff + k0);
        #pragma unroll
        for (int i = 0; i < 4; i++) a[i] = cvt_tf32(__uint_as_float(a[i]));
        #pragma unroll
        for (int p = 0; p < 4; p++) {
            unsigned b[4];
            ldsm4u(b, Wsm + (size_t)(p * 16) * wstr + woff + kbase + k0);
            mma8(acc[2 * p],     a, b);
            mma8(acc[2 * p + 1], a, b + 2);
        }
    }
}

// ---------------------------------------------------------------------------
// Persistent recurrence kernel (round-8 structure: per-warp staging with
// stage-then-wait<2> pipelining; tails use wait<1>/wait<0> correctly).
// ---------------------------------------------------------------------------
__global__ void __launch_bounds__(256, 1) lstm_persistent_k(
    const float* __restrict__ Whh0, const float* __restrict__ Wih1,
    const float* __restrict__ Whh1, const float* __restrict__ bih1,
    const float* __restrict__ bhh1, const float* __restrict__ G0,
    float* __restrict__ h0buf, const float* __restrict__ zbuf,
    float* __restrict__ hs)
{
    extern __shared__ unsigned smem[];
    unsigned* W0 = smem;
    unsigned* W1 = smem + 64 * W0STR;
    float* Abuf  = (float*)(smem + 64 * W0STR + 64 * W1STR);

    int tid = threadIdx.x, lane = tid & 31, wid = tid >> 5;
    int qr = lane >> 2, qk = lane & 3;
    int grp = blockIdx.x >> 4, sub = blockIdx.x & 15;
    int m0  = grp * 128;
    int hc0 = sub * 16;

    for (int i = tid; i < 64 * 64; i += 256) {
        int n = i >> 6, kq = (i & 63) * 4;
        int gr = (n >> 4) * Hc + hc0 + (n & 15);
        float4 v = *(const float4*)(Whh0 + (size_t)gr * Hc + kq);
        unsigned* dst = W0 + n * W0STR + kq;
        dst[0]=cvt_tf32(v.x); dst[1]=cvt_tf32(v.y); dst[2]=cvt_tf32(v.z); dst[3]=cvt_tf32(v.w);
    }
    for (int i = tid; i < 64 * 128; i += 256) {
        int n = i >> 7, kq = (i & 127) * 4;
        int gr = (n >> 4) * Hc + hc0 + (n & 15);
        const float* src = (kq < 256) ? (Wih1 + (size_t)gr * Hc + kq)
                                      : (Whh1 + (size_t)gr * Hc + (kq - 256));
        float4 v = *(const float4*)src;
        unsigned* dst = W1 + n * W1STR + kq;
        dst[0]=cvt_tf32(v.x); dst[1]=cvt_tf32(v.y); dst[2]=cvt_tf32(v.z); dst[3]=cvt_tf32(v.w);
    }
    __syncthreads();

    int l8 = lane & 7, lsel = (lane >> 3) & 1, lhalf = lane >> 4;
    int aoff  = (wid * 16 + l8 + lsel * 8) * ASTR + lhalf * 4;
    int woff0 = (lhalf * 8 + l8) * W0STR + lsel * 4;
    int woff1 = (lhalf * 8 + l8) * W1STR + lsel * 4;

    int wrow = wid * 16 + qr;
    float c0v[2][4] = {};
    float c1v[2][4] = {};
    float b1v[8][2];
    #pragma unroll
    for (int g = 0; g < 4; g++)
        #pragma unroll
        for (int h = 0; h < 2; h++)
            #pragma unroll
            for (int p = 0; p < 2; p++) {
                int n = g * Hc + hc0 + h * 8 + 2 * qk + p;
                b1v[g * 2 + h][p] = bih1[n] + bhh1[n];
            }

    unsigned* ctr = &g_bar[grp];

    for (int t = 0; t < Tc; t++) {
        const float* h0prev = h0buf + (t & 1) * BHc;
        float*       h0cur  = h0buf + ((t + 1) & 1) * BHc;
        const float* h1prev = (t == 0) ? zbuf : (hs + (size_t)(t - 1) * BHc);
        float*       h1cur  = hs + (size_t)t * BHc;
        unsigned tB = (unsigned)(2 * t) * NSUB;
        unsigned tA = (unsigned)(2 * t + 1) * NSUB;

        // ================= layer 0 (K=256, 16 chunks) =================
        float2 gI[2][2], gF[2][2], gG[2][2], gO[2][2];
        {
            const float* g0r0 = G0 + ((size_t)t * Bc + m0 + wrow) * H4c + hc0;
            #pragma unroll
            for (int r = 0; r < 2; r++) {
                const float* g0r = g0r0 + (size_t)r * 8 * H4c;
                #pragma unroll
                for (int h = 0; h < 2; h++) {
                    int hcl = h * 8 + 2 * qk;
                    gI[r][h] = *(const float2*)(g0r + hcl);
                    gF[r][h] = *(const float2*)(g0r + 256 + hcl);
                    gG[r][h] = *(const float2*)(g0r + 512 + hcl);
                    gO[r][h] = *(const float2*)(g0r + 768 + hcl);
                }
            }
        }

        float acc[8][4] = {};
        {
            const float* A0p = h0prev + (size_t)m0 * Hc;
            stage_warp(Abuf + 0 * ABUFW, A0p + 0 * 16, wid, lane);
            stage_warp(Abuf + 1 * ABUFW, A0p + 1 * 16, wid, lane);
            #pragma unroll 4
            for (int c = 0; c < 16; c++) {
                if (c < 14) {
                    stage_warp(Abuf + ((c + 2) % 3) * ABUFW, A0p + (c + 2) * 16, wid, lane);
                    cp_wait<2>();
                } else if (c == 14) cp_wait<1>();
                else cp_wait<0>();
                __syncwarp();
                mma_chunk(Abuf + (c % 3) * ABUFW, aoff, W0, W0STR, woff0, c * 16, acc);
            }
        }
        #pragma unroll
        for (int r = 0; r < 2; r++) {
            float* hw = h0cur + (size_t)(m0 + wrow + r * 8) * Hc + hc0;
            #pragma unroll
            for (int h = 0; h < 2; h++) {
                int hcl = h * 8 + 2 * qk;
                float hv[2];
                #pragma unroll
                for (int p = 0; p < 2; p++) {
                    float gi = acc[0 + h][r * 2 + p] + (p ? gI[r][h].y : gI[r][h].x);
                    float gf = acc[2 + h][r * 2 + p] + (p ? gF[r][h].y : gF[r][h].x);
                    float gg = acc[4 + h][r * 2 + p] + (p ? gG[r][h].y : gG[r][h].x);
                    float go = acc[6 + h][r * 2 + p] + (p ? gO[r][h].y : gO[r][h].x);
                    float c  = c0v[r][h * 2 + p];
                    float c2 = sigmoidf_(gf) * c + sigmoidf_(gi) * tanhf(gg);
                    c0v[r][h * 2 + p] = c2;
                    hv[p] = sigmoidf_(go) * tanhf(c2);
                }
                *(float2*)(hw + hcl) = make_float2(hv[0], hv[1]);
            }
        }
        bar_arrive(ctr);                 // phase 2t+1

        // ================= layer 1 (K=512, 32 chunks) =================
        #pragma unroll
        for (int nf = 0; nf < 8; nf++)
            #pragma unroll
            for (int j = 0; j < 4; j++) acc[nf][j] = 0.f;

        bar_wait(ctr, tB);
        {
            const float* A1 = h1prev + (size_t)m0 * Hc;
            const float* A0 = h0cur + (size_t)m0 * Hc;
            stage_warp(Abuf + 0 * ABUFW, A1 + 0 * 16, wid, lane);
            stage_warp(Abuf + 1 * ABUFW, A1 + 1 * 16, wid, lane);
            #pragma unroll 4
            for (int c = 0; c < 32; c++) {
                if (c == 14) bar_wait(ctr, tA);    // before staging h0cur (chunk 16)
                if (c < 30) {
                    int cn = c + 2;
                    const float* src = (cn < 16) ? (A1 + cn * 16) : (A0 + (cn - 16) * 16);
                    stage_warp(Abuf + (cn % 3) * ABUFW, src, wid, lane);
                    cp_wait<2>();
                } else if (c == 30) cp_wait<1>();
                else cp_wait<0>();
                __syncwarp();
                int kb = (c < 16) ? (256 + c * 16) : ((c - 16) * 16);
                mma_chunk(Abuf + (c % 3) * ABUFW, aoff, W1, W1STR, woff1, kb, acc);
            }
        }
        #pragma unroll
        for (int r = 0; r < 2; r++) {
            float* hw = h1cur + (size_t)(m0 + wrow + r * 8) * Hc + hc0;
            #pragma unroll
            for (int h = 0; h < 2; h++) {
                int hcl = h * 8 + 2 * qk;
                float hv[2];
                #pragma unroll
                for (int p = 0; p < 2; p++) {
                    float gi = acc[0 + h][r * 2 + p] + b1v[0 + h][p];
                    float gf = acc[2 + h][r * 2 + p] + b1v[2 + h][p];
                    float gg = acc[4 + h][r * 2 + p] + b1v[4 + h][p];
                    float go = acc[6 + h][r * 2 + p] + b1v[6 + h][p];
                    float c  = c1v[r][h * 2 + p];
                    float c2 = sigmoidf_(gf) * c + sigmoidf_(gi) * tanhf(gg);
                    c1v[r][h * 2 + p] = c2;
                    hv[p] = sigmoidf_(go) * tanhf(c2);
                }
                *(float2*)(hw + hcl) = make_float2(hv[0], hv[1]);
            }
        }
        bar_arrive(ctr);                 // phase 2t+2
    }
}

// ---------------------------------------------------------------------------
// Final layer: y = A @ Wo3^T + bo3  (N=6, K=256). One warp per row.
// ---------------------------------------------------------------------------
__global__ void __launch_bounds__(256) out_mlp3_k(
    const float* __restrict__ A, const float* __restrict__ W,
    const float* __restrict__ b, float* __restrict__ out)
{
    __shared__ float sW[LAGc * Hc];
    __shared__ float sb[LAGc];
    int tid = threadIdx.x;
    for (int i = tid; i < LAGc * Hc; i += 256) sW[i] = W[i];
    if (tid < LAGc) sb[tid] = b[tid];
    __syncthreads();
    int w = tid >> 5, lane = tid & 31;
    int m = blockIdx.x * 8 + w;
    float a[8];
    #pragma unroll
    for (int j = 0; j < 8; j++) a[j] = A[(size_t)m * Hc + lane + 32 * j];
    #pragma unroll
    for (int n = 0; n < LAGc; n++) {
        float s = 0.f;
        #pragma unroll
        for (int j = 0; j < 8; j++) s += a[j] * sW[n * Hc + lane + 32 * j];
        #pragma unroll
        for (int o = 16; o > 0; o >>= 1) s += __shfl_xor_sync(0xffffffff, s, o);
        if (lane == n) out[m * LAGc + n] = s + sb[n];
    }
}

// ---------------------------------------------------------------------------
extern "C" void kernel_launch(void* const* d_in, const int* in_sizes, int n_in,
                              void* d_out, int out_size)
{
    const float* x    = (const float*)d_in[0];
    const float* Wi1  = (const float*)d_in[1];
    const float* bi1  = (const float*)d_in[2];
    const float* Wi2  = (const float*)d_in[3];
    const float* bi2  = (const float*)d_in[4];
    const float* Wi3  = (const float*)d_in[5];
    const float* bi3  = (const float*)d_in[6];
    const float* Wih0 = (const float*)d_in[7];
    const float* Whh0 = (const float*)d_in[8];
    const float* bih0 = (const float*)d_in[9];
    const float* bhh0 = (const float*)d_in[10];
    const float* Wih1 = (const float*)d_in[11];
    const float* Whh1 = (const float*)d_in[12];
    const float* bih1 = (const float*)d_in[13];
    const float* bhh1 = (const float*)d_in[14];
    const float* Wo1  = (const float*)d_in[15];
    const float* bo1  = (const float*)d_in[16];
    const float* Wo2  = (const float*)d_in[17];
    const float* bo2  = (const float*)d_in[18];
    const float* Wo3  = (const float*)d_in[19];
    const float* bo3  = (const float*)d_in[20];
    float* out = (float*)d_out;

    float *buf0, *buf1, *G0, *hs, *h0, *zb;
    unsigned* bar;
    cudaGetSymbolAddress((void**)&buf0, g_buf0);
    cudaGetSymbolAddress((void**)&buf1, g_buf1);
    cudaGetSymbolAddress((void**)&G0,   g_G0);
    cudaGetSymbolAddress((void**)&hs,   g_hs);
    cudaGetSymbolAddress((void**)&h0,   g_h0);
    cudaGetSymbolAddress((void**)&zb,   g_zb);
    cudaGetSymbolAddress((void**)&bar,  g_bar);

    cudaFuncSetAttribute(lstm_persistent_k,
                         cudaFuncAttributeMaxDynamicSharedMemorySize, SMEM_P);
    cudaFuncSetAttribute(gemm_mma_k<true, false>,
                         cudaFuncAttributeMaxDynamicSharedMemorySize, SMEM_G);
    cudaFuncSetAttribute(gemm_mma_k<false, false>,
                         cudaFuncAttributeMaxDynamicSharedMemorySize, SMEM_G);
    cudaFuncSetAttribute(gemm_mma_k<true, true>,
                         cudaFuncAttributeMaxDynamicSharedMemorySize, SMEM_G);

    cudaMemsetAsync(h0, 0, 2 * BHc * sizeof(float));
    cudaMemsetAsync(zb, 0, BHc * sizeof(float));
    cudaMemsetAsync(bar, 0, NGRP * sizeof(unsigned));

    // Input MLP
    in_mlp1_k<<<TBc / 16, 256>>>(x, Wi1, bi1, buf0);
    dim3 gH(Hc / 128, TBc / 128);
    gemm_mma_k<true, false><<<gH, 256, SMEM_G>>>(buf0, Wi2, bi2, nullptr, buf1, TBc, Hc, Hc);
    gemm_mma_k<true, false><<<gH, 256, SMEM_G>>>(buf1, Wi3, bi3, nullptr, buf0, TBc, Hc, Hc);

    // Layer-0 input projection for ALL timesteps (includes both biases)
    dim3 gG(H4c / 128, TBc / 128);
    gemm_mma_k<false, false><<<gG, 256, SMEM_G>>>(buf0, Wih0, bih0, bhh0, G0, TBc, H4c, Hc);

    // Entire recurrence in one persistent launch
    lstm_persistent_k<<<NBLK, 256, SMEM_P>>>(Whh0, Wih1, Whh1, bih1, bhh1,
                                             G0, h0, zb, hs);

    // Output MLP
    gemm_mma_k<true, true ><<<gH, 256, SMEM_G>>>(hs,   Wo1, bo1, nullptr, buf0, TBc, Hc, Hc);
    gemm_mma_k<true, false><<<gH, 256, SMEM_G>>>(buf0, Wo2, bo2, nullptr, buf1, TBc, Hc, Hc);
    out_mlp3_k<<<TBc / 8, 256>>>(buf1, Wo3, bo3, out);
}

// round 11
// speedup vs baseline: 5.2844x; 1.4787x over previous
#include <cuda_runtime.h>
#include <cuda_fp16.h>
#include <math.h>

// Problem constants
#define Tc   128
#define Bc   1024
#define LAGc 6
#define Hc   256
#define H4c  1024
#define TBc  (Tc * Bc)      // 131072
#define BHc  (Bc * Hc)      // 262144

// Persistent recurrence kernel geometry (fp16)
#define NGRP   8
#define NSUB   16
#define NBLK   (NGRP * NSUB)
#define W0STRH 264          // smem row stride (halves) layer0 weights (K=256)  528B ≡16 mod128
#define W1STRH 520          // layer1 (K=512)                                  1040B ≡16 mod128
#define AHSTR  24           // A staging row stride (halves), 48B, 16B-aligned, conflict-free
#define ABUFH  (128 * AHSTR)  // halves per A buffer (3072)
#define SMEM_P ((64 * W0STRH + 64 * W1STRH + 3 * ABUFH) * 2)   // 118784 bytes

// fp16 GEMM pipeline: 3 stages x (A 128x16 + B 128x16) halves, stride 24
#define HSTG   (128 * AHSTR)          // 3072 halves per operand
#define GSTGH  (2 * HSTG)             // 6144 halves per stage
#define SMEM_GH (3 * GSTGH * 2)       // 36864 bytes

// ---------------------------------------------------------------------------
__device__ __half g_hbuf0[TBc * Hc];
__device__ __half g_hbuf1[TBc * Hc];
__device__ float  g_G0[(size_t)TBc * H4c];
__device__ __half g_hs[TBc * Hc];           // h1 state (h1cur = hs[t])
__device__ __half g_h0[2 * BHc];            // layer-0 hidden ping-pong
__device__ __half g_zb[BHc];                // zero h1prev for t=0
__device__ __half g_wh[1310720];            // fp16 weights: Wi2|Wi3|Wih0|Wo1|Wo2
__device__ unsigned g_bar[NGRP];

// ---------------------------------------------------------------------------
__device__ __forceinline__ void mma16(float* d, const unsigned* a, const unsigned* b) {
    asm volatile("mma.sync.aligned.m16n8k16.row.col.f32.f16.f16.f32 "
        "{%0,%1,%2,%3}, {%4,%5,%6,%7}, {%8,%9}, {%0,%1,%2,%3};"
        : "+f"(d[0]), "+f"(d[1]), "+f"(d[2]), "+f"(d[3])
        : "r"(a[0]), "r"(a[1]), "r"(a[2]), "r"(a[3]), "r"(b[0]), "r"(b[1]));
}
__device__ __forceinline__ float sigmoidf_(float v) { return 1.f / (1.f + expf(-v)); }
__device__ __forceinline__ unsigned hrelu2(unsigned x) {
    __half2 h = __hmax2(*reinterpret_cast<__half2*>(&x), __float2half2_rn(0.f));
    return *reinterpret_cast<unsigned*>(&h);
}

__device__ __forceinline__ void cp_async16(void* dst, const void* src) {
    unsigned d = (unsigned)__cvta_generic_to_shared(dst);
    asm volatile("cp.async.ca.shared.global [%0], [%1], 16;\n" :: "r"(d), "l"(src));
}
__device__ __forceinline__ void cp_commit() {
    asm volatile("cp.async.commit_group;\n");
}
template<int N> __device__ __forceinline__ void cp_wait() {
    asm volatile("cp.async.wait_group %0;\n" :: "n"(N));
}
__device__ __forceinline__ void ldsm4h(unsigned* r, const __half* p) {
    unsigned a = (unsigned)__cvta_generic_to_shared(p);
    asm volatile("ldmatrix.sync.aligned.m8n8.x4.shared.b16 {%0,%1,%2,%3}, [%4];"
        : "=r"(r[0]), "=r"(r[1]), "=r"(r[2]), "=r"(r[3]) : "r"(a));
}

// Decoupled group barrier (recurrence)
__device__ __forceinline__ void bar_arrive(unsigned* ctr) {
    __syncthreads();
    if (threadIdx.x == 0)
        asm volatile("red.release.gpu.global.add.u32 [%0], 1;" :: "l"(ctr) : "memory");
}
__device__ __forceinline__ void bar_wait(unsigned* ctr, unsigned target) {
    if (threadIdx.x == 0) {
        unsigned v;
        do {
            asm volatile("ld.acquire.gpu.global.u32 %0, [%1];" : "=r"(v) : "l"(ctr) : "memory");
        } while (v < target);
    }
    __syncthreads();
}

// ---------------------------------------------------------------------------
// fp32 -> fp16 weight conversion
// ---------------------------------------------------------------------------
__global__ void wconv_k(const float* __restrict__ src, __half* __restrict__ dst, int n4) {
    int i = blockIdx.x * 256 + threadIdx.x;
    if (i < n4) {
        float4 v = ((const float4*)src)[i];
        ((__half2*)dst)[2 * i]     = __floats2half2_rn(v.x, v.y);
        ((__half2*)dst)[2 * i + 1] = __floats2half2_rn(v.z, v.w);
    }
}

// ---------------------------------------------------------------------------
// Kernel 1: u = half(relu(x @ Wi1^T + bi1))   [TB,6] -> [TB,256] fp16
// ---------------------------------------------------------------------------
__global__ void __launch_bounds__(256) in_mlp1_k(
    const float* __restrict__ x, const float* __restrict__ W,
    const float* __restrict__ b, __half* __restrict__ out)
{
    __shared__ float sW[Hc * LAGc];
    __shared__ float sb[Hc];
    __shared__ float sx[16 * LAGc];
    int tid = threadIdx.x;
    int m0  = blockIdx.x * 16;
    for (int i = tid; i < Hc * LAGc; i += 256) sW[i] = W[i];
    sb[tid] = b[tid];
    if (tid < 16 * LAGc) sx[tid] = x[m0 * LAGc + tid];
    __syncthreads();
    #pragma unroll
    for (int r = 0; r < 16; r++) {
        float acc = sb[tid];
        #pragma unroll
        for (int k = 0; k < LAGc; k++) acc += sx[r * LAGc + k] * sW[tid * LAGc + k];
        out[(m0 + r) * Hc + tid] = __float2half(fmaxf(acc, 0.f));
    }
}

// ---------------------------------------------------------------------------
// fp16 GEMM: C = act(A @ W^T + b1 [+b2]); block tile 128x128, K=256 fixed,
// BK=16, 3-stage cp.async, ldmatrix frags, m16n8k16 HMMA, fp32 accum.
// 8 warps (2m x 4n), warp tile 64x32. OUT_HALF selects half/float C.
// ---------------------------------------------------------------------------
template<bool RELU_OUT, bool PRE_RELU, bool OUT_HALF, bool HAS_B2>
__global__ void __launch_bounds__(256, 2) gemm_h16_k(
    const __half* __restrict__ A, const __half* __restrict__ W,
    const float* __restrict__ b1, const float* __restrict__ b2,
    void* __restrict__ Cv, int N)
{
    extern __shared__ __half gsmh[];
    const int K = 256;
    int tid = threadIdx.x, lane = tid & 31, wid = tid >> 5;
    int wm = wid & 1, wn = wid >> 1;
    int m0 = blockIdx.y * 128, n0 = blockIdx.x * 128;
    int qr = lane >> 2, qk = lane & 3;
    int l8 = lane & 7, lsel = (lane >> 3) & 1, lhalf = lane >> 4;

    const __half* Ab = A + (size_t)m0 * K;
    const __half* Wb = W + (size_t)n0 * K;

    int srow = tid >> 1, sko = (tid & 1) * 8;   // halves

    int aoff[4], boff[2];
    #pragma unroll
    for (int mt = 0; mt < 4; mt++)
        aoff[mt] = (wm * 64 + mt * 16 + l8 + lsel * 8) * AHSTR + lhalf * 8;
    #pragma unroll
    for (int q = 0; q < 2; q++)
        boff[q] = HSTG + (wn * 32 + q * 16 + lhalf * 8 + l8) * AHSTR + lsel * 8;

    const int nk = K / 16;   // 16
    auto stage = [&](int kt) {
        __half* S = gsmh + (kt % 3) * GSTGH;
        cp_async16(S + srow * AHSTR + sko, Ab + (size_t)srow * K + kt * 16 + sko);
        cp_async16(S + HSTG + srow * AHSTR + sko, Wb + (size_t)srow * K + kt * 16 + sko);
        cp_commit();
    };

    stage(0);
    stage(1);

    float acc[4][4][4] = {};
    for (int kt = 0; kt < nk; kt++) {
        if (kt == nk - 1) cp_wait<0>(); else cp_wait<1>();
        __syncthreads();
        if (kt + 2 < nk) stage(kt + 2);
        const __half* S = gsmh + (kt % 3) * GSTGH;
        unsigned ua[4][4], ub[2][4];
        #pragma unroll
        for (int mt = 0; mt < 4; mt++) {
            ldsm4h(ua[mt], S + aoff[mt]);
            if (PRE_RELU) {
                #pragma unroll
                for (int i = 0; i < 4; i++) ua[mt][i] = hrelu2(ua[mt][i]);
            }
        }
        #pragma unroll
        for (int q = 0; q < 2; q++)
            ldsm4h(ub[q], S + boff[q]);
        #pragma unroll
        for (int mt = 0; mt < 4; mt++)
            #pragma unroll
            for (int q = 0; q < 2; q++) {
                mma16(acc[mt][2 * q],     ua[mt], ub[q]);
                mma16(acc[mt][2 * q + 1], ua[mt], ub[q] + 2);
            }
        __syncthreads();
    }

    #pragma unroll
    for (int nt = 0; nt < 4; nt++) {
        int col = n0 + wn * 32 + nt * 8 + 2 * qk;
        float bb0 = b1[col]     + (HAS_B2 ? b2[col]     : 0.f);
        float bb1 = b1[col + 1] + (HAS_B2 ? b2[col + 1] : 0.f);
        #pragma unroll
        for (int mt = 0; mt < 4; mt++) {
            int row = m0 + wm * 64 + mt * 16 + qr;
            float2 v0, v1;
            v0.x = acc[mt][nt][0] + bb0; v0.y = acc[mt][nt][1] + bb1;
            v1.x = acc[mt][nt][2] + bb0; v1.y = acc[mt][nt][3] + bb1;
            if (RELU_OUT) {
                v0.x=fmaxf(v0.x,0.f); v0.y=fmaxf(v0.y,0.f);
                v1.x=fmaxf(v1.x,0.f); v1.y=fmaxf(v1.y,0.f);
            }
            if (OUT_HALF) {
                __half* C = (__half*)Cv;
                *(__half2*)(C + (size_t)row * N + col)       = __floats2half2_rn(v0.x, v0.y);
                *(__half2*)(C + (size_t)(row + 8) * N + col) = __floats2half2_rn(v1.x, v1.y);
            } else {
                float* C = (float*)Cv;
                *(float2*)(C + (size_t)row * N + col)       = v0;
                *(float2*)(C + (size_t)(row + 8) * N + col) = v1;
            }
        }
    }
}

// ---------------------------------------------------------------------------
// Persistent LSTM helpers (fp16)
// ---------------------------------------------------------------------------
__device__ __forceinline__ void stage_warp_h(__half* Abuf, const __half* src_base,
                                             int wid, int lane) {
    int row = wid * 16 + (lane >> 1), kq = (lane & 1) * 8;
    cp_async16(Abuf + row * AHSTR + kq, src_base + (size_t)row * Hc + kq);
    cp_commit();
}

// MMA over one k16 chunk: 1 A-ldsm + 4 B-ldsm + 8 mma.
__device__ __forceinline__ void mma_chunk_h(
    const __half* Ab, int aoff, const __half* Wsm, int wstr, int woff, int kbase,
    float acc[8][4])
{
    unsigned a[4];
    ldsm4h(a, Ab + aoff);
    #pragma unroll
    for (int p = 0; p < 4; p++) {
        unsigned b[4];
        ldsm4h(b, Wsm + (size_t)(p * 16) * wstr + woff + kbase);
        mma16(acc[2 * p],     a, b);
        mma16(acc[2 * p + 1], a, b + 2);
    }
}

// ---------------------------------------------------------------------------
// Persistent recurrence: 128 timesteps, both layers, fp16 operands,
// fp32 accum + fp32 cell state; structure identical to round 9.
// ---------------------------------------------------------------------------
__global__ void __launch_bounds__(256, 1) lstm_persistent_k(
    const float* __restrict__ Whh0, const float* __restrict__ Wih1,
    const float* __restrict__ Whh1, const float* __restrict__ bih1,
    const float* __restrict__ bhh1, const float* __restrict__ G0,
    __half* __restrict__ h0buf, const __half* __restrict__ zbuf,
    __half* __restrict__ hs)
{
    extern __shared__ __half smh[];
    __half* W0   = smh;                         // [64][W0STRH]
    __half* W1   = smh + 64 * W0STRH;           // [64][W1STRH]
    __half* Abuf = smh + 64 * W0STRH + 64 * W1STRH;  // 3 x [128][AHSTR]

    int tid = threadIdx.x, lane = tid & 31, wid = tid >> 5;
    int qr = lane >> 2, qk = lane & 3;
    int grp = blockIdx.x >> 4, sub = blockIdx.x & 15;
    int m0  = grp * 128;
    int hc0 = sub * 16;

    // stage weights to smem as fp16 (once)
    for (int i = tid; i < 64 * 64; i += 256) {           // layer0: 64n x 256k /4
        int n = i >> 6, kq = (i & 63) * 4;
        int gr = (n >> 4) * Hc + hc0 + (n & 15);
        float4 v = *(const float4*)(Whh0 + (size_t)gr * Hc + kq);
        __half2* dst = (__half2*)(W0 + n * W0STRH + kq);
        dst[0] = __floats2half2_rn(v.x, v.y);
        dst[1] = __floats2half2_rn(v.z, v.w);
    }
    for (int i = tid; i < 64 * 128; i += 256) {          // layer1: 64n x 512k /4
        int n = i >> 7, kq = (i & 127) * 4;
        int gr = (n >> 4) * Hc + hc0 + (n & 15);
        const float* src = (kq < 256) ? (Wih1 + (size_t)gr * Hc + kq)
                                      : (Whh1 + (size_t)gr * Hc + (kq - 256));
        float4 v = *(const float4*)src;
        __half2* dst = (__half2*)(W1 + n * W1STRH + kq);
        dst[0] = __floats2half2_rn(v.x, v.y);
        dst[1] = __floats2half2_rn(v.z, v.w);
    }
    __syncthreads();

    int l8 = lane & 7, lsel = (lane >> 3) & 1, lhalf = lane >> 4;
    int aoff  = (wid * 16 + l8 + lsel * 8) * AHSTR + lhalf * 8;
    int woff0 = (lhalf * 8 + l8) * W0STRH + lsel * 8;
    int woff1 = (lhalf * 8 + l8) * W1STRH + lsel * 8;

    int wrow = wid * 16 + qr;
    float c0v[2][4] = {};
    float c1v[2][4] = {};
    float b1v[8][2];
    #pragma unroll
    for (int g = 0; g < 4; g++)
        #pragma unroll
        for (int h = 0; h < 2; h++)
            #pragma unroll
            for (int p = 0; p < 2; p++) {
                int n = g * Hc + hc0 + h * 8 + 2 * qk + p;
                b1v[g * 2 + h][p] = bih1[n] + bhh1[n];
            }

    unsigned* ctr = &g_bar[grp];

    for (int t = 0; t < Tc; t++) {
        const __half* h0prev = h0buf + (size_t)(t & 1) * BHc;
        __half*       h0cur  = h0buf + (size_t)((t + 1) & 1) * BHc;
        const __half* h1prev = (t == 0) ? zbuf : (hs + (size_t)(t - 1) * BHc);
        __half*       h1cur  = hs + (size_t)t * BHc;
        unsigned tB = (unsigned)(2 * t) * NSUB;
        unsigned tA = (unsigned)(2 * t + 1) * NSUB;

        // ================= layer 0 (K=256, 16 chunks) =================
        float2 gI[2][2], gF[2][2], gG[2][2], gO[2][2];
        {
            const float* g0r0 = G0 + ((size_t)t * Bc + m0 + wrow) * H4c + hc0;
            #pragma unroll
            for (int r = 0; r < 2; r++) {
                const float* g0r = g0r0 + (size_t)r * 8 * H4c;
                #pragma unroll
                for (int h = 0; h < 2; h++) {
                    int hcl = h * 8 + 2 * qk;
                    gI[r][h] = *(const float2*)(g0r + hcl);
                    gF[r][h] = *(const float2*)(g0r + 256 + hcl);
                    gG[r][h] = *(const float2*)(g0r + 512 + hcl);
                    gO[r][h] = *(const float2*)(g0r + 768 + hcl);
                }
            }
        }

        float acc[8][4] = {};
        {
            const __half* A0p = h0prev + (size_t)m0 * Hc;
            stage_warp_h(Abuf + 0 * ABUFH, A0p + 0 * 16, wid, lane);
            stage_warp_h(Abuf + 1 * ABUFH, A0p + 1 * 16, wid, lane);
            #pragma unroll 4
            for (int c = 0; c < 16; c++) {
                if (c < 14) {
                    stage_warp_h(Abuf + ((c + 2) % 3) * ABUFH, A0p + (c + 2) * 16, wid, lane);
                    cp_wait<2>();
                } else if (c == 14) cp_wait<1>();
                else cp_wait<0>();
                __syncwarp();
                mma_chunk_h(Abuf + (c % 3) * ABUFH, aoff, W0, W0STRH, woff0, c * 16, acc);
            }
        }
        #pragma unroll
        for (int r = 0; r < 2; r++) {
            __half* hw = h0cur + (size_t)(m0 + wrow + r * 8) * Hc + hc0;
            #pragma unroll
            for (int h = 0; h < 2; h++) {
                int hcl = h * 8 + 2 * qk;
                float hv[2];
                #pragma unroll
                for (int p = 0; p < 2; p++) {
                    float gi = acc[0 + h][r * 2 + p] + (p ? gI[r][h].y : gI[r][h].x);
                    float gf = acc[2 + h][r * 2 + p] + (p ? gF[r][h].y : gF[r][h].x);
                    float gg = acc[4 + h][r * 2 + p] + (p ? gG[r][h].y : gG[r][h].x);
                    float go = acc[6 + h][r * 2 + p] + (p ? gO[r][h].y : gO[r][h].x);
                    float c  = c0v[r][h * 2 + p];
                    float c2 = sigmoidf_(gf) * c + sigmoidf_(gi) * tanhf(gg);
                    c0v[r][h * 2 + p] = c2;
                    hv[p] = sigmoidf_(go) * tanhf(c2);
                }
                *(__half2*)(hw + hcl) = __floats2half2_rn(hv[0], hv[1]);
            }
        }
        bar_arrive(ctr);                 // phase 2t+1

        // ================= layer 1 (K=512, 32 chunks) =================
        #pragma unroll
        for (int nf = 0; nf < 8; nf++)
            #pragma unroll
            for (int j = 0; j < 4; j++) acc[nf][j] = 0.f;

        bar_wait(ctr, tB);
        {
            const __half* A1 = h1prev + (size_t)m0 * Hc;
            const __half* A0 = h0cur + (size_t)m0 * Hc;
            stage_warp_h(Abuf + 0 * ABUFH, A1 + 0 * 16, wid, lane);
            stage_warp_h(Abuf + 1 * ABUFH, A1 + 1 * 16, wid, lane);
            #pragma unroll 4
            for (int c = 0; c < 32; c++) {
                if (c == 14) bar_wait(ctr, tA);    // before staging h0cur (chunk 16)
                if (c < 30) {
                    int cn = c + 2;
                    const __half* src = (cn < 16) ? (A1 + cn * 16) : (A0 + (cn - 16) * 16);
                    stage_warp_h(Abuf + (cn % 3) * ABUFH, src, wid, lane);
                    cp_wait<2>();
                } else if (c == 30) cp_wait<1>();
                else cp_wait<0>();
                __syncwarp();
                int kb = (c < 16) ? (256 + c * 16) : ((c - 16) * 16);
                mma_chunk_h(Abuf + (c % 3) * ABUFH, aoff, W1, W1STRH, woff1, kb, acc);
            }
        }
        #pragma unroll
        for (int r = 0; r < 2; r++) {
            __half* hw = h1cur + (size_t)(m0 + wrow + r * 8) * Hc + hc0;
            #pragma unroll
            for (int h = 0; h < 2; h++) {
                int hcl = h * 8 + 2 * qk;
                float hv[2];
                #pragma unroll
                for (int p = 0; p < 2; p++) {
                    float gi = acc[0 + h][r * 2 + p] + b1v[0 + h][p];
                    float gf = acc[2 + h][r * 2 + p] + b1v[2 + h][p];
                    float gg = acc[4 + h][r * 2 + p] + b1v[4 + h][p];
                    float go = acc[6 + h][r * 2 + p] + b1v[6 + h][p];
                    float c  = c1v[r][h * 2 + p];
                    float c2 = sigmoidf_(gf) * c + sigmoidf_(gi) * tanhf(gg);
                    c1v[r][h * 2 + p] = c2;
                    hv[p] = sigmoidf_(go) * tanhf(c2);
                }
                *(__half2*)(hw + hcl) = __floats2half2_rn(hv[0], hv[1]);
            }
        }
        bar_arrive(ctr);                 // phase 2t+2
    }
}

// ---------------------------------------------------------------------------
// Final layer: y = A @ Wo3^T + bo3  (N=6, K=256). A fp16, math fp32.
// ---------------------------------------------------------------------------
__global__ void __launch_bounds__(256) out_mlp3_k(
    const __half* __restrict__ A, const float* __restrict__ W,
    const float* __restrict__ b, float* __restrict__ out)
{
    __shared__ float sW[LAGc * Hc];
    __shared__ float sb[LAGc];
    int tid = threadIdx.x;
    for (int i = tid; i < LAGc * Hc; i += 256) sW[i] = W[i];
    if (tid < LAGc) sb[tid] = b[tid];
    __syncthreads();
    int w = tid >> 5, lane = tid & 31;
    int m = blockIdx.x * 8 + w;
    float a[8];
    #pragma unroll
    for (int j = 0; j < 8; j++) a[j] = __half2float(A[(size_t)m * Hc + lane + 32 * j]);
    #pragma unroll
    for (int n = 0; n < LAGc; n++) {
        float s = 0.f;
        #pragma unroll
        for (int j = 0; j < 8; j++) s += a[j] * sW[n * Hc + lane + 32 * j];
        #pragma unroll
        for (int o = 16; o > 0; o >>= 1) s += __shfl_xor_sync(0xffffffff, s, o);
        if (lane == n) out[m * LAGc + n] = s + sb[n];
    }
}

// ---------------------------------------------------------------------------
extern "C" void kernel_launch(void* const* d_in, const int* in_sizes, int n_in,
                              void* d_out, int out_size)
{
    const float* x    = (const float*)d_in[0];
    const float* Wi1  = (const float*)d_in[1];
    const float* bi1  = (const float*)d_in[2];
    const float* Wi2  = (const float*)d_in[3];
    const float* bi2  = (const float*)d_in[4];
    const float* Wi3  = (const float*)d_in[5];
    const float* bi3  = (const float*)d_in[6];
    const float* Wih0 = (const float*)d_in[7];
    const float* Whh0 = (const float*)d_in[8];
    const float* bih0 = (const float*)d_in[9];
    const float* bhh0 = (const float*)d_in[10];
    const float* Wih1 = (const float*)d_in[11];
    const float* Whh1 = (const float*)d_in[12];
    const float* bih1 = (const float*)d_in[13];
    const float* bhh1 = (const float*)d_in[14];
    const float* Wo1  = (const float*)d_in[15];
    const float* bo1  = (const float*)d_in[16];
    const float* Wo2  = (const float*)d_in[17];
    const float* bo2  = (const float*)d_in[18];
    const float* Wo3  = (const float*)d_in[19];
    const float* bo3  = (const float*)d_in[20];
    float* out = (float*)d_out;

    __half *hbuf0, *hbuf1, *hs, *h0, *zb, *wh;
    float *G0;
    unsigned* bar;
    cudaGetSymbolAddress((void**)&hbuf0, g_hbuf0);
    cudaGetSymbolAddress((void**)&hbuf1, g_hbuf1);
    cudaGetSymbolAddress((void**)&G0,    g_G0);
    cudaGetSymbolAddress((void**)&hs,    g_hs);
    cudaGetSymbolAddress((void**)&h0,    g_h0);
    cudaGetSymbolAddress((void**)&zb,    g_zb);
    cudaGetSymbolAddress((void**)&wh,    g_wh);
    cudaGetSymbolAddress((void**)&bar,   g_bar);

    __half* Wi2h  = wh;                 // 65536
    __half* Wi3h  = wh + 65536;         // 65536
    __half* Wih0h = wh + 131072;        // 1048576
    __half* Wo1h  = wh + 1179648;       // 65536
    __half* Wo2h  = wh + 1245184;       // 65536

    cudaFuncSetAttribute(lstm_persistent_k,
                         cudaFuncAttributeMaxDynamicSharedMemorySize, SMEM_P);
    cudaFuncSetAttribute(gemm_h16_k<true,  false, true,  false>,
                         cudaFuncAttributeMaxDynamicSharedMemorySize, SMEM_GH);
    cudaFuncSetAttribute(gemm_h16_k<false, false, false, true >,
                         cudaFuncAttributeMaxDynamicSharedMemorySize, SMEM_GH);
    cudaFuncSetAttribute(gemm_h16_k<true,  true,  true,  false>,
                         cudaFuncAttributeMaxDynamicSharedMemorySize, SMEM_GH);

    cudaMemsetAsync(h0, 0, 2 * BHc * sizeof(__half));
    cudaMemsetAsync(zb, 0, BHc * sizeof(__half));
    cudaMemsetAsync(bar, 0, NGRP * sizeof(unsigned));

    // fp16 weight copies for the GEMM chain
    wconv_k<<<64,   256>>>(Wi2,  Wi2h,  65536 / 4);
    wconv_k<<<64,   256>>>(Wi3,  Wi3h,  65536 / 4);
    wconv_k<<<1024, 256>>>(Wih0, Wih0h, 1048576 / 4);
    wconv_k<<<64,   256>>>(Wo1,  Wo1h,  65536 / 4);
    wconv_k<<<64,   256>>>(Wo2,  Wo2h,  65536 / 4);

    // Input MLP
    in_mlp1_k<<<TBc / 16, 256>>>(x, Wi1, bi1, hbuf0);
    dim3 gH(Hc / 128, TBc / 128);      // (2, 1024)
    gemm_h16_k<true, false, true, false><<<gH, 256, SMEM_GH>>>(hbuf0, Wi2h, bi2, nullptr, hbuf1, Hc);
    gemm_h16_k<true, false, true, false><<<gH, 256, SMEM_GH>>>(hbuf1, Wi3h, bi3, nullptr, hbuf0, Hc);

    // Layer-0 input projection for ALL timesteps (fp32 output + both biases)
    dim3 gG(H4c / 128, TBc / 128);     // (8, 1024)
    gemm_h16_k<false, false, false, true><<<gG, 256, SMEM_GH>>>(hbuf0, Wih0h, bih0, bhh0, G0, H4c);

    // Entire recurrence in one persistent launch
    lstm_persistent_k<<<NBLK, 256, SMEM_P>>>(Whh0, Wih1, Whh1, bih1, bhh1,
                                             G0, h0, zb, hs);

    // Output MLP (PRE_RELU on hs)
    gemm_h16_k<true, true,  true, false><<<gH, 256, SMEM_GH>>>(hs,    Wo1h, bo1, nullptr, hbuf0, Hc);
    gemm_h16_k<true, false, true, false><<<gH, 256, SMEM_GH>>>(hbuf0, Wo2h, bo2, nullptr, hbuf1, Hc);
    out_mlp3_k<<<TBc / 8, 256>>>(hbuf1, Wo3, bo3, out);
}